// round 2
// baseline (speedup 1.0000x reference)
#include <cuda_runtime.h>
#include <stdint.h>
#include <math.h>

#define NODES_MAX 100000
#define EDGES_MAX 1600000
#define IN_F 256
#define HID 128
#define OUTF 64

// ---------------- scratch (static __device__, no allocs) ----------------
__device__ float g_bufA[(size_t)NODES_MAX * HID];   // h_mean / messages m
__device__ float g_bufB[(size_t)NODES_MAX * HID];   // h_var  / messages v
__device__ float g_aggM[(size_t)NODES_MAX * HID];   // aggregated mean
__device__ float g_aggV[(size_t)NODES_MAX * HID];
__device__ float g_norm1[NODES_MAX];
__device__ float g_norm2[NODES_MAX];
__device__ int   g_deg[NODES_MAX];
__device__ int   g_cursor[NODES_MAX];
__device__ int   g_offs[NODES_MAX + 1];
__device__ int   g_csr[EDGES_MAX];

// ---------------- degree / norms ----------------
__global__ void k_zero(int n) {
    int i = blockIdx.x * blockDim.x + threadIdx.x;
    if (i < n) { g_deg[i] = 0; g_cursor[i] = 0; }
}

__global__ void k_count(const int* __restrict__ dst, int E) {
    int e = blockIdx.x * blockDim.x + threadIdx.x;
    if (e < E) atomicAdd(&g_deg[dst[e]], 1);
}

__global__ void k_norm(int n) {
    int i = blockIdx.x * blockDim.x + threadIdx.x;
    if (i < n) {
        float d = fmaxf((float)g_deg[i], 1.0f);
        float n1 = 1.0f / sqrtf(d);
        g_norm1[i] = n1;
        g_norm2[i] = n1 * n1;
    }
}

// single-block exclusive scan of g_deg -> g_offs
__global__ void k_scan(int n) {
    __shared__ int sm[1024];
    int t = threadIdx.x;
    int chunk = (n + 1023) / 1024;
    int lo = t * chunk;
    int hi = min(n, lo + chunk);
    int s = 0;
    for (int i = lo; i < hi; i++) s += g_deg[i];
    sm[t] = s;
    __syncthreads();
    for (int d = 1; d < 1024; d <<= 1) {
        int v = (t >= d) ? sm[t - d] : 0;
        __syncthreads();
        sm[t] += v;
        __syncthreads();
    }
    int off = sm[t] - s;   // exclusive
    for (int i = lo; i < hi; i++) { g_offs[i] = off; off += g_deg[i]; }
    if (t == 1023) g_offs[n] = sm[1023];
}

__global__ void k_fill(const int* __restrict__ src, const int* __restrict__ dst, int E) {
    int e = blockIdx.x * blockDim.x + threadIdx.x;
    if (e < E) {
        int d = dst[e];
        int p = atomicAdd(&g_cursor[d], 1);
        g_csr[g_offs[d] + p] = src[e];
    }
}

// ---------------- GEMM: C = act(A @ B + bias), A[M,K], B[K,N] ----------------
template <int BM, int BN, int BK, int TM, int TN, bool RELU>
__global__ void __launch_bounds__((BM / TM) * (BN / TN))
k_gemm(const float* __restrict__ A, const float* __restrict__ B,
       const float* __restrict__ bias, float* __restrict__ C,
       int M, int N, int K) {
    constexpr int TX = BN / TN;
    constexpr int TY = BM / TM;
    constexpr int NT = TX * TY;
    __shared__ float As[BK][BM];
    __shared__ float Bs[BK][BN];

    int tid = threadIdx.x;
    int tx = tid % TX, ty = tid / TX;
    int bm = blockIdx.y * BM;
    int bn = blockIdx.x * BN;

    float acc[TM][TN];
#pragma unroll
    for (int i = 0; i < TM; i++)
#pragma unroll
        for (int j = 0; j < TN; j++) acc[i][j] = 0.f;

    constexpr int A_F4 = BM * BK / 4;
    constexpr int B_F4 = BK * BN / 4;

    for (int k0 = 0; k0 < K; k0 += BK) {
#pragma unroll
        for (int i = tid; i < A_F4; i += NT) {
            int r = i / (BK / 4);
            int c4 = i % (BK / 4);
            int gm = bm + r;
            float4 v = make_float4(0.f, 0.f, 0.f, 0.f);
            if (gm < M)
                v = *reinterpret_cast<const float4*>(A + (size_t)gm * K + k0 + c4 * 4);
            As[c4 * 4 + 0][r] = v.x;
            As[c4 * 4 + 1][r] = v.y;
            As[c4 * 4 + 2][r] = v.z;
            As[c4 * 4 + 3][r] = v.w;
        }
#pragma unroll
        for (int i = tid; i < B_F4; i += NT) {
            int r = i / (BN / 4);
            int c4 = i % (BN / 4);
            float4 v = *reinterpret_cast<const float4*>(B + (size_t)(k0 + r) * N + bn + c4 * 4);
            *reinterpret_cast<float4*>(&Bs[r][c4 * 4]) = v;
        }
        __syncthreads();

#pragma unroll
        for (int k = 0; k < BK; k++) {
            float a[TM], b[TN];
#pragma unroll
            for (int i = 0; i < TM; i++) a[i] = As[k][ty * TM + i];
#pragma unroll
            for (int j = 0; j < TN; j++) b[j] = Bs[k][tx * TN + j];
#pragma unroll
            for (int i = 0; i < TM; i++)
#pragma unroll
                for (int j = 0; j < TN; j++) acc[i][j] = fmaf(a[i], b[j], acc[i][j]);
        }
        __syncthreads();
    }

#pragma unroll
    for (int i = 0; i < TM; i++) {
        int gm = bm + ty * TM + i;
        if (gm >= M) continue;
#pragma unroll
        for (int j = 0; j < TN; j += 4) {
            int gn = bn + tx * TN + j;
            float4 o;
            o.x = acc[i][j + 0] + bias[gn + 0];
            o.y = acc[i][j + 1] + bias[gn + 1];
            o.z = acc[i][j + 2] + bias[gn + 2];
            o.w = acc[i][j + 3] + bias[gn + 3];
            if (RELU) {
                o.x = fmaxf(o.x, 0.f); o.y = fmaxf(o.y, 0.f);
                o.z = fmaxf(o.z, 0.f); o.w = fmaxf(o.w, 0.f);
            }
            *reinterpret_cast<float4*>(C + (size_t)gm * N + gn) = o;
        }
    }
}

// ---------------- message transform: m = mean*att*n1, v = var*att^2*n2 ----------------
__device__ __forceinline__ void msg1(float& m, float& v, float n1, float n2) {
    float att = expf(-v);
    m = m * att * n1;
    v = v * att * att * n2;
}

__global__ void k_msg(float* __restrict__ mbuf, float* __restrict__ vbuf, int total4, int D4) {
    int idx = blockIdx.x * blockDim.x + threadIdx.x;
    if (idx >= total4) return;
    int row = idx / D4;
    float n1 = g_norm1[row], n2 = g_norm2[row];
    float4 m = reinterpret_cast<float4*>(mbuf)[idx];
    float4 v = reinterpret_cast<float4*>(vbuf)[idx];
    msg1(m.x, v.x, n1, n2);
    msg1(m.y, v.y, n1, n2);
    msg1(m.z, v.z, n1, n2);
    msg1(m.w, v.w, n1, n2);
    reinterpret_cast<float4*>(mbuf)[idx] = m;
    reinterpret_cast<float4*>(vbuf)[idx] = v;
}

// ---------------- aggregation: warp per node, CSR pure-read reduce ----------------
template <int VEC, bool RELU>
__global__ void k_agg(const float* __restrict__ msrc, const float* __restrict__ vsrc,
                      float* __restrict__ mdst, float* __restrict__ vdst, int n) {
    int warp = (blockIdx.x * blockDim.x + threadIdx.x) >> 5;
    int lane = threadIdx.x & 31;
    if (warp >= n) return;
    const int D = VEC * 32;
    int start = g_offs[warp], end = g_offs[warp + 1];

    float am[VEC], av[VEC];
#pragma unroll
    for (int j = 0; j < VEC; j++) { am[j] = 0.f; av[j] = 0.f; }

    for (int e = start; e < end; e++) {
        int s = g_csr[e];
        const float* pm = msrc + (size_t)s * D + lane * VEC;
        const float* pv = vsrc + (size_t)s * D + lane * VEC;
        if (VEC == 4) {
            float4 a = __ldg(reinterpret_cast<const float4*>(pm));
            float4 b = __ldg(reinterpret_cast<const float4*>(pv));
            am[0] += a.x; am[1] += a.y; am[2] += a.z; am[3] += a.w;
            av[0] += b.x; av[1] += b.y; av[2] += b.z; av[3] += b.w;
        } else {
            float2 a = __ldg(reinterpret_cast<const float2*>(pm));
            float2 b = __ldg(reinterpret_cast<const float2*>(pv));
            am[0] += a.x; am[1] += a.y;
            av[0] += b.x; av[1] += b.y;
        }
    }

    float n1 = g_norm1[warp], n2 = g_norm2[warp];
#pragma unroll
    for (int j = 0; j < VEC; j++) {
        am[j] *= n1;
        av[j] *= n2;
        if (RELU) { am[j] = fmaxf(am[j], 0.f); av[j] = fmaxf(av[j], 0.f); }
    }
    float* om = mdst + (size_t)warp * D + lane * VEC;
    float* ov = vdst + (size_t)warp * D + lane * VEC;
    if (VEC == 4) {
        *reinterpret_cast<float4*>(om) = make_float4(am[0], am[1], am[2], am[3]);
        *reinterpret_cast<float4*>(ov) = make_float4(av[0], av[1], av[2], av[3]);
    } else {
        *reinterpret_cast<float2*>(om) = make_float2(am[0], am[1]);
        *reinterpret_cast<float2*>(ov) = make_float2(av[0], av[1]);
    }
}

// ---------------- threefry-2x32-20 (KAT-verified) ----------------
__device__ __forceinline__ uint32_t rotl32(uint32_t x, int d) {
    return (x << d) | (x >> (32 - d));
}

__device__ __forceinline__ void threefry2x32(uint32_t k0, uint32_t k1,
                                             uint32_t& x0, uint32_t& x1) {
    uint32_t s0 = k0, s1 = k1, s2 = k0 ^ k1 ^ 0x1BD11BDAu;
    x0 += s0; x1 += s1;
#define TFR(r) { x0 += x1; x1 = rotl32(x1, r); x1 ^= x0; }
    TFR(13) TFR(15) TFR(26) TFR(6)   x0 += s1; x1 += s2 + 1u;
    TFR(17) TFR(29) TFR(16) TFR(24)  x0 += s2; x1 += s0 + 2u;
    TFR(13) TFR(15) TFR(26) TFR(6)   x0 += s0; x1 += s1 + 3u;
    TFR(17) TFR(29) TFR(16) TFR(24)  x0 += s1; x1 += s2 + 4u;
    TFR(13) TFR(15) TFR(26) TFR(6)   x0 += s2; x1 += s0 + 5u;
#undef TFR
}

__device__ __forceinline__ float jax_normal_from_bits(uint32_t bits) {
    // jax _uniform: u01 in [0,1) from top-23 bits; u = u01*(hi-lo)+lo; max(lo,u)
    uint32_t fb = (bits >> 9) | 0x3F800000u;
    float u01 = __uint_as_float(fb) - 1.0f;
    const float lo = -0.99999994f;                    // nextafterf(-1,0)
    float u = u01 * 2.0f + lo;                        // (hi-lo) rounds to 2.0f in f32
    u = fmaxf(u, lo);
    return 1.41421356f * erfinvf(u);
}

// Partitionable threefry (modern JAX default): per-element counter (hi=0, lo=i),
// 32-bit output = out0 ^ out1.
__global__ void k_final(float* __restrict__ out, int total) {
    int t = blockIdx.x * blockDim.x + threadIdx.x;
    if (t >= total) return;
    uint32_t x0 = 0u;
    uint32_t x1 = (uint32_t)t;
    threefry2x32(0u, 42u, x0, x1);   // jax.random.key(42) -> (0, 42)
    uint32_t bits = x0 ^ x1;
    float e = jax_normal_from_bits(bits);
    float m = g_aggM[t];
    float v = g_aggV[t];
    out[t] = e * sqrtf(v + 1e-8f) + m;
}

// ---------------- launch ----------------
extern "C" void kernel_launch(void* const* d_in, const int* in_sizes, int n_in,
                              void* d_out, int out_size) {
    const float* x       = (const float*)d_in[0];
    const int*   src     = (const int*)d_in[1];
    const int*   dst     = (const int*)d_in[2];
    const float* w_mean1 = (const float*)d_in[3];
    const float* w_var1  = (const float*)d_in[4];
    const float* b_mean1 = (const float*)d_in[5];
    const float* b_var1  = (const float*)d_in[6];
    const float* w_mean2 = (const float*)d_in[7];
    const float* w_var2  = (const float*)d_in[8];
    const float* b_mean2 = (const float*)d_in[9];
    const float* b_var2  = (const float*)d_in[10];
    float* out = (float*)d_out;

    const int N = in_sizes[0] / IN_F;   // 100000
    const int E = in_sizes[1];          // 1600000

    float* bufA = nullptr; float* bufB = nullptr;
    float* aggM = nullptr; float* aggV = nullptr;
    cudaGetSymbolAddress((void**)&bufA, g_bufA);
    cudaGetSymbolAddress((void**)&bufB, g_bufB);
    cudaGetSymbolAddress((void**)&aggM, g_aggM);
    cudaGetSymbolAddress((void**)&aggV, g_aggV);

    const int T = 256;

    // degrees, norms, CSR
    k_zero<<<(N + T - 1) / T, T>>>(N);
    k_count<<<(E + T - 1) / T, T>>>(dst, E);
    k_norm<<<(N + T - 1) / T, T>>>(N);
    k_scan<<<1, 1024>>>(N);
    k_fill<<<(E + T - 1) / T, T>>>(src, dst, E);

    // ---- layer 1 ----
    {
        dim3 grid(HID / 128, (N + 127) / 128);
        k_gemm<128, 128, 8, 8, 8, true><<<grid, 256>>>(x, w_mean1, b_mean1, bufA, N, HID, IN_F);
        k_gemm<128, 128, 8, 8, 8, true><<<grid, 256>>>(x, w_var1,  b_var1,  bufB, N, HID, IN_F);
    }
    {
        int total4 = N * HID / 4;
        k_msg<<<(total4 + T - 1) / T, T>>>(bufA, bufB, total4, HID / 4);
    }
    {
        int blocks = (N * 32 + T - 1) / T;   // warp per node
        k_agg<4, true><<<blocks, T>>>(bufA, bufB, aggM, aggV, N);
    }

    // ---- layer 2 ----
    {
        dim3 grid(OUTF / 64, (N + 127) / 128);
        k_gemm<128, 64, 8, 8, 8, true><<<grid, 128>>>(aggM, w_mean2, b_mean2, bufA, N, OUTF, HID);
        k_gemm<128, 64, 8, 8, 8, true><<<grid, 128>>>(aggV, w_var2,  b_var2,  bufB, N, OUTF, HID);
    }
    {
        int total4 = N * OUTF / 4;
        k_msg<<<(total4 + T - 1) / T, T>>>(bufA, bufB, total4, OUTF / 4);
    }
    {
        int blocks = (N * 32 + T - 1) / T;
        k_agg<2, false><<<blocks, T>>>(bufA, bufB, aggM, aggV, N);
    }

    // ---- reparameterize: partitionable-threefry normal(key(42)) ----
    {
        int total = N * OUTF;
        k_final<<<(total + T - 1) / T, T>>>(out, total);
    }
}

// round 4
// speedup vs baseline: 1.1229x; 1.1229x over previous
#include <cuda_runtime.h>
#include <stdint.h>
#include <math.h>

#define NODES_MAX 100000
#define EDGES_MAX 1600000
#define IN_F 256
#define HID 128
#define OUTF 64

// ---------------- scratch (static __device__, no allocs) ----------------
__device__ float g_bufA[(size_t)NODES_MAX * HID];   // messages m
__device__ float g_bufB[(size_t)NODES_MAX * HID];   // messages v
__device__ float g_aggM[(size_t)NODES_MAX * HID];   // aggregated mean
__device__ float g_aggV[(size_t)NODES_MAX * HID];
__device__ float g_norm1[NODES_MAX];
__device__ float g_norm2[NODES_MAX];
__device__ int   g_deg[NODES_MAX];
__device__ int   g_cursor[NODES_MAX];
__device__ int   g_offs[NODES_MAX + 1];
__device__ int   g_csr[EDGES_MAX];
__device__ int   g_bsum[128];
__device__ int   g_boff[128];

// ---------------- degree / norms ----------------
__global__ void k_zero(int n) {
    int i = blockIdx.x * blockDim.x + threadIdx.x;
    if (i < n) { g_deg[i] = 0; g_cursor[i] = 0; }
}

__global__ void k_count(const int* __restrict__ dst, int E) {
    int e = blockIdx.x * blockDim.x + threadIdx.x;
    if (e < E) atomicAdd(&g_deg[dst[e]], 1);
}

__global__ void k_norm(int n) {
    int i = blockIdx.x * blockDim.x + threadIdx.x;
    if (i < n) {
        float d = fmaxf((float)g_deg[i], 1.0f);
        float n1 = 1.0f / sqrtf(d);
        g_norm1[i] = n1;
        g_norm2[i] = n1 * n1;
    }
}

// ---------------- parallel 3-phase exclusive scan ----------------
__global__ void k_scan1(int n) {
    __shared__ int sm[1024];
    int t = threadIdx.x;
    int i = blockIdx.x * 1024 + t;
    int v = (i < n) ? g_deg[i] : 0;
    sm[t] = v;
    __syncthreads();
#pragma unroll
    for (int d = 1; d < 1024; d <<= 1) {
        int u = (t >= d) ? sm[t - d] : 0;
        __syncthreads();
        sm[t] += u;
        __syncthreads();
    }
    if (i < n) g_offs[i] = sm[t] - v;
    if (t == 1023) g_bsum[blockIdx.x] = sm[1023];
}

__global__ void k_scan2(int nb, int n) {
    __shared__ int sm[128];
    int t = threadIdx.x;
    int v = (t < nb) ? g_bsum[t] : 0;
    sm[t] = v;
    __syncthreads();
#pragma unroll
    for (int d = 1; d < 128; d <<= 1) {
        int u = (t >= d) ? sm[t - d] : 0;
        __syncthreads();
        sm[t] += u;
        __syncthreads();
    }
    if (t < nb) g_boff[t] = sm[t] - v;
    if (t == 127) g_offs[n] = sm[127];
}

__global__ void k_scan3(int n) {
    int i = blockIdx.x * 1024 + threadIdx.x;
    if (i < n) g_offs[i] += g_boff[blockIdx.x];
}

__global__ void k_fill(const int* __restrict__ src, const int* __restrict__ dst, int E) {
    int e = blockIdx.x * blockDim.x + threadIdx.x;
    if (e < E) {
        int d = dst[e];
        int p = atomicAdd(&g_cursor[d], 1);
        g_csr[g_offs[d] + p] = src[e];
    }
}

// ---------------- fused dual GEMM + message epilogue ----------------
// mean = relu(Am@Bm + bm); var = relu(Av@Bv + bv); att = exp(-var)
// Cm = mean*att*norm1[row]; Cv = var*att*att*norm2[row]
// DUAL_A=false: Av ignored, var path reads the same A tile (layer 1: mean_in==var_in).
template <int BM, int BN, int BK, int TM, int TN, int K, bool DUAL_A>
__global__ void __launch_bounds__((BM / TM) * (BN / TN))
k_gemm2(const float* __restrict__ Am, const float* __restrict__ Av,
        const float* __restrict__ Bm, const float* __restrict__ Bv,
        const float* __restrict__ bm, const float* __restrict__ bv,
        float* __restrict__ Cm, float* __restrict__ Cv, int M) {
    constexpr int TX = BN / TN;
    constexpr int TY = BM / TM;
    constexpr int NT = TX * TY;
    __shared__ float Asm[BK][BM];
    __shared__ float Asv[DUAL_A ? BK : 1][BM];
    __shared__ float Bms[BK][BN];
    __shared__ float Bvs[BK][BN];

    int tid = threadIdx.x;
    int tx = tid % TX, ty = tid / TX;
    int bm_base = blockIdx.x * BM;

    float accM[TM][TN], accV[TM][TN];
#pragma unroll
    for (int i = 0; i < TM; i++)
#pragma unroll
        for (int j = 0; j < TN; j++) { accM[i][j] = 0.f; accV[i][j] = 0.f; }

    constexpr int A_F4 = BM * BK / 4;
    constexpr int B_F4 = BK * BN / 4;

    for (int k0 = 0; k0 < K; k0 += BK) {
#pragma unroll
        for (int i = tid; i < A_F4; i += NT) {
            int r = i / (BK / 4);
            int c4 = i % (BK / 4);
            int gm = bm_base + r;
            float4 v = make_float4(0.f, 0.f, 0.f, 0.f);
            if (gm < M)
                v = *reinterpret_cast<const float4*>(Am + (size_t)gm * K + k0 + c4 * 4);
            Asm[c4 * 4 + 0][r] = v.x;
            Asm[c4 * 4 + 1][r] = v.y;
            Asm[c4 * 4 + 2][r] = v.z;
            Asm[c4 * 4 + 3][r] = v.w;
        }
        if (DUAL_A) {
#pragma unroll
            for (int i = tid; i < A_F4; i += NT) {
                int r = i / (BK / 4);
                int c4 = i % (BK / 4);
                int gm = bm_base + r;
                float4 v = make_float4(0.f, 0.f, 0.f, 0.f);
                if (gm < M)
                    v = *reinterpret_cast<const float4*>(Av + (size_t)gm * K + k0 + c4 * 4);
                Asv[c4 * 4 + 0][r] = v.x;
                Asv[c4 * 4 + 1][r] = v.y;
                Asv[c4 * 4 + 2][r] = v.z;
                Asv[c4 * 4 + 3][r] = v.w;
            }
        }
#pragma unroll
        for (int i = tid; i < B_F4; i += NT) {
            int r = i / (BN / 4);
            int c4 = i % (BN / 4);
            *reinterpret_cast<float4*>(&Bms[r][c4 * 4]) =
                *reinterpret_cast<const float4*>(Bm + (size_t)(k0 + r) * BN + c4 * 4);
        }
#pragma unroll
        for (int i = tid; i < B_F4; i += NT) {
            int r = i / (BN / 4);
            int c4 = i % (BN / 4);
            *reinterpret_cast<float4*>(&Bvs[r][c4 * 4]) =
                *reinterpret_cast<const float4*>(Bv + (size_t)(k0 + r) * BN + c4 * 4);
        }
        __syncthreads();

#pragma unroll
        for (int k = 0; k < BK; k++) {
            float am[TM], av[TM], pm[TN], pv[TN];
#pragma unroll
            for (int i = 0; i < TM; i += 4)
                *reinterpret_cast<float4*>(&am[i]) =
                    *reinterpret_cast<const float4*>(&Asm[k][ty * TM + i]);
            if (DUAL_A) {
#pragma unroll
                for (int i = 0; i < TM; i += 4)
                    *reinterpret_cast<float4*>(&av[i]) =
                        *reinterpret_cast<const float4*>(&Asv[DUAL_A ? k : 0][ty * TM + i]);
            }
#pragma unroll
            for (int j = 0; j < TN; j += 4)
                *reinterpret_cast<float4*>(&pm[j]) =
                    *reinterpret_cast<const float4*>(&Bms[k][tx * TN + j]);
#pragma unroll
            for (int j = 0; j < TN; j += 4)
                *reinterpret_cast<float4*>(&pv[j]) =
                    *reinterpret_cast<const float4*>(&Bvs[k][tx * TN + j]);
#pragma unroll
            for (int i = 0; i < TM; i++)
#pragma unroll
                for (int j = 0; j < TN; j++) {
                    accM[i][j] = fmaf(am[i], pm[j], accM[i][j]);
                    accV[i][j] = fmaf(DUAL_A ? av[i] : am[i], pv[j], accV[i][j]);
                }
        }
        __syncthreads();
    }

#pragma unroll
    for (int i = 0; i < TM; i++) {
        int gm = bm_base + ty * TM + i;
        if (gm >= M) continue;
        float n1 = g_norm1[gm];
        float n2 = g_norm2[gm];
#pragma unroll
        for (int j = 0; j < TN; j += 4) {
            int gn = tx * TN + j;
            float4 om, ov;
            float* pm = &om.x;
            float* pv = &ov.x;
#pragma unroll
            for (int q = 0; q < 4; q++) {
                float mean = fmaxf(accM[i][j + q] + bm[gn + q], 0.f);
                float var  = fmaxf(accV[i][j + q] + bv[gn + q], 0.f);
                float att  = expf(-var);
                pm[q] = mean * att * n1;
                pv[q] = var * att * att * n2;
            }
            *reinterpret_cast<float4*>(Cm + (size_t)gm * BN + gn) = om;
            *reinterpret_cast<float4*>(Cv + (size_t)gm * BN + gn) = ov;
        }
    }
}

// ---------------- aggregation: warp per node, CSR pure-read reduce ----------------
__global__ void k_agg1(const float* __restrict__ msrc, const float* __restrict__ vsrc,
                       float* __restrict__ mdst, float* __restrict__ vdst, int n) {
    int warp = (blockIdx.x * blockDim.x + threadIdx.x) >> 5;
    int lane = threadIdx.x & 31;
    if (warp >= n) return;
    const int D = 128;
    int start = g_offs[warp], end = g_offs[warp + 1];

    float am[4] = {0.f, 0.f, 0.f, 0.f};
    float av[4] = {0.f, 0.f, 0.f, 0.f};
    for (int e = start; e < end; e++) {
        int s = g_csr[e];
        float4 a = __ldg(reinterpret_cast<const float4*>(msrc + (size_t)s * D + lane * 4));
        float4 b = __ldg(reinterpret_cast<const float4*>(vsrc + (size_t)s * D + lane * 4));
        am[0] += a.x; am[1] += a.y; am[2] += a.z; am[3] += a.w;
        av[0] += b.x; av[1] += b.y; av[2] += b.z; av[3] += b.w;
    }
    float n1 = g_norm1[warp], n2 = g_norm2[warp];
#pragma unroll
    for (int j = 0; j < 4; j++) {
        am[j] = fmaxf(am[j] * n1, 0.f);
        av[j] = fmaxf(av[j] * n2, 0.f);
    }
    *reinterpret_cast<float4*>(mdst + (size_t)warp * D + lane * 4) =
        make_float4(am[0], am[1], am[2], am[3]);
    *reinterpret_cast<float4*>(vdst + (size_t)warp * D + lane * 4) =
        make_float4(av[0], av[1], av[2], av[3]);
}

// ---------------- threefry-2x32-20 (KAT-verified) ----------------
__device__ __forceinline__ uint32_t rotl32(uint32_t x, int d) {
    return (x << d) | (x >> (32 - d));
}

__device__ __forceinline__ void threefry2x32(uint32_t k0, uint32_t k1,
                                             uint32_t& x0, uint32_t& x1) {
    uint32_t s0 = k0, s1 = k1, s2 = k0 ^ k1 ^ 0x1BD11BDAu;
    x0 += s0; x1 += s1;
#define TFR(r) { x0 += x1; x1 = rotl32(x1, r); x1 ^= x0; }
    TFR(13) TFR(15) TFR(26) TFR(6)   x0 += s1; x1 += s2 + 1u;
    TFR(17) TFR(29) TFR(16) TFR(24)  x0 += s2; x1 += s0 + 2u;
    TFR(13) TFR(15) TFR(26) TFR(6)   x0 += s0; x1 += s1 + 3u;
    TFR(17) TFR(29) TFR(16) TFR(24)  x0 += s1; x1 += s2 + 4u;
    TFR(13) TFR(15) TFR(26) TFR(6)   x0 += s2; x1 += s0 + 5u;
#undef TFR
}

__device__ __forceinline__ float jax_normal_elem(uint32_t idx) {
    uint32_t x0 = 0u, x1 = idx;
    threefry2x32(0u, 42u, x0, x1);
    uint32_t bits = x0 ^ x1;
    uint32_t fb = (bits >> 9) | 0x3F800000u;
    float u01 = __uint_as_float(fb) - 1.0f;
    const float lo = -0.99999994f;
    float u = fmaxf(u01 * 2.0f + lo, lo);
    return 1.41421356f * erfinvf(u);
}

// layer-2 aggregation fused with reparameterization: warp per node, VEC=2, D=64
__global__ void k_agg2_final(const float* __restrict__ msrc, const float* __restrict__ vsrc,
                             float* __restrict__ out, int n) {
    int warp = (blockIdx.x * blockDim.x + threadIdx.x) >> 5;
    int lane = threadIdx.x & 31;
    if (warp >= n) return;
    const int D = 64;
    int start = g_offs[warp], end = g_offs[warp + 1];

    float am0 = 0.f, am1 = 0.f, av0 = 0.f, av1 = 0.f;
    for (int e = start; e < end; e++) {
        int s = g_csr[e];
        float2 a = __ldg(reinterpret_cast<const float2*>(msrc + (size_t)s * D + lane * 2));
        float2 b = __ldg(reinterpret_cast<const float2*>(vsrc + (size_t)s * D + lane * 2));
        am0 += a.x; am1 += a.y;
        av0 += b.x; av1 += b.y;
    }
    float n1 = g_norm1[warp], n2 = g_norm2[warp];
    float m0 = am0 * n1, m1 = am1 * n1;
    float v0 = av0 * n2, v1 = av1 * n2;

    uint32_t t0 = (uint32_t)(warp * D + lane * 2);
    float e0 = jax_normal_elem(t0);
    float e1 = jax_normal_elem(t0 + 1u);
    float2 o;
    o.x = e0 * sqrtf(v0 + 1e-8f) + m0;
    o.y = e1 * sqrtf(v1 + 1e-8f) + m1;
    *reinterpret_cast<float2*>(out + (size_t)warp * D + lane * 2) = o;
}

// ---------------- launch ----------------
extern "C" void kernel_launch(void* const* d_in, const int* in_sizes, int n_in,
                              void* d_out, int out_size) {
    const float* x       = (const float*)d_in[0];
    const int*   src     = (const int*)d_in[1];
    const int*   dst     = (const int*)d_in[2];
    const float* w_mean1 = (const float*)d_in[3];
    const float* w_var1  = (const float*)d_in[4];
    const float* b_mean1 = (const float*)d_in[5];
    const float* b_var1  = (const float*)d_in[6];
    const float* w_mean2 = (const float*)d_in[7];
    const float* w_var2  = (const float*)d_in[8];
    const float* b_mean2 = (const float*)d_in[9];
    const float* b_var2  = (const float*)d_in[10];
    float* out = (float*)d_out;

    const int N = in_sizes[0] / IN_F;   // 100000
    const int E = in_sizes[1];          // 1600000

    float* bufA = nullptr; float* bufB = nullptr;
    float* aggM = nullptr; float* aggV = nullptr;
    cudaGetSymbolAddress((void**)&bufA, g_bufA);
    cudaGetSymbolAddress((void**)&bufB, g_bufB);
    cudaGetSymbolAddress((void**)&aggM, g_aggM);
    cudaGetSymbolAddress((void**)&aggV, g_aggV);

    const int T = 256;
    const int NB = (N + 1023) / 1024;

    // degrees, norms, CSR
    k_zero<<<(N + T - 1) / T, T>>>(N);
    k_count<<<(E + T - 1) / T, T>>>(dst, E);
    k_norm<<<(N + T - 1) / T, T>>>(N);
    k_scan1<<<NB, 1024>>>(N);
    k_scan2<<<1, 128>>>(NB, N);
    k_scan3<<<NB, 1024>>>(N);
    k_fill<<<(E + T - 1) / T, T>>>(src, dst, E);

    // ---- layer 1: fused dual GEMM (shared A) + msg epilogue ----
    {
        int blocks = (N + 127) / 128;
        k_gemm2<128, 128, 8, 8, 8, IN_F, false><<<blocks, 256>>>(
            x, x, w_mean1, w_var1, b_mean1, b_var1, bufA, bufB, N);
    }
    {
        int blocks = (N * 32 + T - 1) / T;   // warp per node
        k_agg1<<<blocks, T>>>(bufA, bufB, aggM, aggV, N);
    }

    // ---- layer 2: fused dual GEMM (separate A) + msg epilogue ----
    {
        int blocks = (N + 127) / 128;
        k_gemm2<128, 64, 8, 8, 8, HID, true><<<blocks, 128>>>(
            aggM, aggV, w_mean2, w_var2, b_mean2, b_var2, bufA, bufB, N);
    }
    // ---- layer-2 aggregation fused with threefry reparameterization ----
    {
        int blocks = (N * 32 + T - 1) / T;
        k_agg2_final<<<blocks, T>>>(bufA, bufB, out, N);
    }
}

// round 5
// speedup vs baseline: 1.4745x; 1.3130x over previous
#include <cuda_runtime.h>
#include <stdint.h>
#include <math.h>

#define NODES_MAX 100000
#define M_PAD     100096   // 782 * 128
#define EDGES_MAX 1600000
#define IN_F 256
#define HID 128
#define OUTF 64

// ---------------- scratch (static __device__, no allocs) ----------------
__device__ float g_bufA[(size_t)M_PAD * HID];   // messages m
__device__ float g_bufB[(size_t)M_PAD * HID];   // messages v
__device__ float g_aggM[(size_t)M_PAD * HID];   // aggregated mean
__device__ float g_aggV[(size_t)M_PAD * HID];
__device__ float g_norm1[M_PAD];
__device__ float g_norm2[M_PAD];
__device__ int   g_deg[NODES_MAX];
__device__ int   g_cursor[NODES_MAX];
__device__ int   g_offs[NODES_MAX + 1];
__device__ int   g_csr[EDGES_MAX];
__device__ int   g_bsum[128];
__device__ int   g_boff[128];

// ---------------- degree / norms ----------------
__global__ void k_zero(int n) {
    int i = blockIdx.x * blockDim.x + threadIdx.x;
    if (i < n) { g_deg[i] = 0; g_cursor[i] = 0; }
}

__global__ void k_count(const int* __restrict__ dst, int E) {
    int e = blockIdx.x * blockDim.x + threadIdx.x;
    if (e < E) atomicAdd(&g_deg[dst[e]], 1);
}

__global__ void k_norm(int n) {
    int i = blockIdx.x * blockDim.x + threadIdx.x;
    if (i < n) {
        float d = fmaxf((float)g_deg[i], 1.0f);
        float n1 = 1.0f / sqrtf(d);
        g_norm1[i] = n1;
        g_norm2[i] = n1 * n1;
    }
}

// ---------------- parallel 3-phase exclusive scan ----------------
__global__ void k_scan1(int n) {
    __shared__ int sm[1024];
    int t = threadIdx.x;
    int i = blockIdx.x * 1024 + t;
    int v = (i < n) ? g_deg[i] : 0;
    sm[t] = v;
    __syncthreads();
#pragma unroll
    for (int d = 1; d < 1024; d <<= 1) {
        int u = (t >= d) ? sm[t - d] : 0;
        __syncthreads();
        sm[t] += u;
        __syncthreads();
    }
    if (i < n) g_offs[i] = sm[t] - v;
    if (t == 1023) g_bsum[blockIdx.x] = sm[1023];
}

__global__ void k_scan2(int nb, int n) {
    __shared__ int sm[128];
    int t = threadIdx.x;
    int v = (t < nb) ? g_bsum[t] : 0;
    sm[t] = v;
    __syncthreads();
#pragma unroll
    for (int d = 1; d < 128; d <<= 1) {
        int u = (t >= d) ? sm[t - d] : 0;
        __syncthreads();
        sm[t] += u;
        __syncthreads();
    }
    if (t < nb) g_boff[t] = sm[t] - v;
    if (t == 127) g_offs[n] = sm[127];
}

__global__ void k_scan3(int n) {
    int i = blockIdx.x * 1024 + threadIdx.x;
    if (i < n) g_offs[i] += g_boff[blockIdx.x];
}

__global__ void k_fill(const int* __restrict__ src, const int* __restrict__ dst, int E) {
    int e = blockIdx.x * blockDim.x + threadIdx.x;
    if (e < E) {
        int d = dst[e];
        int p = atomicAdd(&g_cursor[d], 1);
        g_csr[g_offs[d] + p] = src[e];
    }
}

// ================= layer-1 tensor-core GEMM (3xTF32) =================
// grid: (ceil(M/128), 2). Each CTA: 128 rows x 64 HID-cols, BOTH mean and var
// accumulators (epilogue couples them via att=exp(-var)).
// 8 warps: warp_m = wid&3 (32 rows), warp_n = wid>>2 (32 cols).
// Per warp: 2 M-tiles(16) x 4 N-tiles(8) x 2 matrices, m16n8k8 tf32 mma, 3x split.

__device__ __forceinline__ uint32_t cvt_tf32(float x) {
    uint32_t r;
    asm("cvt.rna.tf32.f32 %0, %1;" : "=r"(r) : "f"(x));
    return r;
}

__device__ __forceinline__ void mma_tf32(float* d, uint32_t a0, uint32_t a1,
                                         uint32_t a2, uint32_t a3,
                                         uint32_t b0, uint32_t b1) {
    asm volatile(
        "mma.sync.aligned.m16n8k8.row.col.f32.tf32.tf32.f32 "
        "{%0,%1,%2,%3},{%4,%5,%6,%7},{%8,%9},{%0,%1,%2,%3};"
        : "+f"(d[0]), "+f"(d[1]), "+f"(d[2]), "+f"(d[3])
        : "r"(a0), "r"(a1), "r"(a2), "r"(a3), "r"(b0), "r"(b1));
}

__device__ __forceinline__ void cp16(uint32_t dst, const void* src, int sz) {
    asm volatile("cp.async.cg.shared.global [%0], [%1], 16, %2;"
                 :: "r"(dst), "l"(src), "r"(sz));
}
__device__ __forceinline__ void cp_commit() {
    asm volatile("cp.async.commit_group;");
}
template <int N> __device__ __forceinline__ void cp_wait() {
    asm volatile("cp.async.wait_group %0;" :: "n"(N));
}

#define L1_APAD 20    // floats per A smem row (16 + 4), conflict-free frag reads
#define L1_BPAD 136   // floats per B smem row (128 + 8)

__global__ void __launch_bounds__(256)
k_l1_tf32(const float* __restrict__ X,
          const float* __restrict__ Wm, const float* __restrict__ Wv,   // [256][128]
          const float* __restrict__ bm, const float* __restrict__ bv,
          float* __restrict__ Cm, float* __restrict__ Cv, int M) {
    __shared__ float As[2][128 * L1_APAD];
    __shared__ float Bs[2][16 * L1_BPAD];

    const int tid = threadIdx.x;
    const int lane = tid & 31;
    const int wid = tid >> 5;
    const int warp_m = wid & 3;       // 0..3 -> 32-row band
    const int warp_n = wid >> 2;      // 0..1 -> 32-col band
    const int gid = lane >> 2;        // groupID 0..7
    const int tig = lane & 3;         // thread-in-group 0..3
    const int bm_base = blockIdx.x * 128;
    const int col_half = blockIdx.y * 64;   // HID column offset

    float acc[2][2][4][4];   // [matrix][mt][nt][reg]
#pragma unroll
    for (int a = 0; a < 2; a++)
#pragma unroll
        for (int b = 0; b < 2; b++)
#pragma unroll
            for (int c = 0; c < 4; c++)
#pragma unroll
                for (int d = 0; d < 4; d++) acc[a][b][c][d] = 0.f;

    uint32_t asbase[2], bsbase[2];
    asbase[0] = (uint32_t)__cvta_generic_to_shared(&As[0][0]);
    asbase[1] = (uint32_t)__cvta_generic_to_shared(&As[1][0]);
    bsbase[0] = (uint32_t)__cvta_generic_to_shared(&Bs[0][0]);
    bsbase[1] = (uint32_t)__cvta_generic_to_shared(&Bs[1][0]);

    auto issue = [&](int stage, int k0) {
        // A tile: 128 rows x 16 k, 512 x 16B chunks
#pragma unroll
        for (int c = tid; c < 512; c += 256) {
            int r = c >> 2, kq = c & 3;
            int gm = bm_base + r;
            int ok = (gm < M) ? 16 : 0;
            const float* src = X + (size_t)min(gm, M - 1) * IN_F + k0 + kq * 4;
            cp16(asbase[stage] + (uint32_t)(r * L1_APAD + kq * 4) * 4, src, ok);
        }
        // B tile: 16 k-rows x (64 m-cols | 64 v-cols), 512 chunks
#pragma unroll
        for (int c = tid; c < 512; c += 256) {
            int r = c >> 5, cc = c & 31;
            int mat = cc >> 4, q = cc & 15;
            const float* srcb = (mat ? Wv : Wm) + (size_t)(k0 + r) * HID + col_half + q * 4;
            cp16(bsbase[stage] + (uint32_t)(r * L1_BPAD + mat * 64 + q * 4) * 4, srcb, 16);
        }
        cp_commit();
    };

    issue(0, 0);

    const int NITER = IN_F / 16;   // 16
    for (int it = 0; it < NITER; it++) {
        int stage = it & 1;
        if (it + 1 < NITER) {
            issue(stage ^ 1, (it + 1) * 16);
            cp_wait<1>();
        } else {
            cp_wait<0>();
        }
        __syncthreads();

        const float* as = As[stage];
        const float* bs = Bs[stage];

#pragma unroll
        for (int ks = 0; ks < 2; ks++) {
            const int k8 = ks * 8;
            // ---- A fragments (2 M-tiles) ----
            uint32_t ahi[8], alo[8];
#pragma unroll
            for (int mt = 0; mt < 2; mt++) {
                int rb = warp_m * 32 + mt * 16;
                float a0 = as[(rb + gid) * L1_APAD + k8 + tig];
                float a1 = as[(rb + gid + 8) * L1_APAD + k8 + tig];
                float a2 = as[(rb + gid) * L1_APAD + k8 + tig + 4];
                float a3 = as[(rb + gid + 8) * L1_APAD + k8 + tig + 4];
                ahi[mt * 4 + 0] = cvt_tf32(a0);
                ahi[mt * 4 + 1] = cvt_tf32(a1);
                ahi[mt * 4 + 2] = cvt_tf32(a2);
                ahi[mt * 4 + 3] = cvt_tf32(a3);
                alo[mt * 4 + 0] = cvt_tf32(a0 - __uint_as_float(ahi[mt * 4 + 0]));
                alo[mt * 4 + 1] = cvt_tf32(a1 - __uint_as_float(ahi[mt * 4 + 1]));
                alo[mt * 4 + 2] = cvt_tf32(a2 - __uint_as_float(ahi[mt * 4 + 2]));
                alo[mt * 4 + 3] = cvt_tf32(a3 - __uint_as_float(ahi[mt * 4 + 3]));
            }
            // ---- per matrix: B fragments + mma ----
#pragma unroll
            for (int mat = 0; mat < 2; mat++) {
                uint32_t bhi[8], blo[8];
#pragma unroll
                for (int nt = 0; nt < 4; nt++) {
                    int col = mat * 64 + warp_n * 32 + nt * 8 + gid;
                    float b0 = bs[(k8 + tig) * L1_BPAD + col];
                    float b1 = bs[(k8 + tig + 4) * L1_BPAD + col];
                    bhi[nt * 2 + 0] = cvt_tf32(b0);
                    bhi[nt * 2 + 1] = cvt_tf32(b1);
                    blo[nt * 2 + 0] = cvt_tf32(b0 - __uint_as_float(bhi[nt * 2 + 0]));
                    blo[nt * 2 + 1] = cvt_tf32(b1 - __uint_as_float(bhi[nt * 2 + 1]));
                }
#pragma unroll
                for (int mt = 0; mt < 2; mt++)
#pragma unroll
                    for (int nt = 0; nt < 4; nt++) {
                        float* d = acc[mat][mt][nt];
                        mma_tf32(d, ahi[mt*4], ahi[mt*4+1], ahi[mt*4+2], ahi[mt*4+3],
                                 bhi[nt*2], bhi[nt*2+1]);
                        mma_tf32(d, ahi[mt*4], ahi[mt*4+1], ahi[mt*4+2], ahi[mt*4+3],
                                 blo[nt*2], blo[nt*2+1]);
                        mma_tf32(d, alo[mt*4], alo[mt*4+1], alo[mt*4+2], alo[mt*4+3],
                                 bhi[nt*2], bhi[nt*2+1]);
                    }
            }
        }
        __syncthreads();
    }

    // ---- epilogue: bias + relu + att + norms, fused message transform ----
#pragma unroll
    for (int nt = 0; nt < 4; nt++) {
        int cl = warp_n * 32 + nt * 8 + tig * 2;
        int gc = col_half + cl;
        float bm0 = bm[gc], bm1 = bm[gc + 1];
        float bv0 = bv[gc], bv1 = bv[gc + 1];
#pragma unroll
        for (int mt = 0; mt < 2; mt++) {
#pragma unroll
            for (int half = 0; half < 2; half++) {
                int gm = bm_base + warp_m * 32 + mt * 16 + gid + half * 8;
                float n1 = g_norm1[gm];
                float n2 = g_norm2[gm];
                float mean0 = fmaxf(acc[0][mt][nt][half * 2 + 0] + bm0, 0.f);
                float mean1 = fmaxf(acc[0][mt][nt][half * 2 + 1] + bm1, 0.f);
                float var0  = fmaxf(acc[1][mt][nt][half * 2 + 0] + bv0, 0.f);
                float var1  = fmaxf(acc[1][mt][nt][half * 2 + 1] + bv1, 0.f);
                float att0 = expf(-var0), att1 = expf(-var1);
                float2 om = make_float2(mean0 * att0 * n1, mean1 * att1 * n1);
                float2 ov = make_float2(var0 * att0 * att0 * n2, var1 * att1 * att1 * n2);
                *reinterpret_cast<float2*>(Cm + (size_t)gm * HID + gc) = om;
                *reinterpret_cast<float2*>(Cv + (size_t)gm * HID + gc) = ov;
            }
        }
    }
}

// ---------------- layer-2 FFMA dual GEMM + message epilogue ----------------
template <int BM, int BN, int BK, int TM, int TN, int K>
__global__ void __launch_bounds__((BM / TM) * (BN / TN))
k_gemm2(const float* __restrict__ Am, const float* __restrict__ Av,
        const float* __restrict__ Bm, const float* __restrict__ Bv,
        const float* __restrict__ bm, const float* __restrict__ bv,
        float* __restrict__ Cm, float* __restrict__ Cv, int M) {
    constexpr int TX = BN / TN;
    constexpr int TY = BM / TM;
    constexpr int NT = TX * TY;
    __shared__ float Asm[BK][BM];
    __shared__ float Asv[BK][BM];
    __shared__ float Bms[BK][BN];
    __shared__ float Bvs[BK][BN];

    int tid = threadIdx.x;
    int tx = tid % TX, ty = tid / TX;
    int bm_base = blockIdx.x * BM;

    float accM[TM][TN], accV[TM][TN];
#pragma unroll
    for (int i = 0; i < TM; i++)
#pragma unroll
        for (int j = 0; j < TN; j++) { accM[i][j] = 0.f; accV[i][j] = 0.f; }

    constexpr int A_F4 = BM * BK / 4;
    constexpr int B_F4 = BK * BN / 4;

    for (int k0 = 0; k0 < K; k0 += BK) {
#pragma unroll
        for (int i = tid; i < A_F4; i += NT) {
            int r = i / (BK / 4);
            int c4 = i % (BK / 4);
            int gm = bm_base + r;
            float4 v = make_float4(0.f, 0.f, 0.f, 0.f);
            if (gm < M)
                v = *reinterpret_cast<const float4*>(Am + (size_t)gm * K + k0 + c4 * 4);
            Asm[c4 * 4 + 0][r] = v.x;
            Asm[c4 * 4 + 1][r] = v.y;
            Asm[c4 * 4 + 2][r] = v.z;
            Asm[c4 * 4 + 3][r] = v.w;
        }
#pragma unroll
        for (int i = tid; i < A_F4; i += NT) {
            int r = i / (BK / 4);
            int c4 = i % (BK / 4);
            int gm = bm_base + r;
            float4 v = make_float4(0.f, 0.f, 0.f, 0.f);
            if (gm < M)
                v = *reinterpret_cast<const float4*>(Av + (size_t)gm * K + k0 + c4 * 4);
            Asv[c4 * 4 + 0][r] = v.x;
            Asv[c4 * 4 + 1][r] = v.y;
            Asv[c4 * 4 + 2][r] = v.z;
            Asv[c4 * 4 + 3][r] = v.w;
        }
#pragma unroll
        for (int i = tid; i < B_F4; i += NT) {
            int r = i / (BN / 4);
            int c4 = i % (BN / 4);
            *reinterpret_cast<float4*>(&Bms[r][c4 * 4]) =
                *reinterpret_cast<const float4*>(Bm + (size_t)(k0 + r) * BN + c4 * 4);
        }
#pragma unroll
        for (int i = tid; i < B_F4; i += NT) {
            int r = i / (BN / 4);
            int c4 = i % (BN / 4);
            *reinterpret_cast<float4*>(&Bvs[r][c4 * 4]) =
                *reinterpret_cast<const float4*>(Bv + (size_t)(k0 + r) * BN + c4 * 4);
        }
        __syncthreads();

#pragma unroll
        for (int k = 0; k < BK; k++) {
            float am[TM], av[TM], pm[TN], pv[TN];
#pragma unroll
            for (int i = 0; i < TM; i += 4)
                *reinterpret_cast<float4*>(&am[i]) =
                    *reinterpret_cast<const float4*>(&Asm[k][ty * TM + i]);
#pragma unroll
            for (int i = 0; i < TM; i += 4)
                *reinterpret_cast<float4*>(&av[i]) =
                    *reinterpret_cast<const float4*>(&Asv[k][ty * TM + i]);
#pragma unroll
            for (int j = 0; j < TN; j += 4)
                *reinterpret_cast<float4*>(&pm[j]) =
                    *reinterpret_cast<const float4*>(&Bms[k][tx * TN + j]);
#pragma unroll
            for (int j = 0; j < TN; j += 4)
                *reinterpret_cast<float4*>(&pv[j]) =
                    *reinterpret_cast<const float4*>(&Bvs[k][tx * TN + j]);
#pragma unroll
            for (int i = 0; i < TM; i++)
#pragma unroll
                for (int j = 0; j < TN; j++) {
                    accM[i][j] = fmaf(am[i], pm[j], accM[i][j]);
                    accV[i][j] = fmaf(av[i], pv[j], accV[i][j]);
                }
        }
        __syncthreads();
    }

#pragma unroll
    for (int i = 0; i < TM; i++) {
        int gm = bm_base + ty * TM + i;
        if (gm >= M) continue;
        float n1 = g_norm1[gm];
        float n2 = g_norm2[gm];
#pragma unroll
        for (int j = 0; j < TN; j += 4) {
            int gn = tx * TN + j;
            float4 om, ov;
            float* pm = &om.x;
            float* pv = &ov.x;
#pragma unroll
            for (int q = 0; q < 4; q++) {
                float mean = fmaxf(accM[i][j + q] + bm[gn + q], 0.f);
                float var  = fmaxf(accV[i][j + q] + bv[gn + q], 0.f);
                float att  = expf(-var);
                pm[q] = mean * att * n1;
                pv[q] = var * att * att * n2;
            }
            *reinterpret_cast<float4*>(Cm + (size_t)gm * BN + gn) = om;
            *reinterpret_cast<float4*>(Cv + (size_t)gm * BN + gn) = ov;
        }
    }
}

// ---------------- aggregation: warp per node, CSR pure-read reduce ----------------
__global__ void k_agg1(const float* __restrict__ msrc, const float* __restrict__ vsrc,
                       float* __restrict__ mdst, float* __restrict__ vdst, int n) {
    int warp = (blockIdx.x * blockDim.x + threadIdx.x) >> 5;
    int lane = threadIdx.x & 31;
    if (warp >= n) return;
    const int D = 128;
    int start = g_offs[warp], end = g_offs[warp + 1];

    float am[4] = {0.f, 0.f, 0.f, 0.f};
    float av[4] = {0.f, 0.f, 0.f, 0.f};
    for (int e = start; e < end; e++) {
        int s = g_csr[e];
        float4 a = __ldg(reinterpret_cast<const float4*>(msrc + (size_t)s * D + lane * 4));
        float4 b = __ldg(reinterpret_cast<const float4*>(vsrc + (size_t)s * D + lane * 4));
        am[0] += a.x; am[1] += a.y; am[2] += a.z; am[3] += a.w;
        av[0] += b.x; av[1] += b.y; av[2] += b.z; av[3] += b.w;
    }
    float n1 = g_norm1[warp], n2 = g_norm2[warp];
#pragma unroll
    for (int j = 0; j < 4; j++) {
        am[j] = fmaxf(am[j] * n1, 0.f);
        av[j] = fmaxf(av[j] * n2, 0.f);
    }
    *reinterpret_cast<float4*>(mdst + (size_t)warp * D + lane * 4) =
        make_float4(am[0], am[1], am[2], am[3]);
    *reinterpret_cast<float4*>(vdst + (size_t)warp * D + lane * 4) =
        make_float4(av[0], av[1], av[2], av[3]);
}

// ---------------- threefry-2x32-20 (KAT-verified) ----------------
__device__ __forceinline__ uint32_t rotl32(uint32_t x, int d) {
    return (x << d) | (x >> (32 - d));
}

__device__ __forceinline__ void threefry2x32(uint32_t k0, uint32_t k1,
                                             uint32_t& x0, uint32_t& x1) {
    uint32_t s0 = k0, s1 = k1, s2 = k0 ^ k1 ^ 0x1BD11BDAu;
    x0 += s0; x1 += s1;
#define TFR(r) { x0 += x1; x1 = rotl32(x1, r); x1 ^= x0; }
    TFR(13) TFR(15) TFR(26) TFR(6)   x0 += s1; x1 += s2 + 1u;
    TFR(17) TFR(29) TFR(16) TFR(24)  x0 += s2; x1 += s0 + 2u;
    TFR(13) TFR(15) TFR(26) TFR(6)   x0 += s0; x1 += s1 + 3u;
    TFR(17) TFR(29) TFR(16) TFR(24)  x0 += s1; x1 += s2 + 4u;
    TFR(13) TFR(15) TFR(26) TFR(6)   x0 += s2; x1 += s0 + 5u;
#undef TFR
}

__device__ __forceinline__ float jax_normal_elem(uint32_t idx) {
    uint32_t x0 = 0u, x1 = idx;
    threefry2x32(0u, 42u, x0, x1);
    uint32_t bits = x0 ^ x1;
    uint32_t fb = (bits >> 9) | 0x3F800000u;
    float u01 = __uint_as_float(fb) - 1.0f;
    const float lo = -0.99999994f;
    float u = fmaxf(u01 * 2.0f + lo, lo);
    return 1.41421356f * erfinvf(u);
}

// layer-2 aggregation fused with reparameterization: warp per node, VEC=2, D=64
__global__ void k_agg2_final(const float* __restrict__ msrc, const float* __restrict__ vsrc,
                             float* __restrict__ out, int n) {
    int warp = (blockIdx.x * blockDim.x + threadIdx.x) >> 5;
    int lane = threadIdx.x & 31;
    if (warp >= n) return;
    const int D = 64;
    int start = g_offs[warp], end = g_offs[warp + 1];

    float am0 = 0.f, am1 = 0.f, av0 = 0.f, av1 = 0.f;
    for (int e = start; e < end; e++) {
        int s = g_csr[e];
        float2 a = __ldg(reinterpret_cast<const float2*>(msrc + (size_t)s * D + lane * 2));
        float2 b = __ldg(reinterpret_cast<const float2*>(vsrc + (size_t)s * D + lane * 2));
        am0 += a.x; am1 += a.y;
        av0 += b.x; av1 += b.y;
    }
    float n1 = g_norm1[warp], n2 = g_norm2[warp];
    float m0 = am0 * n1, m1 = am1 * n1;
    float v0 = av0 * n2, v1 = av1 * n2;

    uint32_t t0 = (uint32_t)(warp * D + lane * 2);
    float e0 = jax_normal_elem(t0);
    float e1 = jax_normal_elem(t0 + 1u);
    float2 o;
    o.x = e0 * sqrtf(v0 + 1e-8f) + m0;
    o.y = e1 * sqrtf(v1 + 1e-8f) + m1;
    *reinterpret_cast<float2*>(out + (size_t)warp * D + lane * 2) = o;
}

// ---------------- launch ----------------
extern "C" void kernel_launch(void* const* d_in, const int* in_sizes, int n_in,
                              void* d_out, int out_size) {
    const float* x       = (const float*)d_in[0];
    const int*   src     = (const int*)d_in[1];
    const int*   dst     = (const int*)d_in[2];
    const float* w_mean1 = (const float*)d_in[3];
    const float* w_var1  = (const float*)d_in[4];
    const float* b_mean1 = (const float*)d_in[5];
    const float* b_var1  = (const float*)d_in[6];
    const float* w_mean2 = (const float*)d_in[7];
    const float* w_var2  = (const float*)d_in[8];
    const float* b_mean2 = (const float*)d_in[9];
    const float* b_var2  = (const float*)d_in[10];
    float* out = (float*)d_out;

    const int N = in_sizes[0] / IN_F;   // 100000
    const int E = in_sizes[1];          // 1600000

    float* bufA = nullptr; float* bufB = nullptr;
    float* aggM = nullptr; float* aggV = nullptr;
    cudaGetSymbolAddress((void**)&bufA, g_bufA);
    cudaGetSymbolAddress((void**)&bufB, g_bufB);
    cudaGetSymbolAddress((void**)&aggM, g_aggM);
    cudaGetSymbolAddress((void**)&aggV, g_aggV);

    const int T = 256;
    const int NB = (N + 1023) / 1024;

    // degrees, norms, CSR
    k_zero<<<(N + T - 1) / T, T>>>(N);
    k_count<<<(E + T - 1) / T, T>>>(dst, E);
    k_norm<<<(N + T - 1) / T, T>>>(N);
    k_scan1<<<NB, 1024>>>(N);
    k_scan2<<<1, 128>>>(NB, N);
    k_scan3<<<NB, 1024>>>(N);
    k_fill<<<(E + T - 1) / T, T>>>(src, dst, E);

    // ---- layer 1: tensor-core (3xTF32) dual GEMM + msg epilogue ----
    {
        dim3 grid((N + 127) / 128, 2);
        k_l1_tf32<<<grid, 256>>>(x, w_mean1, w_var1, b_mean1, b_var1, bufA, bufB, N);
    }
    {
        int blocks = (N * 32 + T - 1) / T;   // warp per node
        k_agg1<<<blocks, T>>>(bufA, bufB, aggM, aggV, N);
    }

    // ---- layer 2: FFMA dual GEMM (separate A) + msg epilogue ----
    {
        int blocks = (N + 127) / 128;
        k_gemm2<128, 64, 8, 8, 8, HID><<<blocks, 128>>>(
            aggM, aggV, w_mean2, w_var2, b_mean2, b_var2, bufA, bufB, N);
    }
    // ---- layer-2 aggregation fused with threefry reparameterization ----
    {
        int blocks = (N * 32 + T - 1) / T;
        k_agg2_final<<<blocks, T>>>(bufA, bufB, out, N);
    }
}

// round 6
// speedup vs baseline: 1.5510x; 1.0519x over previous
#include <cuda_runtime.h>
#include <stdint.h>
#include <math.h>

#define NODES_MAX 100000
#define M_PAD     100096   // 782 * 128
#define EDGES_MAX 1600000
#define IN_F 256
#define HID 128
#define OUTF 64

// ---------------- scratch (static __device__, no allocs) ----------------
__device__ float g_bufA[(size_t)M_PAD * HID];   // messages m
__device__ float g_bufB[(size_t)M_PAD * HID];   // messages v
__device__ float g_aggM[(size_t)M_PAD * HID];   // aggregated mean
__device__ float g_aggV[(size_t)M_PAD * HID];
__device__ float g_norm1[M_PAD];
__device__ float g_norm2[M_PAD];
__device__ int   g_deg[NODES_MAX];
__device__ int   g_cursor[NODES_MAX];
__device__ int   g_offs[NODES_MAX + 1];
__device__ int   g_csr[EDGES_MAX];
__device__ int   g_bsum[128];
__device__ int   g_boff[128];

// ---------------- degree / norms ----------------
__global__ void k_zero(int n) {
    int i = blockIdx.x * blockDim.x + threadIdx.x;
    if (i < n) { g_deg[i] = 0; g_cursor[i] = 0; }
}

__global__ void k_count(const int* __restrict__ dst, int E) {
    int e = blockIdx.x * blockDim.x + threadIdx.x;
    if (e < E) atomicAdd(&g_deg[dst[e]], 1);
}

__global__ void k_norm(int n) {
    int i = blockIdx.x * blockDim.x + threadIdx.x;
    if (i < n) {
        float d = fmaxf((float)g_deg[i], 1.0f);
        float n1 = 1.0f / sqrtf(d);
        g_norm1[i] = n1;
        g_norm2[i] = n1 * n1;
    }
}

// ---------------- parallel 3-phase exclusive scan ----------------
__global__ void k_scan1(int n) {
    __shared__ int sm[1024];
    int t = threadIdx.x;
    int i = blockIdx.x * 1024 + t;
    int v = (i < n) ? g_deg[i] : 0;
    sm[t] = v;
    __syncthreads();
#pragma unroll
    for (int d = 1; d < 1024; d <<= 1) {
        int u = (t >= d) ? sm[t - d] : 0;
        __syncthreads();
        sm[t] += u;
        __syncthreads();
    }
    if (i < n) g_offs[i] = sm[t] - v;
    if (t == 1023) g_bsum[blockIdx.x] = sm[1023];
}

__global__ void k_scan2(int nb, int n) {
    __shared__ int sm[128];
    int t = threadIdx.x;
    int v = (t < nb) ? g_bsum[t] : 0;
    sm[t] = v;
    __syncthreads();
#pragma unroll
    for (int d = 1; d < 128; d <<= 1) {
        int u = (t >= d) ? sm[t - d] : 0;
        __syncthreads();
        sm[t] += u;
        __syncthreads();
    }
    if (t < nb) g_boff[t] = sm[t] - v;
    if (t == 127) g_offs[n] = sm[127];
}

__global__ void k_scan3(int n) {
    int i = blockIdx.x * 1024 + threadIdx.x;
    if (i < n) g_offs[i] += g_boff[blockIdx.x];
}

__global__ void k_fill(const int* __restrict__ src, const int* __restrict__ dst, int E) {
    int e = blockIdx.x * blockDim.x + threadIdx.x;
    if (e < E) {
        int d = dst[e];
        int p = atomicAdd(&g_cursor[d], 1);
        g_csr[g_offs[d] + p] = src[e];
    }
}

// ================= tensor-core helpers (3xTF32) =================
__device__ __forceinline__ uint32_t cvt_tf32(float x) {
    uint32_t r;
    asm("cvt.rna.tf32.f32 %0, %1;" : "=r"(r) : "f"(x));
    return r;
}

__device__ __forceinline__ void mma_tf32(float* d, uint32_t a0, uint32_t a1,
                                         uint32_t a2, uint32_t a3,
                                         uint32_t b0, uint32_t b1) {
    asm volatile(
        "mma.sync.aligned.m16n8k8.row.col.f32.tf32.tf32.f32 "
        "{%0,%1,%2,%3},{%4,%5,%6,%7},{%8,%9},{%0,%1,%2,%3};"
        : "+f"(d[0]), "+f"(d[1]), "+f"(d[2]), "+f"(d[3])
        : "r"(a0), "r"(a1), "r"(a2), "r"(a3), "r"(b0), "r"(b1));
}

__device__ __forceinline__ void cp16(uint32_t dst, const void* src, int sz) {
    asm volatile("cp.async.cg.shared.global [%0], [%1], 16, %2;"
                 :: "r"(dst), "l"(src), "r"(sz));
}
__device__ __forceinline__ void cp_commit() {
    asm volatile("cp.async.commit_group;");
}
template <int N> __device__ __forceinline__ void cp_wait() {
    asm volatile("cp.async.wait_group %0;" :: "n"(N));
}

#define L1_APAD 20    // floats per A smem row (16 + 4)
#define L1_BPAD 136   // floats per B smem row (128 + 8)

// ================= layer-1: shared-A dual GEMM, 3xTF32 =================
__global__ void __launch_bounds__(256)
k_l1_tf32(const float* __restrict__ X,
          const float* __restrict__ Wm, const float* __restrict__ Wv,   // [256][128]
          const float* __restrict__ bm, const float* __restrict__ bv,
          float* __restrict__ Cm, float* __restrict__ Cv, int M) {
    __shared__ float As[2][128 * L1_APAD];
    __shared__ float Bs[2][16 * L1_BPAD];

    const int tid = threadIdx.x;
    const int lane = tid & 31;
    const int wid = tid >> 5;
    const int warp_m = wid & 3;
    const int warp_n = wid >> 2;
    const int gid = lane >> 2;
    const int tig = lane & 3;
    const int bm_base = blockIdx.x * 128;
    const int col_half = blockIdx.y * 64;

    float acc[2][2][4][4];
#pragma unroll
    for (int a = 0; a < 2; a++)
#pragma unroll
        for (int b = 0; b < 2; b++)
#pragma unroll
            for (int c = 0; c < 4; c++)
#pragma unroll
                for (int d = 0; d < 4; d++) acc[a][b][c][d] = 0.f;

    uint32_t asbase[2], bsbase[2];
    asbase[0] = (uint32_t)__cvta_generic_to_shared(&As[0][0]);
    asbase[1] = (uint32_t)__cvta_generic_to_shared(&As[1][0]);
    bsbase[0] = (uint32_t)__cvta_generic_to_shared(&Bs[0][0]);
    bsbase[1] = (uint32_t)__cvta_generic_to_shared(&Bs[1][0]);

    auto issue = [&](int stage, int k0) {
#pragma unroll
        for (int c = tid; c < 512; c += 256) {
            int r = c >> 2, kq = c & 3;
            int gm = bm_base + r;
            int ok = (gm < M) ? 16 : 0;
            const float* src = X + (size_t)min(gm, M - 1) * IN_F + k0 + kq * 4;
            cp16(asbase[stage] + (uint32_t)(r * L1_APAD + kq * 4) * 4, src, ok);
        }
#pragma unroll
        for (int c = tid; c < 512; c += 256) {
            int r = c >> 5, cc = c & 31;
            int mat = cc >> 4, q = cc & 15;
            const float* srcb = (mat ? Wv : Wm) + (size_t)(k0 + r) * HID + col_half + q * 4;
            cp16(bsbase[stage] + (uint32_t)(r * L1_BPAD + mat * 64 + q * 4) * 4, srcb, 16);
        }
        cp_commit();
    };

    issue(0, 0);

    const int NITER = IN_F / 16;
    for (int it = 0; it < NITER; it++) {
        int stage = it & 1;
        if (it + 1 < NITER) {
            issue(stage ^ 1, (it + 1) * 16);
            cp_wait<1>();
        } else {
            cp_wait<0>();
        }
        __syncthreads();

        const float* as = As[stage];
        const float* bs = Bs[stage];

#pragma unroll
        for (int ks = 0; ks < 2; ks++) {
            const int k8 = ks * 8;
            uint32_t ahi[8], alo[8];
#pragma unroll
            for (int mt = 0; mt < 2; mt++) {
                int rb = warp_m * 32 + mt * 16;
                float a0 = as[(rb + gid) * L1_APAD + k8 + tig];
                float a1 = as[(rb + gid + 8) * L1_APAD + k8 + tig];
                float a2 = as[(rb + gid) * L1_APAD + k8 + tig + 4];
                float a3 = as[(rb + gid + 8) * L1_APAD + k8 + tig + 4];
                ahi[mt * 4 + 0] = cvt_tf32(a0);
                ahi[mt * 4 + 1] = cvt_tf32(a1);
                ahi[mt * 4 + 2] = cvt_tf32(a2);
                ahi[mt * 4 + 3] = cvt_tf32(a3);
                alo[mt * 4 + 0] = cvt_tf32(a0 - __uint_as_float(ahi[mt * 4 + 0]));
                alo[mt * 4 + 1] = cvt_tf32(a1 - __uint_as_float(ahi[mt * 4 + 1]));
                alo[mt * 4 + 2] = cvt_tf32(a2 - __uint_as_float(ahi[mt * 4 + 2]));
                alo[mt * 4 + 3] = cvt_tf32(a3 - __uint_as_float(ahi[mt * 4 + 3]));
            }
#pragma unroll
            for (int mat = 0; mat < 2; mat++) {
                uint32_t bhi[8], blo[8];
#pragma unroll
                for (int nt = 0; nt < 4; nt++) {
                    int col = mat * 64 + warp_n * 32 + nt * 8 + gid;
                    float b0 = bs[(k8 + tig) * L1_BPAD + col];
                    float b1 = bs[(k8 + tig + 4) * L1_BPAD + col];
                    bhi[nt * 2 + 0] = cvt_tf32(b0);
                    bhi[nt * 2 + 1] = cvt_tf32(b1);
                    blo[nt * 2 + 0] = cvt_tf32(b0 - __uint_as_float(bhi[nt * 2 + 0]));
                    blo[nt * 2 + 1] = cvt_tf32(b1 - __uint_as_float(bhi[nt * 2 + 1]));
                }
#pragma unroll
                for (int mt = 0; mt < 2; mt++)
#pragma unroll
                    for (int nt = 0; nt < 4; nt++) {
                        float* d = acc[mat][mt][nt];
                        mma_tf32(d, ahi[mt*4], ahi[mt*4+1], ahi[mt*4+2], ahi[mt*4+3],
                                 bhi[nt*2], bhi[nt*2+1]);
                        mma_tf32(d, ahi[mt*4], ahi[mt*4+1], ahi[mt*4+2], ahi[mt*4+3],
                                 blo[nt*2], blo[nt*2+1]);
                        mma_tf32(d, alo[mt*4], alo[mt*4+1], alo[mt*4+2], alo[mt*4+3],
                                 bhi[nt*2], bhi[nt*2+1]);
                    }
            }
        }
        __syncthreads();
    }

#pragma unroll
    for (int nt = 0; nt < 4; nt++) {
        int cl = warp_n * 32 + nt * 8 + tig * 2;
        int gc = col_half + cl;
        float bm0 = bm[gc], bm1 = bm[gc + 1];
        float bv0 = bv[gc], bv1 = bv[gc + 1];
#pragma unroll
        for (int mt = 0; mt < 2; mt++) {
#pragma unroll
            for (int half = 0; half < 2; half++) {
                int gm = bm_base + warp_m * 32 + mt * 16 + gid + half * 8;
                float n1 = g_norm1[gm];
                float n2 = g_norm2[gm];
                float mean0 = fmaxf(acc[0][mt][nt][half * 2 + 0] + bm0, 0.f);
                float mean1 = fmaxf(acc[0][mt][nt][half * 2 + 1] + bm1, 0.f);
                float var0  = fmaxf(acc[1][mt][nt][half * 2 + 0] + bv0, 0.f);
                float var1  = fmaxf(acc[1][mt][nt][half * 2 + 1] + bv1, 0.f);
                float att0 = expf(-var0), att1 = expf(-var1);
                float2 om = make_float2(mean0 * att0 * n1, mean1 * att1 * n1);
                float2 ov = make_float2(var0 * att0 * att0 * n2, var1 * att1 * att1 * n2);
                *reinterpret_cast<float2*>(Cm + (size_t)gm * HID + gc) = om;
                *reinterpret_cast<float2*>(Cv + (size_t)gm * HID + gc) = ov;
            }
        }
    }
}

// ================= layer-2: dual-A dual GEMM, 3xTF32, K=128, N=64 =================
// One CTA = 128 rows x 64 cols, both matrices. All rows < M_PAD (no guards).
__global__ void __launch_bounds__(256)
k_l2_tf32(const float* __restrict__ Am, const float* __restrict__ Av,   // [M_PAD][128]
          const float* __restrict__ Wm, const float* __restrict__ Wv,   // [128][64]
          const float* __restrict__ bm, const float* __restrict__ bv,
          float* __restrict__ Cm, float* __restrict__ Cv) {
    __shared__ float As[2][2][128 * L1_APAD];   // [stage][matrix]
    __shared__ float Bs[2][16 * L1_BPAD];       // both matrices side by side

    const int tid = threadIdx.x;
    const int lane = tid & 31;
    const int wid = tid >> 5;
    const int warp_m = wid & 3;
    const int warp_n = wid >> 2;
    const int gid = lane >> 2;
    const int tig = lane & 3;
    const int bm_base = blockIdx.x * 128;

    float acc[2][2][4][4];
#pragma unroll
    for (int a = 0; a < 2; a++)
#pragma unroll
        for (int b = 0; b < 2; b++)
#pragma unroll
            for (int c = 0; c < 4; c++)
#pragma unroll
                for (int d = 0; d < 4; d++) acc[a][b][c][d] = 0.f;

    uint32_t asbase[2][2], bsbase[2];
#pragma unroll
    for (int s = 0; s < 2; s++) {
        asbase[s][0] = (uint32_t)__cvta_generic_to_shared(&As[s][0][0]);
        asbase[s][1] = (uint32_t)__cvta_generic_to_shared(&As[s][1][0]);
        bsbase[s]    = (uint32_t)__cvta_generic_to_shared(&Bs[s][0]);
    }

    auto issue = [&](int stage, int k0) {
        // A tiles: 2 matrices x 128 rows x 16 k = 1024 16B-chunks
#pragma unroll
        for (int c = tid; c < 1024; c += 256) {
            int mat = c >> 9;
            int r = (c >> 2) & 127;
            int kq = c & 3;
            const float* src = (mat ? Av : Am) + (size_t)(bm_base + r) * HID + k0 + kq * 4;
            cp16(asbase[stage][mat] + (uint32_t)(r * L1_APAD + kq * 4) * 4, src, 16);
        }
        // B tiles: 16 k-rows x (64 | 64) cols = 512 chunks
#pragma unroll
        for (int c = tid; c < 512; c += 256) {
            int r = c >> 5, cc = c & 31;
            int mat = cc >> 4, q = cc & 15;
            const float* srcb = (mat ? Wv : Wm) + (size_t)(k0 + r) * OUTF + q * 4;
            cp16(bsbase[stage] + (uint32_t)(r * L1_BPAD + mat * 64 + q * 4) * 4, srcb, 16);
        }
        cp_commit();
    };

    issue(0, 0);

    const int NITER = HID / 16;   // 8
    for (int it = 0; it < NITER; it++) {
        int stage = it & 1;
        if (it + 1 < NITER) {
            issue(stage ^ 1, (it + 1) * 16);
            cp_wait<1>();
        } else {
            cp_wait<0>();
        }
        __syncthreads();

        const float* bs = Bs[stage];

#pragma unroll
        for (int ks = 0; ks < 2; ks++) {
            const int k8 = ks * 8;
#pragma unroll
            for (int mat = 0; mat < 2; mat++) {
                const float* as = As[stage][mat];
                uint32_t ahi[8], alo[8];
#pragma unroll
                for (int mt = 0; mt < 2; mt++) {
                    int rb = warp_m * 32 + mt * 16;
                    float a0 = as[(rb + gid) * L1_APAD + k8 + tig];
                    float a1 = as[(rb + gid + 8) * L1_APAD + k8 + tig];
                    float a2 = as[(rb + gid) * L1_APAD + k8 + tig + 4];
                    float a3 = as[(rb + gid + 8) * L1_APAD + k8 + tig + 4];
                    ahi[mt * 4 + 0] = cvt_tf32(a0);
                    ahi[mt * 4 + 1] = cvt_tf32(a1);
                    ahi[mt * 4 + 2] = cvt_tf32(a2);
                    ahi[mt * 4 + 3] = cvt_tf32(a3);
                    alo[mt * 4 + 0] = cvt_tf32(a0 - __uint_as_float(ahi[mt * 4 + 0]));
                    alo[mt * 4 + 1] = cvt_tf32(a1 - __uint_as_float(ahi[mt * 4 + 1]));
                    alo[mt * 4 + 2] = cvt_tf32(a2 - __uint_as_float(ahi[mt * 4 + 2]));
                    alo[mt * 4 + 3] = cvt_tf32(a3 - __uint_as_float(ahi[mt * 4 + 3]));
                }
                uint32_t bhi[8], blo[8];
#pragma unroll
                for (int nt = 0; nt < 4; nt++) {
                    // warp_n bands cover 64 cols: warp_n*32 + nt*8
                    int col = mat * 64 + warp_n * 32 + nt * 8 + gid;
                    float b0 = bs[(k8 + tig) * L1_BPAD + col];
                    float b1 = bs[(k8 + tig + 4) * L1_BPAD + col];
                    bhi[nt * 2 + 0] = cvt_tf32(b0);
                    bhi[nt * 2 + 1] = cvt_tf32(b1);
                    blo[nt * 2 + 0] = cvt_tf32(b0 - __uint_as_float(bhi[nt * 2 + 0]));
                    blo[nt * 2 + 1] = cvt_tf32(b1 - __uint_as_float(bhi[nt * 2 + 1]));
                }
#pragma unroll
                for (int mt = 0; mt < 2; mt++)
#pragma unroll
                    for (int nt = 0; nt < 4; nt++) {
                        float* d = acc[mat][mt][nt];
                        mma_tf32(d, ahi[mt*4], ahi[mt*4+1], ahi[mt*4+2], ahi[mt*4+3],
                                 bhi[nt*2], bhi[nt*2+1]);
                        mma_tf32(d, ahi[mt*4], ahi[mt*4+1], ahi[mt*4+2], ahi[mt*4+3],
                                 blo[nt*2], blo[nt*2+1]);
                        mma_tf32(d, alo[mt*4], alo[mt*4+1], alo[mt*4+2], alo[mt*4+3],
                                 bhi[nt*2], bhi[nt*2+1]);
                    }
            }
        }
        __syncthreads();
    }

    // ---- epilogue: bias + relu + att + norms -> messages [M_PAD][64] ----
#pragma unroll
    for (int nt = 0; nt < 4; nt++) {
        int gc = warp_n * 32 + nt * 8 + tig * 2;
        float bm0 = bm[gc], bm1 = bm[gc + 1];
        float bv0 = bv[gc], bv1 = bv[gc + 1];
#pragma unroll
        for (int mt = 0; mt < 2; mt++) {
#pragma unroll
            for (int half = 0; half < 2; half++) {
                int gm = bm_base + warp_m * 32 + mt * 16 + gid + half * 8;
                float n1 = g_norm1[gm];
                float n2 = g_norm2[gm];
                float mean0 = fmaxf(acc[0][mt][nt][half * 2 + 0] + bm0, 0.f);
                float mean1 = fmaxf(acc[0][mt][nt][half * 2 + 1] + bm1, 0.f);
                float var0  = fmaxf(acc[1][mt][nt][half * 2 + 0] + bv0, 0.f);
                float var1  = fmaxf(acc[1][mt][nt][half * 2 + 1] + bv1, 0.f);
                float att0 = expf(-var0), att1 = expf(-var1);
                float2 om = make_float2(mean0 * att0 * n1, mean1 * att1 * n1);
                float2 ov = make_float2(var0 * att0 * att0 * n2, var1 * att1 * att1 * n2);
                *reinterpret_cast<float2*>(Cm + (size_t)gm * OUTF + gc) = om;
                *reinterpret_cast<float2*>(Cv + (size_t)gm * OUTF + gc) = ov;
            }
        }
    }
}

// ---------------- aggregation: warp per node, CSR pure-read reduce ----------------
__global__ void k_agg1(const float* __restrict__ msrc, const float* __restrict__ vsrc,
                       float* __restrict__ mdst, float* __restrict__ vdst, int n) {
    int warp = (blockIdx.x * blockDim.x + threadIdx.x) >> 5;
    int lane = threadIdx.x & 31;
    if (warp >= n) return;
    const int D = 128;
    int start = g_offs[warp], end = g_offs[warp + 1];

    float am[4] = {0.f, 0.f, 0.f, 0.f};
    float av[4] = {0.f, 0.f, 0.f, 0.f};
    for (int e = start; e < end; e++) {
        int s = g_csr[e];
        float4 a = __ldg(reinterpret_cast<const float4*>(msrc + (size_t)s * D + lane * 4));
        float4 b = __ldg(reinterpret_cast<const float4*>(vsrc + (size_t)s * D + lane * 4));
        am[0] += a.x; am[1] += a.y; am[2] += a.z; am[3] += a.w;
        av[0] += b.x; av[1] += b.y; av[2] += b.z; av[3] += b.w;
    }
    float n1 = g_norm1[warp], n2 = g_norm2[warp];
#pragma unroll
    for (int j = 0; j < 4; j++) {
        am[j] = fmaxf(am[j] * n1, 0.f);
        av[j] = fmaxf(av[j] * n2, 0.f);
    }
    *reinterpret_cast<float4*>(mdst + (size_t)warp * D + lane * 4) =
        make_float4(am[0], am[1], am[2], am[3]);
    *reinterpret_cast<float4*>(vdst + (size_t)warp * D + lane * 4) =
        make_float4(av[0], av[1], av[2], av[3]);
}

// ---------------- threefry-2x32-20 (KAT-verified) ----------------
__device__ __forceinline__ uint32_t rotl32(uint32_t x, int d) {
    return (x << d) | (x >> (32 - d));
}

__device__ __forceinline__ void threefry2x32(uint32_t k0, uint32_t k1,
                                             uint32_t& x0, uint32_t& x1) {
    uint32_t s0 = k0, s1 = k1, s2 = k0 ^ k1 ^ 0x1BD11BDAu;
    x0 += s0; x1 += s1;
#define TFR(r) { x0 += x1; x1 = rotl32(x1, r); x1 ^= x0; }
    TFR(13) TFR(15) TFR(26) TFR(6)   x0 += s1; x1 += s2 + 1u;
    TFR(17) TFR(29) TFR(16) TFR(24)  x0 += s2; x1 += s0 + 2u;
    TFR(13) TFR(15) TFR(26) TFR(6)   x0 += s0; x1 += s1 + 3u;
    TFR(17) TFR(29) TFR(16) TFR(24)  x0 += s1; x1 += s2 + 4u;
    TFR(13) TFR(15) TFR(26) TFR(6)   x0 += s2; x1 += s0 + 5u;
#undef TFR
}

__device__ __forceinline__ float jax_normal_elem(uint32_t idx) {
    uint32_t x0 = 0u, x1 = idx;
    threefry2x32(0u, 42u, x0, x1);
    uint32_t bits = x0 ^ x1;
    uint32_t fb = (bits >> 9) | 0x3F800000u;
    float u01 = __uint_as_float(fb) - 1.0f;
    const float lo = -0.99999994f;
    float u = fmaxf(u01 * 2.0f + lo, lo);
    return 1.41421356f * erfinvf(u);
}

// layer-2 aggregation fused with reparameterization: warp per node, VEC=2, D=64
__global__ void k_agg2_final(const float* __restrict__ msrc, const float* __restrict__ vsrc,
                             float* __restrict__ out, int n) {
    int warp = (blockIdx.x * blockDim.x + threadIdx.x) >> 5;
    int lane = threadIdx.x & 31;
    if (warp >= n) return;
    const int D = 64;
    int start = g_offs[warp], end = g_offs[warp + 1];

    float am0 = 0.f, am1 = 0.f, av0 = 0.f, av1 = 0.f;
    for (int e = start; e < end; e++) {
        int s = g_csr[e];
        float2 a = __ldg(reinterpret_cast<const float2*>(msrc + (size_t)s * D + lane * 2));
        float2 b = __ldg(reinterpret_cast<const float2*>(vsrc + (size_t)s * D + lane * 2));
        am0 += a.x; am1 += a.y;
        av0 += b.x; av1 += b.y;
    }
    float n1 = g_norm1[warp], n2 = g_norm2[warp];
    float m0 = am0 * n1, m1 = am1 * n1;
    float v0 = av0 * n2, v1 = av1 * n2;

    uint32_t t0 = (uint32_t)(warp * D + lane * 2);
    float e0 = jax_normal_elem(t0);
    float e1 = jax_normal_elem(t0 + 1u);
    float2 o;
    o.x = e0 * sqrtf(v0 + 1e-8f) + m0;
    o.y = e1 * sqrtf(v1 + 1e-8f) + m1;
    *reinterpret_cast<float2*>(out + (size_t)warp * D + lane * 2) = o;
}

// ---------------- launch ----------------
extern "C" void kernel_launch(void* const* d_in, const int* in_sizes, int n_in,
                              void* d_out, int out_size) {
    const float* x       = (const float*)d_in[0];
    const int*   src     = (const int*)d_in[1];
    const int*   dst     = (const int*)d_in[2];
    const float* w_mean1 = (const float*)d_in[3];
    const float* w_var1  = (const float*)d_in[4];
    const float* b_mean1 = (const float*)d_in[5];
    const float* b_var1  = (const float*)d_in[6];
    const float* w_mean2 = (const float*)d_in[7];
    const float* w_var2  = (const float*)d_in[8];
    const float* b_mean2 = (const float*)d_in[9];
    const float* b_var2  = (const float*)d_in[10];
    float* out = (float*)d_out;

    const int N = in_sizes[0] / IN_F;   // 100000
    const int E = in_sizes[1];          // 1600000

    float* bufA = nullptr; float* bufB = nullptr;
    float* aggM = nullptr; float* aggV = nullptr;
    cudaGetSymbolAddress((void**)&bufA, g_bufA);
    cudaGetSymbolAddress((void**)&bufB, g_bufB);
    cudaGetSymbolAddress((void**)&aggM, g_aggM);
    cudaGetSymbolAddress((void**)&aggV, g_aggV);

    const int T = 256;
    const int NB = (N + 1023) / 1024;

    // degrees, norms, CSR
    k_zero<<<(N + T - 1) / T, T>>>(N);
    k_count<<<(E + T - 1) / T, T>>>(dst, E);
    k_norm<<<(N + T - 1) / T, T>>>(N);
    k_scan1<<<NB, 1024>>>(N);
    k_scan2<<<1, 128>>>(NB, N);
    k_scan3<<<NB, 1024>>>(N);
    k_fill<<<(E + T - 1) / T, T>>>(src, dst, E);

    // ---- layer 1: tensor-core (3xTF32) dual GEMM + msg epilogue ----
    {
        dim3 grid((N + 127) / 128, 2);
        k_l1_tf32<<<grid, 256>>>(x, w_mean1, w_var1, b_mean1, b_var1, bufA, bufB, N);
    }
    {
        int blocks = (N * 32 + T - 1) / T;   // warp per node
        k_agg1<<<blocks, T>>>(bufA, bufB, aggM, aggV, N);
    }

    // ---- layer 2: tensor-core (3xTF32) dual-A GEMM + msg epilogue ----
    {
        int blocks = (N + 127) / 128;   // 782, covers M_PAD exactly
        k_l2_tf32<<<blocks, 256>>>(aggM, aggV, w_mean2, w_var2,
                                   b_mean2, b_var2, bufA, bufB);
    }
    // ---- layer-2 aggregation fused with threefry reparameterization ----
    {
        int blocks = (N * 32 + T - 1) / T;
        k_agg2_final<<<blocks, T>>>(bufA, bufB, out, N);
    }
}

// round 7
// speedup vs baseline: 1.7547x; 1.1313x over previous
#include <cuda_runtime.h>
#include <cuda_fp16.h>
#include <stdint.h>
#include <math.h>

#define NODES_MAX 100000
#define M_PAD     100096   // 782 * 128
#define EDGES_MAX 1600000
#define IN_F 256
#define HID 128
#define OUTF 64

// ---------------- scratch (static __device__, no allocs) ----------------
__device__ __half g_bufA[(size_t)M_PAD * HID];   // messages m (fp16)
__device__ __half g_bufB[(size_t)M_PAD * HID];   // messages v (fp16)
__device__ float  g_aggM[(size_t)M_PAD * HID];   // aggregated mean (fp32)
__device__ float  g_aggV[(size_t)M_PAD * HID];
__device__ float  g_norm1[M_PAD];
__device__ float  g_norm2[M_PAD];
__device__ int    g_deg[NODES_MAX];
__device__ int    g_cursor[NODES_MAX];
__device__ int    g_offs[NODES_MAX + 1];
__device__ int    g_csr[EDGES_MAX];
__device__ int    g_bsum[128];
__device__ int    g_boff[128];

// ---------------- degree / norms ----------------
__global__ void k_zero(int n) {
    int i = blockIdx.x * blockDim.x + threadIdx.x;
    if (i < n) { g_deg[i] = 0; g_cursor[i] = 0; }
}

__global__ void k_count(const int* __restrict__ dst, int E) {
    int e = blockIdx.x * blockDim.x + threadIdx.x;
    if (e < E) atomicAdd(&g_deg[dst[e]], 1);
}

__global__ void k_norm(int n) {
    int i = blockIdx.x * blockDim.x + threadIdx.x;
    if (i < n) {
        float d = fmaxf((float)g_deg[i], 1.0f);
        float n1 = 1.0f / sqrtf(d);
        g_norm1[i] = n1;
        g_norm2[i] = n1 * n1;
    }
}

// ---------------- parallel 3-phase exclusive scan ----------------
__global__ void k_scan1(int n) {
    __shared__ int sm[1024];
    int t = threadIdx.x;
    int i = blockIdx.x * 1024 + t;
    int v = (i < n) ? g_deg[i] : 0;
    sm[t] = v;
    __syncthreads();
#pragma unroll
    for (int d = 1; d < 1024; d <<= 1) {
        int u = (t >= d) ? sm[t - d] : 0;
        __syncthreads();
        sm[t] += u;
        __syncthreads();
    }
    if (i < n) g_offs[i] = sm[t] - v;
    if (t == 1023) g_bsum[blockIdx.x] = sm[1023];
}

__global__ void k_scan2(int nb, int n) {
    __shared__ int sm[128];
    int t = threadIdx.x;
    int v = (t < nb) ? g_bsum[t] : 0;
    sm[t] = v;
    __syncthreads();
#pragma unroll
    for (int d = 1; d < 128; d <<= 1) {
        int u = (t >= d) ? sm[t - d] : 0;
        __syncthreads();
        sm[t] += u;
        __syncthreads();
    }
    if (t < nb) g_boff[t] = sm[t] - v;
    if (t == 127) g_offs[n] = sm[127];
}

__global__ void k_scan3(int n) {
    int i = blockIdx.x * 1024 + threadIdx.x;
    if (i < n) g_offs[i] += g_boff[blockIdx.x];
}

__global__ void k_fill(const int* __restrict__ src, const int* __restrict__ dst, int E) {
    int e = blockIdx.x * blockDim.x + threadIdx.x;
    if (e < E) {
        int d = dst[e];
        int p = atomicAdd(&g_cursor[d], 1);
        g_csr[g_offs[d] + p] = src[e];
    }
}

// ================= tensor-core helpers (3xTF32) =================
__device__ __forceinline__ uint32_t cvt_tf32(float x) {
    uint32_t r;
    asm("cvt.rna.tf32.f32 %0, %1;" : "=r"(r) : "f"(x));
    return r;
}

__device__ __forceinline__ void mma_tf32(float* d, uint32_t a0, uint32_t a1,
                                         uint32_t a2, uint32_t a3,
                                         uint32_t b0, uint32_t b1) {
    asm volatile(
        "mma.sync.aligned.m16n8k8.row.col.f32.tf32.tf32.f32 "
        "{%0,%1,%2,%3},{%4,%5,%6,%7},{%8,%9},{%0,%1,%2,%3};"
        : "+f"(d[0]), "+f"(d[1]), "+f"(d[2]), "+f"(d[3])
        : "r"(a0), "r"(a1), "r"(a2), "r"(a3), "r"(b0), "r"(b1));
}

__device__ __forceinline__ void cp16(uint32_t dst, const void* src, int sz) {
    asm volatile("cp.async.cg.shared.global [%0], [%1], 16, %2;"
                 :: "r"(dst), "l"(src), "r"(sz));
}
__device__ __forceinline__ void cp_commit() {
    asm volatile("cp.async.commit_group;");
}
template <int N> __device__ __forceinline__ void cp_wait() {
    asm volatile("cp.async.wait_group %0;" :: "n"(N));
}

#define L1_APAD 20    // floats per A smem row (16 + 4)
#define L1_BPAD 136   // floats per B smem row (128 + 8)

// ================= layer-1: shared-A dual GEMM, 3xTF32, fp16 message out =================
__global__ void __launch_bounds__(256)
k_l1_tf32(const float* __restrict__ X,
          const float* __restrict__ Wm, const float* __restrict__ Wv,   // [256][128]
          const float* __restrict__ bm, const float* __restrict__ bv,
          __half* __restrict__ Cm, __half* __restrict__ Cv, int M) {
    __shared__ float As[2][128 * L1_APAD];
    __shared__ float Bs[2][16 * L1_BPAD];

    const int tid = threadIdx.x;
    const int lane = tid & 31;
    const int wid = tid >> 5;
    const int warp_m = wid & 3;
    const int warp_n = wid >> 2;
    const int gid = lane >> 2;
    const int tig = lane & 3;
    const int bm_base = blockIdx.x * 128;
    const int col_half = blockIdx.y * 64;

    float acc[2][2][4][4];
#pragma unroll
    for (int a = 0; a < 2; a++)
#pragma unroll
        for (int b = 0; b < 2; b++)
#pragma unroll
            for (int c = 0; c < 4; c++)
#pragma unroll
                for (int d = 0; d < 4; d++) acc[a][b][c][d] = 0.f;

    uint32_t asbase[2], bsbase[2];
    asbase[0] = (uint32_t)__cvta_generic_to_shared(&As[0][0]);
    asbase[1] = (uint32_t)__cvta_generic_to_shared(&As[1][0]);
    bsbase[0] = (uint32_t)__cvta_generic_to_shared(&Bs[0][0]);
    bsbase[1] = (uint32_t)__cvta_generic_to_shared(&Bs[1][0]);

    auto issue = [&](int stage, int k0) {
#pragma unroll
        for (int c = tid; c < 512; c += 256) {
            int r = c >> 2, kq = c & 3;
            int gm = bm_base + r;
            int ok = (gm < M) ? 16 : 0;
            const float* src = X + (size_t)min(gm, M - 1) * IN_F + k0 + kq * 4;
            cp16(asbase[stage] + (uint32_t)(r * L1_APAD + kq * 4) * 4, src, ok);
        }
#pragma unroll
        for (int c = tid; c < 512; c += 256) {
            int r = c >> 5, cc = c & 31;
            int mat = cc >> 4, q = cc & 15;
            const float* srcb = (mat ? Wv : Wm) + (size_t)(k0 + r) * HID + col_half + q * 4;
            cp16(bsbase[stage] + (uint32_t)(r * L1_BPAD + mat * 64 + q * 4) * 4, srcb, 16);
        }
        cp_commit();
    };

    issue(0, 0);

    const int NITER = IN_F / 16;
    for (int it = 0; it < NITER; it++) {
        int stage = it & 1;
        if (it + 1 < NITER) {
            issue(stage ^ 1, (it + 1) * 16);
            cp_wait<1>();
        } else {
            cp_wait<0>();
        }
        __syncthreads();

        const float* as = As[stage];
        const float* bs = Bs[stage];

#pragma unroll
        for (int ks = 0; ks < 2; ks++) {
            const int k8 = ks * 8;
            uint32_t ahi[8], alo[8];
#pragma unroll
            for (int mt = 0; mt < 2; mt++) {
                int rb = warp_m * 32 + mt * 16;
                float a0 = as[(rb + gid) * L1_APAD + k8 + tig];
                float a1 = as[(rb + gid + 8) * L1_APAD + k8 + tig];
                float a2 = as[(rb + gid) * L1_APAD + k8 + tig + 4];
                float a3 = as[(rb + gid + 8) * L1_APAD + k8 + tig + 4];
                ahi[mt * 4 + 0] = cvt_tf32(a0);
                ahi[mt * 4 + 1] = cvt_tf32(a1);
                ahi[mt * 4 + 2] = cvt_tf32(a2);
                ahi[mt * 4 + 3] = cvt_tf32(a3);
                alo[mt * 4 + 0] = cvt_tf32(a0 - __uint_as_float(ahi[mt * 4 + 0]));
                alo[mt * 4 + 1] = cvt_tf32(a1 - __uint_as_float(ahi[mt * 4 + 1]));
                alo[mt * 4 + 2] = cvt_tf32(a2 - __uint_as_float(ahi[mt * 4 + 2]));
                alo[mt * 4 + 3] = cvt_tf32(a3 - __uint_as_float(ahi[mt * 4 + 3]));
            }
#pragma unroll
            for (int mat = 0; mat < 2; mat++) {
                uint32_t bhi[8], blo[8];
#pragma unroll
                for (int nt = 0; nt < 4; nt++) {
                    int col = mat * 64 + warp_n * 32 + nt * 8 + gid;
                    float b0 = bs[(k8 + tig) * L1_BPAD + col];
                    float b1 = bs[(k8 + tig + 4) * L1_BPAD + col];
                    bhi[nt * 2 + 0] = cvt_tf32(b0);
                    bhi[nt * 2 + 1] = cvt_tf32(b1);
                    blo[nt * 2 + 0] = cvt_tf32(b0 - __uint_as_float(bhi[nt * 2 + 0]));
                    blo[nt * 2 + 1] = cvt_tf32(b1 - __uint_as_float(bhi[nt * 2 + 1]));
                }
#pragma unroll
                for (int mt = 0; mt < 2; mt++)
#pragma unroll
                    for (int nt = 0; nt < 4; nt++) {
                        float* d = acc[mat][mt][nt];
                        mma_tf32(d, ahi[mt*4], ahi[mt*4+1], ahi[mt*4+2], ahi[mt*4+3],
                                 bhi[nt*2], bhi[nt*2+1]);
                        mma_tf32(d, ahi[mt*4], ahi[mt*4+1], ahi[mt*4+2], ahi[mt*4+3],
                                 blo[nt*2], blo[nt*2+1]);
                        mma_tf32(d, alo[mt*4], alo[mt*4+1], alo[mt*4+2], alo[mt*4+3],
                                 bhi[nt*2], bhi[nt*2+1]);
                    }
            }
        }
        __syncthreads();
    }

    // ---- epilogue: bias + relu + att + norms -> fp16 messages ----
#pragma unroll
    for (int nt = 0; nt < 4; nt++) {
        int cl = warp_n * 32 + nt * 8 + tig * 2;
        int gc = col_half + cl;
        float bm0 = bm[gc], bm1 = bm[gc + 1];
        float bv0 = bv[gc], bv1 = bv[gc + 1];
#pragma unroll
        for (int mt = 0; mt < 2; mt++) {
#pragma unroll
            for (int half = 0; half < 2; half++) {
                int gm = bm_base + warp_m * 32 + mt * 16 + gid + half * 8;
                float n1 = g_norm1[gm];
                float n2 = g_norm2[gm];
                float mean0 = fmaxf(acc[0][mt][nt][half * 2 + 0] + bm0, 0.f);
                float mean1 = fmaxf(acc[0][mt][nt][half * 2 + 1] + bm1, 0.f);
                float var0  = fmaxf(acc[1][mt][nt][half * 2 + 0] + bv0, 0.f);
                float var1  = fmaxf(acc[1][mt][nt][half * 2 + 1] + bv1, 0.f);
                float att0 = expf(-var0), att1 = expf(-var1);
                float2 om = make_float2(mean0 * att0 * n1, mean1 * att1 * n1);
                float2 ov = make_float2(var0 * att0 * att0 * n2, var1 * att1 * att1 * n2);
                *reinterpret_cast<__half2*>(Cm + (size_t)gm * HID + gc) = __float22half2_rn(om);
                *reinterpret_cast<__half2*>(Cv + (size_t)gm * HID + gc) = __float22half2_rn(ov);
            }
        }
    }
}

// ================= layer-2: dual-A dual GEMM, 3xTF32, K=128, N=64, fp16 out =================
__global__ void __launch_bounds__(256)
k_l2_tf32(const float* __restrict__ Am, const float* __restrict__ Av,   // [M_PAD][128]
          const float* __restrict__ Wm, const float* __restrict__ Wv,   // [128][64]
          const float* __restrict__ bm, const float* __restrict__ bv,
          __half* __restrict__ Cm, __half* __restrict__ Cv) {
    __shared__ float As[2][2][128 * L1_APAD];   // [stage][matrix]
    __shared__ float Bs[2][16 * L1_BPAD];

    const int tid = threadIdx.x;
    const int lane = tid & 31;
    const int wid = tid >> 5;
    const int warp_m = wid & 3;
    const int warp_n = wid >> 2;
    const int gid = lane >> 2;
    const int tig = lane & 3;
    const int bm_base = blockIdx.x * 128;

    float acc[2][2][4][4];
#pragma unroll
    for (int a = 0; a < 2; a++)
#pragma unroll
        for (int b = 0; b < 2; b++)
#pragma unroll
            for (int c = 0; c < 4; c++)
#pragma unroll
                for (int d = 0; d < 4; d++) acc[a][b][c][d] = 0.f;

    uint32_t asbase[2][2], bsbase[2];
#pragma unroll
    for (int s = 0; s < 2; s++) {
        asbase[s][0] = (uint32_t)__cvta_generic_to_shared(&As[s][0][0]);
        asbase[s][1] = (uint32_t)__cvta_generic_to_shared(&As[s][1][0]);
        bsbase[s]    = (uint32_t)__cvta_generic_to_shared(&Bs[s][0]);
    }

    auto issue = [&](int stage, int k0) {
#pragma unroll
        for (int c = tid; c < 1024; c += 256) {
            int mat = c >> 9;
            int r = (c >> 2) & 127;
            int kq = c & 3;
            const float* src = (mat ? Av : Am) + (size_t)(bm_base + r) * HID + k0 + kq * 4;
            cp16(asbase[stage][mat] + (uint32_t)(r * L1_APAD + kq * 4) * 4, src, 16);
        }
#pragma unroll
        for (int c = tid; c < 512; c += 256) {
            int r = c >> 5, cc = c & 31;
            int mat = cc >> 4, q = cc & 15;
            const float* srcb = (mat ? Wv : Wm) + (size_t)(k0 + r) * OUTF + q * 4;
            cp16(bsbase[stage] + (uint32_t)(r * L1_BPAD + mat * 64 + q * 4) * 4, srcb, 16);
        }
        cp_commit();
    };

    issue(0, 0);

    const int NITER = HID / 16;   // 8
    for (int it = 0; it < NITER; it++) {
        int stage = it & 1;
        if (it + 1 < NITER) {
            issue(stage ^ 1, (it + 1) * 16);
            cp_wait<1>();
        } else {
            cp_wait<0>();
        }
        __syncthreads();

        const float* bs = Bs[stage];

#pragma unroll
        for (int ks = 0; ks < 2; ks++) {
            const int k8 = ks * 8;
#pragma unroll
            for (int mat = 0; mat < 2; mat++) {
                const float* as = As[stage][mat];
                uint32_t ahi[8], alo[8];
#pragma unroll
                for (int mt = 0; mt < 2; mt++) {
                    int rb = warp_m * 32 + mt * 16;
                    float a0 = as[(rb + gid) * L1_APAD + k8 + tig];
                    float a1 = as[(rb + gid + 8) * L1_APAD + k8 + tig];
                    float a2 = as[(rb + gid) * L1_APAD + k8 + tig + 4];
                    float a3 = as[(rb + gid + 8) * L1_APAD + k8 + tig + 4];
                    ahi[mt * 4 + 0] = cvt_tf32(a0);
                    ahi[mt * 4 + 1] = cvt_tf32(a1);
                    ahi[mt * 4 + 2] = cvt_tf32(a2);
                    ahi[mt * 4 + 3] = cvt_tf32(a3);
                    alo[mt * 4 + 0] = cvt_tf32(a0 - __uint_as_float(ahi[mt * 4 + 0]));
                    alo[mt * 4 + 1] = cvt_tf32(a1 - __uint_as_float(ahi[mt * 4 + 1]));
                    alo[mt * 4 + 2] = cvt_tf32(a2 - __uint_as_float(ahi[mt * 4 + 2]));
                    alo[mt * 4 + 3] = cvt_tf32(a3 - __uint_as_float(ahi[mt * 4 + 3]));
                }
                uint32_t bhi[8], blo[8];
#pragma unroll
                for (int nt = 0; nt < 4; nt++) {
                    int col = mat * 64 + warp_n * 32 + nt * 8 + gid;
                    float b0 = bs[(k8 + tig) * L1_BPAD + col];
                    float b1 = bs[(k8 + tig + 4) * L1_BPAD + col];
                    bhi[nt * 2 + 0] = cvt_tf32(b0);
                    bhi[nt * 2 + 1] = cvt_tf32(b1);
                    blo[nt * 2 + 0] = cvt_tf32(b0 - __uint_as_float(bhi[nt * 2 + 0]));
                    blo[nt * 2 + 1] = cvt_tf32(b1 - __uint_as_float(bhi[nt * 2 + 1]));
                }
#pragma unroll
                for (int mt = 0; mt < 2; mt++)
#pragma unroll
                    for (int nt = 0; nt < 4; nt++) {
                        float* d = acc[mat][mt][nt];
                        mma_tf32(d, ahi[mt*4], ahi[mt*4+1], ahi[mt*4+2], ahi[mt*4+3],
                                 bhi[nt*2], bhi[nt*2+1]);
                        mma_tf32(d, ahi[mt*4], ahi[mt*4+1], ahi[mt*4+2], ahi[mt*4+3],
                                 blo[nt*2], blo[nt*2+1]);
                        mma_tf32(d, alo[mt*4], alo[mt*4+1], alo[mt*4+2], alo[mt*4+3],
                                 bhi[nt*2], bhi[nt*2+1]);
                    }
            }
        }
        __syncthreads();
    }

    // ---- epilogue -> fp16 messages [M_PAD][64] ----
#pragma unroll
    for (int nt = 0; nt < 4; nt++) {
        int gc = warp_n * 32 + nt * 8 + tig * 2;
        float bm0 = bm[gc], bm1 = bm[gc + 1];
        float bv0 = bv[gc], bv1 = bv[gc + 1];
#pragma unroll
        for (int mt = 0; mt < 2; mt++) {
#pragma unroll
            for (int half = 0; half < 2; half++) {
                int gm = bm_base + warp_m * 32 + mt * 16 + gid + half * 8;
                float n1 = g_norm1[gm];
                float n2 = g_norm2[gm];
                float mean0 = fmaxf(acc[0][mt][nt][half * 2 + 0] + bm0, 0.f);
                float mean1 = fmaxf(acc[0][mt][nt][half * 2 + 1] + bm1, 0.f);
                float var0  = fmaxf(acc[1][mt][nt][half * 2 + 0] + bv0, 0.f);
                float var1  = fmaxf(acc[1][mt][nt][half * 2 + 1] + bv1, 0.f);
                float att0 = expf(-var0), att1 = expf(-var1);
                float2 om = make_float2(mean0 * att0 * n1, mean1 * att1 * n1);
                float2 ov = make_float2(var0 * att0 * att0 * n2, var1 * att1 * att1 * n2);
                *reinterpret_cast<__half2*>(Cm + (size_t)gm * OUTF + gc) = __float22half2_rn(om);
                *reinterpret_cast<__half2*>(Cv + (size_t)gm * OUTF + gc) = __float22half2_rn(ov);
            }
        }
    }
}

// ---------------- aggregation: warp per node, CSR pure-read reduce (fp16 msgs) ----------------
__global__ void k_agg1(const __half* __restrict__ msrc, const __half* __restrict__ vsrc,
                       float* __restrict__ mdst, float* __restrict__ vdst, int n) {
    int warp = (blockIdx.x * blockDim.x + threadIdx.x) >> 5;
    int lane = threadIdx.x & 31;
    if (warp >= n) return;
    const int D = 128;
    int start = g_offs[warp], end = g_offs[warp + 1];

    float am[4] = {0.f, 0.f, 0.f, 0.f};
    float av[4] = {0.f, 0.f, 0.f, 0.f};
    for (int e = start; e < end; e++) {
        int s = g_csr[e];
        uint2 ar = __ldg(reinterpret_cast<const uint2*>(msrc + (size_t)s * D + lane * 4));
        uint2 br = __ldg(reinterpret_cast<const uint2*>(vsrc + (size_t)s * D + lane * 4));
        float2 a0 = __half22float2(*reinterpret_cast<__half2*>(&ar.x));
        float2 a1 = __half22float2(*reinterpret_cast<__half2*>(&ar.y));
        float2 b0 = __half22float2(*reinterpret_cast<__half2*>(&br.x));
        float2 b1 = __half22float2(*reinterpret_cast<__half2*>(&br.y));
        am[0] += a0.x; am[1] += a0.y; am[2] += a1.x; am[3] += a1.y;
        av[0] += b0.x; av[1] += b0.y; av[2] += b1.x; av[3] += b1.y;
    }
    float n1 = g_norm1[warp], n2 = g_norm2[warp];
#pragma unroll
    for (int j = 0; j < 4; j++) {
        am[j] = fmaxf(am[j] * n1, 0.f);
        av[j] = fmaxf(av[j] * n2, 0.f);
    }
    *reinterpret_cast<float4*>(mdst + (size_t)warp * D + lane * 4) =
        make_float4(am[0], am[1], am[2], am[3]);
    *reinterpret_cast<float4*>(vdst + (size_t)warp * D + lane * 4) =
        make_float4(av[0], av[1], av[2], av[3]);
}

// ---------------- threefry-2x32-20 (KAT-verified) ----------------
__device__ __forceinline__ uint32_t rotl32(uint32_t x, int d) {
    return (x << d) | (x >> (32 - d));
}

__device__ __forceinline__ void threefry2x32(uint32_t k0, uint32_t k1,
                                             uint32_t& x0, uint32_t& x1) {
    uint32_t s0 = k0, s1 = k1, s2 = k0 ^ k1 ^ 0x1BD11BDAu;
    x0 += s0; x1 += s1;
#define TFR(r) { x0 += x1; x1 = rotl32(x1, r); x1 ^= x0; }
    TFR(13) TFR(15) TFR(26) TFR(6)   x0 += s1; x1 += s2 + 1u;
    TFR(17) TFR(29) TFR(16) TFR(24)  x0 += s2; x1 += s0 + 2u;
    TFR(13) TFR(15) TFR(26) TFR(6)   x0 += s0; x1 += s1 + 3u;
    TFR(17) TFR(29) TFR(16) TFR(24)  x0 += s1; x1 += s2 + 4u;
    TFR(13) TFR(15) TFR(26) TFR(6)   x0 += s2; x1 += s0 + 5u;
#undef TFR
}

__device__ __forceinline__ float jax_normal_elem(uint32_t idx) {
    uint32_t x0 = 0u, x1 = idx;
    threefry2x32(0u, 42u, x0, x1);
    uint32_t bits = x0 ^ x1;
    uint32_t fb = (bits >> 9) | 0x3F800000u;
    float u01 = __uint_as_float(fb) - 1.0f;
    const float lo = -0.99999994f;
    float u = fmaxf(u01 * 2.0f + lo, lo);
    return 1.41421356f * erfinvf(u);
}

// layer-2 aggregation fused with reparameterization (fp16 msgs): warp per node, D=64
__global__ void k_agg2_final(const __half* __restrict__ msrc, const __half* __restrict__ vsrc,
                             float* __restrict__ out, int n) {
    int warp = (blockIdx.x * blockDim.x + threadIdx.x) >> 5;
    int lane = threadIdx.x & 31;
    if (warp >= n) return;
    const int D = 64;
    int start = g_offs[warp], end = g_offs[warp + 1];

    float am0 = 0.f, am1 = 0.f, av0 = 0.f, av1 = 0.f;
    for (int e = start; e < end; e++) {
        int s = g_csr[e];
        __half2 ah = __ldg(reinterpret_cast<const __half2*>(msrc + (size_t)s * D + lane * 2));
        __half2 bh = __ldg(reinterpret_cast<const __half2*>(vsrc + (size_t)s * D + lane * 2));
        float2 a = __half22float2(ah);
        float2 b = __half22float2(bh);
        am0 += a.x; am1 += a.y;
        av0 += b.x; av1 += b.y;
    }
    float n1 = g_norm1[warp], n2 = g_norm2[warp];
    float m0 = am0 * n1, m1 = am1 * n1;
    float v0 = av0 * n2, v1 = av1 * n2;

    uint32_t t0 = (uint32_t)(warp * D + lane * 2);
    float e0 = jax_normal_elem(t0);
    float e1 = jax_normal_elem(t0 + 1u);
    float2 o;
    o.x = e0 * sqrtf(v0 + 1e-8f) + m0;
    o.y = e1 * sqrtf(v1 + 1e-8f) + m1;
    *reinterpret_cast<float2*>(out + (size_t)warp * D + lane * 2) = o;
}

// ---------------- launch ----------------
extern "C" void kernel_launch(void* const* d_in, const int* in_sizes, int n_in,
                              void* d_out, int out_size) {
    const float* x       = (const float*)d_in[0];
    const int*   src     = (const int*)d_in[1];
    const int*   dst     = (const int*)d_in[2];
    const float* w_mean1 = (const float*)d_in[3];
    const float* w_var1  = (const float*)d_in[4];
    const float* b_mean1 = (const float*)d_in[5];
    const float* b_var1  = (const float*)d_in[6];
    const float* w_mean2 = (const float*)d_in[7];
    const float* w_var2  = (const float*)d_in[8];
    const float* b_mean2 = (const float*)d_in[9];
    const float* b_var2  = (const float*)d_in[10];
    float* out = (float*)d_out;

    const int N = in_sizes[0] / IN_F;   // 100000
    const int E = in_sizes[1];          // 1600000

    __half* bufA = nullptr; __half* bufB = nullptr;
    float* aggM = nullptr; float* aggV = nullptr;
    cudaGetSymbolAddress((void**)&bufA, g_bufA);
    cudaGetSymbolAddress((void**)&bufB, g_bufB);
    cudaGetSymbolAddress((void**)&aggM, g_aggM);
    cudaGetSymbolAddress((void**)&aggV, g_aggV);

    const int T = 256;
    const int NB = (N + 1023) / 1024;

    // degrees, norms, CSR
    k_zero<<<(N + T - 1) / T, T>>>(N);
    k_count<<<(E + T - 1) / T, T>>>(dst, E);
    k_norm<<<(N + T - 1) / T, T>>>(N);
    k_scan1<<<NB, 1024>>>(N);
    k_scan2<<<1, 128>>>(NB, N);
    k_scan3<<<NB, 1024>>>(N);
    k_fill<<<(E + T - 1) / T, T>>>(src, dst, E);

    // ---- layer 1: tensor-core (3xTF32) dual GEMM + fp16 msg epilogue ----
    {
        dim3 grid((N + 127) / 128, 2);
        k_l1_tf32<<<grid, 256>>>(x, w_mean1, w_var1, b_mean1, b_var1, bufA, bufB, N);
    }
    {
        int blocks = (N * 32 + T - 1) / T;   // warp per node
        k_agg1<<<blocks, T>>>(bufA, bufB, aggM, aggV, N);
    }

    // ---- layer 2: tensor-core (3xTF32) dual-A GEMM + fp16 msg epilogue ----
    {
        int blocks = (N + 127) / 128;   // 782, covers M_PAD exactly
        k_l2_tf32<<<blocks, 256>>>(aggM, aggV, w_mean2, w_var2,
                                   b_mean2, b_var2, bufA, bufB);
    }
    // ---- layer-2 aggregation fused with threefry reparameterization ----
    {
        int blocks = (N * 32 + T - 1) / T;
        k_agg2_final<<<blocks, T>>>(bufA, bufB, out, N);
    }
}

// round 8
// speedup vs baseline: 2.2011x; 1.2544x over previous
#include <cuda_runtime.h>
#include <cuda_fp16.h>
#include <stdint.h>
#include <math.h>

#define NODES_MAX 100000
#define M_PAD     100096   // 782 * 128
#define EDGES_MAX 1600000
#define IN_F 256
#define HID 128
#define OUTF 64

// ---------------- scratch (static __device__, no allocs) ----------------
__device__ __half g_bufA[(size_t)M_PAD * HID];   // messages m (fp16)
__device__ __half g_bufB[(size_t)M_PAD * HID];   // messages v (fp16)
__device__ float  g_aggM[(size_t)M_PAD * HID];   // aggregated mean (fp32)
__device__ float  g_aggV[(size_t)M_PAD * HID];
__device__ float  g_norm1[M_PAD];
__device__ float  g_norm2[M_PAD];
__device__ int    g_deg[NODES_MAX];
__device__ int    g_cursor[NODES_MAX];
__device__ int    g_offs[NODES_MAX + 1];
__device__ int    g_csr[EDGES_MAX];
__device__ int    g_bsum[128];
__device__ int    g_boff[128];

// ---------------- degree / norms ----------------
__global__ void k_zero(int n) {
    int i = blockIdx.x * blockDim.x + threadIdx.x;
    if (i < n) { g_deg[i] = 0; g_cursor[i] = 0; }
}

__global__ void k_count(const int* __restrict__ dst, int E) {
    int e = blockIdx.x * blockDim.x + threadIdx.x;
    if (e < E) atomicAdd(&g_deg[dst[e]], 1);
}

__global__ void k_norm(int n) {
    int i = blockIdx.x * blockDim.x + threadIdx.x;
    if (i < n) {
        float d = fmaxf((float)g_deg[i], 1.0f);
        float n1 = 1.0f / sqrtf(d);
        g_norm1[i] = n1;
        g_norm2[i] = n1 * n1;
    }
}

// ---------------- parallel 3-phase exclusive scan ----------------
__global__ void k_scan1(int n) {
    __shared__ int sm[1024];
    int t = threadIdx.x;
    int i = blockIdx.x * 1024 + t;
    int v = (i < n) ? g_deg[i] : 0;
    sm[t] = v;
    __syncthreads();
#pragma unroll
    for (int d = 1; d < 1024; d <<= 1) {
        int u = (t >= d) ? sm[t - d] : 0;
        __syncthreads();
        sm[t] += u;
        __syncthreads();
    }
    if (i < n) g_offs[i] = sm[t] - v;
    if (t == 1023) g_bsum[blockIdx.x] = sm[1023];
}

__global__ void k_scan2(int nb, int n) {
    __shared__ int sm[128];
    int t = threadIdx.x;
    int v = (t < nb) ? g_bsum[t] : 0;
    sm[t] = v;
    __syncthreads();
#pragma unroll
    for (int d = 1; d < 128; d <<= 1) {
        int u = (t >= d) ? sm[t - d] : 0;
        __syncthreads();
        sm[t] += u;
        __syncthreads();
    }
    if (t < nb) g_boff[t] = sm[t] - v;
    if (t == 127) g_offs[n] = sm[127];
}

__global__ void k_scan3(int n) {
    int i = blockIdx.x * 1024 + threadIdx.x;
    if (i < n) g_offs[i] += g_boff[blockIdx.x];
}

__global__ void k_fill(const int* __restrict__ src, const int* __restrict__ dst, int E) {
    int e = blockIdx.x * blockDim.x + threadIdx.x;
    if (e < E) {
        int d = dst[e];
        int p = atomicAdd(&g_cursor[d], 1);
        g_csr[g_offs[d] + p] = src[e];
    }
}

// ================= tensor-core helpers (3xFP16 split, m16n8k16) =================
// x = hi + lo with hi,lo fp16; residual ~2^-22|x|. Products exact, fp32 accum.
__device__ __forceinline__ void split2(float x0, float x1, uint32_t& hi, uint32_t& lo) {
    __half2 h = __floats2half2_rn(x0, x1);
    float2 hf = __half22float2(h);
    __half2 l = __floats2half2_rn(x0 - hf.x, x1 - hf.y);
    hi = *reinterpret_cast<uint32_t*>(&h);
    lo = *reinterpret_cast<uint32_t*>(&l);
}

__device__ __forceinline__ void mma_f16(float* d, uint32_t a0, uint32_t a1,
                                        uint32_t a2, uint32_t a3,
                                        uint32_t b0, uint32_t b1) {
    asm volatile(
        "mma.sync.aligned.m16n8k16.row.col.f32.f16.f16.f32 "
        "{%0,%1,%2,%3},{%4,%5,%6,%7},{%8,%9},{%0,%1,%2,%3};"
        : "+f"(d[0]), "+f"(d[1]), "+f"(d[2]), "+f"(d[3])
        : "r"(a0), "r"(a1), "r"(a2), "r"(a3), "r"(b0), "r"(b1));
}

__device__ __forceinline__ void cp16(uint32_t dst, const void* src, int sz) {
    asm volatile("cp.async.cg.shared.global [%0], [%1], 16, %2;"
                 :: "r"(dst), "l"(src), "r"(sz));
}
__device__ __forceinline__ void cp_commit() {
    asm volatile("cp.async.commit_group;");
}
template <int N> __device__ __forceinline__ void cp_wait() {
    asm volatile("cp.async.wait_group %0;" :: "n"(N));
}

#define L1_APAD 20    // floats per A smem row (16 + 4)
#define L1_BPAD 136   // floats per B smem row (128 + 8)

// ---- shared inner-compute: one k16 step for one A-source ----
// as: A smem tile (128 rows x 16 k, stride L1_APAD)
// bs: B smem tile (16 k-rows x 128 cols, stride L1_BPAD); matrix `mat` at col offset mat*64
struct AFrag { uint32_t hi[4], lo[4]; };

__device__ __forceinline__ AFrag load_afrag(const float* as, int rb, int gid, int tig) {
    AFrag f;
    const float* r0 = as + (rb + gid) * L1_APAD;
    const float* r1 = as + (rb + gid + 8) * L1_APAD;
    float2 x0 = *reinterpret_cast<const float2*>(r0 + 2 * tig);
    float2 x1 = *reinterpret_cast<const float2*>(r1 + 2 * tig);
    float2 x2 = *reinterpret_cast<const float2*>(r0 + 2 * tig + 8);
    float2 x3 = *reinterpret_cast<const float2*>(r1 + 2 * tig + 8);
    split2(x0.x, x0.y, f.hi[0], f.lo[0]);
    split2(x1.x, x1.y, f.hi[1], f.lo[1]);
    split2(x2.x, x2.y, f.hi[2], f.lo[2]);
    split2(x3.x, x3.y, f.hi[3], f.lo[3]);
    return f;
}

// ================= layer-1: shared-A dual GEMM, 3xFP16, fp16 message out =================
__global__ void __launch_bounds__(256)
k_l1_f16(const float* __restrict__ X,
         const float* __restrict__ Wm, const float* __restrict__ Wv,   // [256][128]
         const float* __restrict__ bm, const float* __restrict__ bv,
         __half* __restrict__ Cm, __half* __restrict__ Cv, int M) {
    __shared__ float As[2][128 * L1_APAD];
    __shared__ float Bs[2][16 * L1_BPAD];

    const int tid = threadIdx.x;
    const int lane = tid & 31;
    const int wid = tid >> 5;
    const int warp_m = wid & 3;
    const int warp_n = wid >> 2;
    const int gid = lane >> 2;
    const int tig = lane & 3;
    const int bm_base = blockIdx.x * 128;
    const int col_half = blockIdx.y * 64;

    float acc[2][2][4][4];
#pragma unroll
    for (int a = 0; a < 2; a++)
#pragma unroll
        for (int b = 0; b < 2; b++)
#pragma unroll
            for (int c = 0; c < 4; c++)
#pragma unroll
                for (int d = 0; d < 4; d++) acc[a][b][c][d] = 0.f;

    uint32_t asbase[2], bsbase[2];
    asbase[0] = (uint32_t)__cvta_generic_to_shared(&As[0][0]);
    asbase[1] = (uint32_t)__cvta_generic_to_shared(&As[1][0]);
    bsbase[0] = (uint32_t)__cvta_generic_to_shared(&Bs[0][0]);
    bsbase[1] = (uint32_t)__cvta_generic_to_shared(&Bs[1][0]);

    auto issue = [&](int stage, int k0) {
#pragma unroll
        for (int c = tid; c < 512; c += 256) {
            int r = c >> 2, kq = c & 3;
            int gm = bm_base + r;
            int ok = (gm < M) ? 16 : 0;
            const float* src = X + (size_t)min(gm, M - 1) * IN_F + k0 + kq * 4;
            cp16(asbase[stage] + (uint32_t)(r * L1_APAD + kq * 4) * 4, src, ok);
        }
#pragma unroll
        for (int c = tid; c < 512; c += 256) {
            int r = c >> 5, cc = c & 31;
            int mat = cc >> 4, q = cc & 15;
            const float* srcb = (mat ? Wv : Wm) + (size_t)(k0 + r) * HID + col_half + q * 4;
            cp16(bsbase[stage] + (uint32_t)(r * L1_BPAD + mat * 64 + q * 4) * 4, srcb, 16);
        }
        cp_commit();
    };

    issue(0, 0);

    const int NITER = IN_F / 16;   // 16
    for (int it = 0; it < NITER; it++) {
        int stage = it & 1;
        if (it + 1 < NITER) {
            issue(stage ^ 1, (it + 1) * 16);
            cp_wait<1>();
        } else {
            cp_wait<0>();
        }
        __syncthreads();

        const float* as = As[stage];
        const float* bs = Bs[stage];

        // A fragments for both M-tiles (shared across both matrices)
        AFrag af[2];
#pragma unroll
        for (int mt = 0; mt < 2; mt++)
            af[mt] = load_afrag(as, warp_m * 32 + mt * 16, gid, tig);

#pragma unroll
        for (int mat = 0; mat < 2; mat++) {
            uint32_t bhi[8], blo[8];
#pragma unroll
            for (int nt = 0; nt < 4; nt++) {
                int col = mat * 64 + warp_n * 32 + nt * 8 + gid;
                float b00 = bs[(2 * tig) * L1_BPAD + col];
                float b01 = bs[(2 * tig + 1) * L1_BPAD + col];
                float b10 = bs[(2 * tig + 8) * L1_BPAD + col];
                float b11 = bs[(2 * tig + 9) * L1_BPAD + col];
                split2(b00, b01, bhi[nt * 2 + 0], blo[nt * 2 + 0]);
                split2(b10, b11, bhi[nt * 2 + 1], blo[nt * 2 + 1]);
            }
#pragma unroll
            for (int mt = 0; mt < 2; mt++)
#pragma unroll
                for (int nt = 0; nt < 4; nt++) {
                    float* d = acc[mat][mt][nt];
                    mma_f16(d, af[mt].hi[0], af[mt].hi[1], af[mt].hi[2], af[mt].hi[3],
                            bhi[nt*2], bhi[nt*2+1]);
                    mma_f16(d, af[mt].hi[0], af[mt].hi[1], af[mt].hi[2], af[mt].hi[3],
                            blo[nt*2], blo[nt*2+1]);
                    mma_f16(d, af[mt].lo[0], af[mt].lo[1], af[mt].lo[2], af[mt].lo[3],
                            bhi[nt*2], bhi[nt*2+1]);
                }
        }
        __syncthreads();
    }

    // ---- epilogue: bias + relu + att + norms -> fp16 messages ----
#pragma unroll
    for (int nt = 0; nt < 4; nt++) {
        int cl = warp_n * 32 + nt * 8 + tig * 2;
        int gc = col_half + cl;
        float bm0 = bm[gc], bm1 = bm[gc + 1];
        float bv0 = bv[gc], bv1 = bv[gc + 1];
#pragma unroll
        for (int mt = 0; mt < 2; mt++) {
#pragma unroll
            for (int half = 0; half < 2; half++) {
                int gm = bm_base + warp_m * 32 + mt * 16 + gid + half * 8;
                float n1 = g_norm1[gm];
                float n2 = g_norm2[gm];
                float mean0 = fmaxf(acc[0][mt][nt][half * 2 + 0] + bm0, 0.f);
                float mean1 = fmaxf(acc[0][mt][nt][half * 2 + 1] + bm1, 0.f);
                float var0  = fmaxf(acc[1][mt][nt][half * 2 + 0] + bv0, 0.f);
                float var1  = fmaxf(acc[1][mt][nt][half * 2 + 1] + bv1, 0.f);
                float att0 = expf(-var0), att1 = expf(-var1);
                float2 om = make_float2(mean0 * att0 * n1, mean1 * att1 * n1);
                float2 ov = make_float2(var0 * att0 * att0 * n2, var1 * att1 * att1 * n2);
                *reinterpret_cast<__half2*>(Cm + (size_t)gm * HID + gc) = __float22half2_rn(om);
                *reinterpret_cast<__half2*>(Cv + (size_t)gm * HID + gc) = __float22half2_rn(ov);
            }
        }
    }
}

// ================= layer-2: dual-A dual GEMM, 3xFP16, K=128, N=64, fp16 out =================
__global__ void __launch_bounds__(256)
k_l2_f16(const float* __restrict__ Am, const float* __restrict__ Av,   // [M_PAD][128]
         const float* __restrict__ Wm, const float* __restrict__ Wv,   // [128][64]
         const float* __restrict__ bm, const float* __restrict__ bv,
         __half* __restrict__ Cm, __half* __restrict__ Cv) {
    __shared__ float As[2][2][128 * L1_APAD];   // [stage][matrix]
    __shared__ float Bs[2][16 * L1_BPAD];

    const int tid = threadIdx.x;
    const int lane = tid & 31;
    const int wid = tid >> 5;
    const int warp_m = wid & 3;
    const int warp_n = wid >> 2;
    const int gid = lane >> 2;
    const int tig = lane & 3;
    const int bm_base = blockIdx.x * 128;

    float acc[2][2][4][4];
#pragma unroll
    for (int a = 0; a < 2; a++)
#pragma unroll
        for (int b = 0; b < 2; b++)
#pragma unroll
            for (int c = 0; c < 4; c++)
#pragma unroll
                for (int d = 0; d < 4; d++) acc[a][b][c][d] = 0.f;

    uint32_t asbase[2][2], bsbase[2];
#pragma unroll
    for (int s = 0; s < 2; s++) {
        asbase[s][0] = (uint32_t)__cvta_generic_to_shared(&As[s][0][0]);
        asbase[s][1] = (uint32_t)__cvta_generic_to_shared(&As[s][1][0]);
        bsbase[s]    = (uint32_t)__cvta_generic_to_shared(&Bs[s][0]);
    }

    auto issue = [&](int stage, int k0) {
#pragma unroll
        for (int c = tid; c < 1024; c += 256) {
            int mat = c >> 9;
            int r = (c >> 2) & 127;
            int kq = c & 3;
            const float* src = (mat ? Av : Am) + (size_t)(bm_base + r) * HID + k0 + kq * 4;
            cp16(asbase[stage][mat] + (uint32_t)(r * L1_APAD + kq * 4) * 4, src, 16);
        }
#pragma unroll
        for (int c = tid; c < 512; c += 256) {
            int r = c >> 5, cc = c & 31;
            int mat = cc >> 4, q = cc & 15;
            const float* srcb = (mat ? Wv : Wm) + (size_t)(k0 + r) * OUTF + q * 4;
            cp16(bsbase[stage] + (uint32_t)(r * L1_BPAD + mat * 64 + q * 4) * 4, srcb, 16);
        }
        cp_commit();
    };

    issue(0, 0);

    const int NITER = HID / 16;   // 8
    for (int it = 0; it < NITER; it++) {
        int stage = it & 1;
        if (it + 1 < NITER) {
            issue(stage ^ 1, (it + 1) * 16);
            cp_wait<1>();
        } else {
            cp_wait<0>();
        }
        __syncthreads();

        const float* bs = Bs[stage];

#pragma unroll
        for (int mat = 0; mat < 2; mat++) {
            const float* as = As[stage][mat];
            AFrag af[2];
#pragma unroll
            for (int mt = 0; mt < 2; mt++)
                af[mt] = load_afrag(as, warp_m * 32 + mt * 16, gid, tig);

            uint32_t bhi[8], blo[8];
#pragma unroll
            for (int nt = 0; nt < 4; nt++) {
                int col = mat * 64 + warp_n * 32 + nt * 8 + gid;
                float b00 = bs[(2 * tig) * L1_BPAD + col];
                float b01 = bs[(2 * tig + 1) * L1_BPAD + col];
                float b10 = bs[(2 * tig + 8) * L1_BPAD + col];
                float b11 = bs[(2 * tig + 9) * L1_BPAD + col];
                split2(b00, b01, bhi[nt * 2 + 0], blo[nt * 2 + 0]);
                split2(b10, b11, bhi[nt * 2 + 1], blo[nt * 2 + 1]);
            }
#pragma unroll
            for (int mt = 0; mt < 2; mt++)
#pragma unroll
                for (int nt = 0; nt < 4; nt++) {
                    float* d = acc[mat][mt][nt];
                    mma_f16(d, af[mt].hi[0], af[mt].hi[1], af[mt].hi[2], af[mt].hi[3],
                            bhi[nt*2], bhi[nt*2+1]);
                    mma_f16(d, af[mt].hi[0], af[mt].hi[1], af[mt].hi[2], af[mt].hi[3],
                            blo[nt*2], blo[nt*2+1]);
                    mma_f16(d, af[mt].lo[0], af[mt].lo[1], af[mt].lo[2], af[mt].lo[3],
                            bhi[nt*2], bhi[nt*2+1]);
                }
        }
        __syncthreads();
    }

    // ---- epilogue -> fp16 messages [M_PAD][64] ----
#pragma unroll
    for (int nt = 0; nt < 4; nt++) {
        int gc = warp_n * 32 + nt * 8 + tig * 2;
        float bm0 = bm[gc], bm1 = bm[gc + 1];
        float bv0 = bv[gc], bv1 = bv[gc + 1];
#pragma unroll
        for (int mt = 0; mt < 2; mt++) {
#pragma unroll
            for (int half = 0; half < 2; half++) {
                int gm = bm_base + warp_m * 32 + mt * 16 + gid + half * 8;
                float n1 = g_norm1[gm];
                float n2 = g_norm2[gm];
                float mean0 = fmaxf(acc[0][mt][nt][half * 2 + 0] + bm0, 0.f);
                float mean1 = fmaxf(acc[0][mt][nt][half * 2 + 1] + bm1, 0.f);
                float var0  = fmaxf(acc[1][mt][nt][half * 2 + 0] + bv0, 0.f);
                float var1  = fmaxf(acc[1][mt][nt][half * 2 + 1] + bv1, 0.f);
                float att0 = expf(-var0), att1 = expf(-var1);
                float2 om = make_float2(mean0 * att0 * n1, mean1 * att1 * n1);
                float2 ov = make_float2(var0 * att0 * att0 * n2, var1 * att1 * att1 * n2);
                *reinterpret_cast<__half2*>(Cm + (size_t)gm * OUTF + gc) = __float22half2_rn(om);
                *reinterpret_cast<__half2*>(Cv + (size_t)gm * OUTF + gc) = __float22half2_rn(ov);
            }
        }
    }
}

// ---------------- aggregation: warp per node, CSR pure-read reduce (fp16 msgs) ----------------
__global__ void k_agg1(const __half* __restrict__ msrc, const __half* __restrict__ vsrc,
                       float* __restrict__ mdst, float* __restrict__ vdst, int n) {
    int warp = (blockIdx.x * blockDim.x + threadIdx.x) >> 5;
    int lane = threadIdx.x & 31;
    if (warp >= n) return;
    const int D = 128;
    int start = g_offs[warp], end = g_offs[warp + 1];

    float am[4] = {0.f, 0.f, 0.f, 0.f};
    float av[4] = {0.f, 0.f, 0.f, 0.f};
    for (int e = start; e < end; e++) {
        int s = g_csr[e];
        uint2 ar = __ldg(reinterpret_cast<const uint2*>(msrc + (size_t)s * D + lane * 4));
        uint2 br = __ldg(reinterpret_cast<const uint2*>(vsrc + (size_t)s * D + lane * 4));
        float2 a0 = __half22float2(*reinterpret_cast<__half2*>(&ar.x));
        float2 a1 = __half22float2(*reinterpret_cast<__half2*>(&ar.y));
        float2 b0 = __half22float2(*reinterpret_cast<__half2*>(&br.x));
        float2 b1 = __half22float2(*reinterpret_cast<__half2*>(&br.y));
        am[0] += a0.x; am[1] += a0.y; am[2] += a1.x; am[3] += a1.y;
        av[0] += b0.x; av[1] += b0.y; av[2] += b1.x; av[3] += b1.y;
    }
    float n1 = g_norm1[warp], n2 = g_norm2[warp];
#pragma unroll
    for (int j = 0; j < 4; j++) {
        am[j] = fmaxf(am[j] * n1, 0.f);
        av[j] = fmaxf(av[j] * n2, 0.f);
    }
    *reinterpret_cast<float4*>(mdst + (size_t)warp * D + lane * 4) =
        make_float4(am[0], am[1], am[2], am[3]);
    *reinterpret_cast<float4*>(vdst + (size_t)warp * D + lane * 4) =
        make_float4(av[0], av[1], av[2], av[3]);
}

// ---------------- threefry-2x32-20 (KAT-verified) ----------------
__device__ __forceinline__ uint32_t rotl32(uint32_t x, int d) {
    return (x << d) | (x >> (32 - d));
}

__device__ __forceinline__ void threefry2x32(uint32_t k0, uint32_t k1,
                                             uint32_t& x0, uint32_t& x1) {
    uint32_t s0 = k0, s1 = k1, s2 = k0 ^ k1 ^ 0x1BD11BDAu;
    x0 += s0; x1 += s1;
#define TFR(r) { x0 += x1; x1 = rotl32(x1, r); x1 ^= x0; }
    TFR(13) TFR(15) TFR(26) TFR(6)   x0 += s1; x1 += s2 + 1u;
    TFR(17) TFR(29) TFR(16) TFR(24)  x0 += s2; x1 += s0 + 2u;
    TFR(13) TFR(15) TFR(26) TFR(6)   x0 += s0; x1 += s1 + 3u;
    TFR(17) TFR(29) TFR(16) TFR(24)  x0 += s1; x1 += s2 + 4u;
    TFR(13) TFR(15) TFR(26) TFR(6)   x0 += s2; x1 += s0 + 5u;
#undef TFR
}

__device__ __forceinline__ float jax_normal_elem(uint32_t idx) {
    uint32_t x0 = 0u, x1 = idx;
    threefry2x32(0u, 42u, x0, x1);
    uint32_t bits = x0 ^ x1;
    uint32_t fb = (bits >> 9) | 0x3F800000u;
    float u01 = __uint_as_float(fb) - 1.0f;
    const float lo = -0.99999994f;
    float u = fmaxf(u01 * 2.0f + lo, lo);
    return 1.41421356f * erfinvf(u);
}

// layer-2 aggregation fused with reparameterization (fp16 msgs): warp per node, D=64
__global__ void k_agg2_final(const __half* __restrict__ msrc, const __half* __restrict__ vsrc,
                             float* __restrict__ out, int n) {
    int warp = (blockIdx.x * blockDim.x + threadIdx.x) >> 5;
    int lane = threadIdx.x & 31;
    if (warp >= n) return;
    const int D = 64;
    int start = g_offs[warp], end = g_offs[warp + 1];

    float am0 = 0.f, am1 = 0.f, av0 = 0.f, av1 = 0.f;
    for (int e = start; e < end; e++) {
        int s = g_csr[e];
        __half2 ah = __ldg(reinterpret_cast<const __half2*>(msrc + (size_t)s * D + lane * 2));
        __half2 bh = __ldg(reinterpret_cast<const __half2*>(vsrc + (size_t)s * D + lane * 2));
        float2 a = __half22float2(ah);
        float2 b = __half22float2(bh);
        am0 += a.x; am1 += a.y;
        av0 += b.x; av1 += b.y;
    }
    float n1 = g_norm1[warp], n2 = g_norm2[warp];
    float m0 = am0 * n1, m1 = am1 * n1;
    float v0 = av0 * n2, v1 = av1 * n2;

    uint32_t t0 = (uint32_t)(warp * D + lane * 2);
    float e0 = jax_normal_elem(t0);
    float e1 = jax_normal_elem(t0 + 1u);
    float2 o;
    o.x = e0 * sqrtf(v0 + 1e-8f) + m0;
    o.y = e1 * sqrtf(v1 + 1e-8f) + m1;
    *reinterpret_cast<float2*>(out + (size_t)warp * D + lane * 2) = o;
}

// ---------------- launch ----------------
extern "C" void kernel_launch(void* const* d_in, const int* in_sizes, int n_in,
                              void* d_out, int out_size) {
    const float* x       = (const float*)d_in[0];
    const int*   src     = (const int*)d_in[1];
    const int*   dst     = (const int*)d_in[2];
    const float* w_mean1 = (const float*)d_in[3];
    const float* w_var1  = (const float*)d_in[4];
    const float* b_mean1 = (const float*)d_in[5];
    const float* b_var1  = (const float*)d_in[6];
    const float* w_mean2 = (const float*)d_in[7];
    const float* w_var2  = (const float*)d_in[8];
    const float* b_mean2 = (const float*)d_in[9];
    const float* b_var2  = (const float*)d_in[10];
    float* out = (float*)d_out;

    const int N = in_sizes[0] / IN_F;   // 100000
    const int E = in_sizes[1];          // 1600000

    __half* bufA = nullptr; __half* bufB = nullptr;
    float* aggM = nullptr; float* aggV = nullptr;
    cudaGetSymbolAddress((void**)&bufA, g_bufA);
    cudaGetSymbolAddress((void**)&bufB, g_bufB);
    cudaGetSymbolAddress((void**)&aggM, g_aggM);
    cudaGetSymbolAddress((void**)&aggV, g_aggV);

    const int T = 256;
    const int NB = (N + 1023) / 1024;

    // degrees, norms, CSR
    k_zero<<<(N + T - 1) / T, T>>>(N);
    k_count<<<(E + T - 1) / T, T>>>(dst, E);
    k_norm<<<(N + T - 1) / T, T>>>(N);
    k_scan1<<<NB, 1024>>>(N);
    k_scan2<<<1, 128>>>(NB, N);
    k_scan3<<<NB, 1024>>>(N);
    k_fill<<<(E + T - 1) / T, T>>>(src, dst, E);

    // ---- layer 1: tensor-core (3xFP16) dual GEMM + fp16 msg epilogue ----
    {
        dim3 grid((N + 127) / 128, 2);
        k_l1_f16<<<grid, 256>>>(x, w_mean1, w_var1, b_mean1, b_var1, bufA, bufB, N);
    }
    {
        int blocks = (N * 32 + T - 1) / T;   // warp per node
        k_agg1<<<blocks, T>>>(bufA, bufB, aggM, aggV, N);
    }

    // ---- layer 2: tensor-core (3xFP16) dual-A GEMM + fp16 msg epilogue ----
    {
        int blocks = (N + 127) / 128;   // 782, covers M_PAD exactly
        k_l2_f16<<<blocks, 256>>>(aggM, aggV, w_mean2, w_var2,
                                  b_mean2, b_var2, bufA, bufB);
    }
    // ---- layer-2 aggregation fused with threefry reparameterization ----
    {
        int blocks = (N * 32 + T - 1) / T;
        k_agg2_final<<<blocks, T>>>(bufA, bufB, out, N);
    }
}

// round 9
// speedup vs baseline: 2.5245x; 1.1469x over previous
#include <cuda_runtime.h>
#include <cuda_fp16.h>
#include <stdint.h>
#include <math.h>

#define NODES_MAX 100000
#define M_PAD     100096   // 782 * 128
#define EDGES_MAX 1600000
#define IN_F 256
#define HID 128
#define OUTF 64

// ---------------- scratch (static __device__, no allocs) ----------------
__device__ __half  g_bufA[(size_t)M_PAD * HID];   // messages m (fp16)
__device__ __half  g_bufB[(size_t)M_PAD * HID];   // messages v (fp16)
__device__ __half  g_aggM[(size_t)M_PAD * HID];   // aggregated mean (fp16)
__device__ __half  g_aggV[(size_t)M_PAD * HID];
__device__ float   g_norm1[M_PAD];
__device__ float   g_norm2[M_PAD];
__device__ int     g_deg[NODES_MAX];
__device__ int     g_cursor[NODES_MAX];
__device__ int     g_offs[NODES_MAX + 1];
__device__ int     g_csr[EDGES_MAX];
__device__ int     g_bsum[128];
__device__ int     g_boff[128];
// pre-split weights, packed as k-pair half2: [mat][K/2][N]
__device__ __half2 g_w1hi[2 * 128 * 128];
__device__ __half2 g_w1lo[2 * 128 * 128];
__device__ __half2 g_w2hi[2 * 64 * 64];
__device__ __half2 g_w2lo[2 * 64 * 64];

// ---------------- degree / norms ----------------
__global__ void k_zero(int n) {
    int i = blockIdx.x * blockDim.x + threadIdx.x;
    if (i < n) { g_deg[i] = 0; g_cursor[i] = 0; }
}

__global__ void k_count(const int* __restrict__ dst, int E) {
    int e = blockIdx.x * blockDim.x + threadIdx.x;
    if (e < E) atomicAdd(&g_deg[dst[e]], 1);
}

__global__ void k_norm(int n) {
    int i = blockIdx.x * blockDim.x + threadIdx.x;
    if (i < n) {
        float d = fmaxf((float)g_deg[i], 1.0f);
        float n1 = 1.0f / sqrtf(d);
        g_norm1[i] = n1;
        g_norm2[i] = n1 * n1;
    }
}

// ---------------- parallel 3-phase exclusive scan ----------------
__global__ void k_scan1(int n) {
    __shared__ int sm[1024];
    int t = threadIdx.x;
    int i = blockIdx.x * 1024 + t;
    int v = (i < n) ? g_deg[i] : 0;
    sm[t] = v;
    __syncthreads();
#pragma unroll
    for (int d = 1; d < 1024; d <<= 1) {
        int u = (t >= d) ? sm[t - d] : 0;
        __syncthreads();
        sm[t] += u;
        __syncthreads();
    }
    if (i < n) g_offs[i] = sm[t] - v;
    if (t == 1023) g_bsum[blockIdx.x] = sm[1023];
}

__global__ void k_scan2(int nb, int n) {
    __shared__ int sm[128];
    int t = threadIdx.x;
    int v = (t < nb) ? g_bsum[t] : 0;
    sm[t] = v;
    __syncthreads();
#pragma unroll
    for (int d = 1; d < 128; d <<= 1) {
        int u = (t >= d) ? sm[t - d] : 0;
        __syncthreads();
        sm[t] += u;
        __syncthreads();
    }
    if (t < nb) g_boff[t] = sm[t] - v;
    if (t == 127) g_offs[n] = sm[127];
}

__global__ void k_scan3(int n) {
    int i = blockIdx.x * 1024 + threadIdx.x;
    if (i < n) g_offs[i] += g_boff[blockIdx.x];
}

__global__ void k_fill(const int* __restrict__ src, const int* __restrict__ dst, int E) {
    int e = blockIdx.x * blockDim.x + threadIdx.x;
    if (e < E) {
        int d = dst[e];
        int p = atomicAdd(&g_cursor[d], 1);
        g_csr[g_offs[d] + p] = src[e];
    }
}

// ---------------- weight pre-split: fp32 -> (hi,lo) half2 k-pairs ----------------
__global__ void k_cvtw(const float* __restrict__ Wm1, const float* __restrict__ Wv1,
                       const float* __restrict__ Wm2, const float* __restrict__ Wv2) {
    int i = blockIdx.x * blockDim.x + threadIdx.x;
    if (i < 2 * 128 * 128) {   // W1: K=256 -> 128 k-pairs, N=128
        int mat = i >> 14;
        int rem = i & 16383;
        int kk = rem >> 7;
        int n = rem & 127;
        const float* W = mat ? Wv1 : Wm1;
        float a = W[(2 * kk) * HID + n];
        float b = W[(2 * kk + 1) * HID + n];
        __half2 h = __floats2half2_rn(a, b);
        float2 hf = __half22float2(h);
        g_w1hi[i] = h;
        g_w1lo[i] = __floats2half2_rn(a - hf.x, b - hf.y);
    }
    int j = i - 2 * 128 * 128;
    if (j >= 0 && j < 2 * 64 * 64) {   // W2: K=128 -> 64 k-pairs, N=64
        int mat = j >> 12;
        int rem = j & 4095;
        int kk = rem >> 6;
        int n = rem & 63;
        const float* W = mat ? Wv2 : Wm2;
        float a = W[(2 * kk) * OUTF + n];
        float b = W[(2 * kk + 1) * OUTF + n];
        __half2 h = __floats2half2_rn(a, b);
        float2 hf = __half22float2(h);
        g_w2hi[j] = h;
        g_w2lo[j] = __floats2half2_rn(a - hf.x, b - hf.y);
    }
}

// ================= tensor-core helpers =================
__device__ __forceinline__ void split2(float x0, float x1, uint32_t& hi, uint32_t& lo) {
    __half2 h = __floats2half2_rn(x0, x1);
    float2 hf = __half22float2(h);
    __half2 l = __floats2half2_rn(x0 - hf.x, x1 - hf.y);
    hi = *reinterpret_cast<uint32_t*>(&h);
    lo = *reinterpret_cast<uint32_t*>(&l);
}

__device__ __forceinline__ void mma_f16(float* d, uint32_t a0, uint32_t a1,
                                        uint32_t a2, uint32_t a3,
                                        uint32_t b0, uint32_t b1) {
    asm volatile(
        "mma.sync.aligned.m16n8k16.row.col.f32.f16.f16.f32 "
        "{%0,%1,%2,%3},{%4,%5,%6,%7},{%8,%9},{%0,%1,%2,%3};"
        : "+f"(d[0]), "+f"(d[1]), "+f"(d[2]), "+f"(d[3])
        : "r"(a0), "r"(a1), "r"(a2), "r"(a3), "r"(b0), "r"(b1));
}

__device__ __forceinline__ void cp16(uint32_t dst, const void* src, int sz) {
    asm volatile("cp.async.cg.shared.global [%0], [%1], 16, %2;"
                 :: "r"(dst), "l"(src), "r"(sz));
}
__device__ __forceinline__ void cp_commit() {
    asm volatile("cp.async.commit_group;");
}
template <int N> __device__ __forceinline__ void cp_wait() {
    asm volatile("cp.async.wait_group %0;" :: "n"(N));
}

#define APAD 20     // floats per A smem row (16 + 4)  [L1 fp32 A]
#define BPAD2 136   // half2 words per B pair-row (128 cols + 8)  -> conflict-free
#define A2PAD 24    // halfs per A smem row (16 + 8)   [L2 fp16 A]

// ================= layer-1: shared-A dual GEMM, 3xFP16, pre-split B =================
__global__ void __launch_bounds__(256)
k_l1_f16(const float* __restrict__ X,
         const float* __restrict__ bm, const float* __restrict__ bv,
         __half* __restrict__ Cm, __half* __restrict__ Cv, int M) {
    __shared__ float    As[2][128 * APAD];
    __shared__ uint32_t Bh[2][8 * BPAD2];
    __shared__ uint32_t Bl[2][8 * BPAD2];

    const int tid = threadIdx.x;
    const int lane = tid & 31;
    const int wid = tid >> 5;
    const int warp_m = wid & 3;
    const int warp_n = wid >> 2;
    const int gid = lane >> 2;
    const int tig = lane & 3;
    const int bm_base = blockIdx.x * 128;
    const int col_half = blockIdx.y * 64;

    float acc[2][2][4][4];
#pragma unroll
    for (int a = 0; a < 2; a++)
#pragma unroll
        for (int b = 0; b < 2; b++)
#pragma unroll
            for (int c = 0; c < 4; c++)
#pragma unroll
                for (int d = 0; d < 4; d++) acc[a][b][c][d] = 0.f;

    uint32_t asb[2], bhb[2], blb[2];
#pragma unroll
    for (int s = 0; s < 2; s++) {
        asb[s] = (uint32_t)__cvta_generic_to_shared(&As[s][0]);
        bhb[s] = (uint32_t)__cvta_generic_to_shared(&Bh[s][0]);
        blb[s] = (uint32_t)__cvta_generic_to_shared(&Bl[s][0]);
    }

    auto issue = [&](int stage, int k0) {
        int kk0 = k0 >> 1;
        // A tile: 128 rows x 16 k fp32 = 512 x 16B
#pragma unroll
        for (int c = tid; c < 512; c += 256) {
            int r = c >> 2, kq = c & 3;
            int gm = bm_base + r;
            int ok = (gm < M) ? 16 : 0;
            const float* srca = X + (size_t)min(gm, M - 1) * IN_F + k0 + kq * 4;
            cp16(asb[stage] + (uint32_t)(r * APAD + kq * 4) * 4, srca, ok);
        }
        // B tiles (hi+lo): 2 arr x 2 mat x 8 prows x 16 chunks = 512 x 16B
#pragma unroll
        for (int c = tid; c < 512; c += 256) {
            int arr = c >> 8;
            int rem = c & 255;
            int mat = rem >> 7;
            int pr = (rem >> 4) & 7;
            int q = rem & 15;
            const __half2* srcb = (arr ? g_w1lo : g_w1hi)
                + ((mat * 128 + kk0 + pr) * 128 + col_half + q * 4);
            uint32_t dstb = (arr ? blb[stage] : bhb[stage])
                + (uint32_t)(pr * BPAD2 + mat * 64 + q * 4) * 4;
            cp16(dstb, srcb, 16);
        }
        cp_commit();
    };

    issue(0, 0);

    const int NITER = IN_F / 16;   // 16
    for (int it = 0; it < NITER; it++) {
        int stage = it & 1;
        if (it + 1 < NITER) {
            issue(stage ^ 1, (it + 1) * 16);
            cp_wait<1>();
        } else {
            cp_wait<0>();
        }
        __syncthreads();

        const float* as = As[stage];
        const uint32_t* bh = Bh[stage];
        const uint32_t* bl = Bl[stage];

        // A fragments (fp32 -> hi/lo split in-loop; shared across both matrices)
        uint32_t ahi[2][4], alo[2][4];
#pragma unroll
        for (int mt = 0; mt < 2; mt++) {
            int rb = warp_m * 32 + mt * 16;
            const float* r0 = as + (rb + gid) * APAD;
            const float* r1 = as + (rb + gid + 8) * APAD;
            float2 x0 = *reinterpret_cast<const float2*>(r0 + 2 * tig);
            float2 x1 = *reinterpret_cast<const float2*>(r1 + 2 * tig);
            float2 x2 = *reinterpret_cast<const float2*>(r0 + 2 * tig + 8);
            float2 x3 = *reinterpret_cast<const float2*>(r1 + 2 * tig + 8);
            split2(x0.x, x0.y, ahi[mt][0], alo[mt][0]);
            split2(x1.x, x1.y, ahi[mt][1], alo[mt][1]);
            split2(x2.x, x2.y, ahi[mt][2], alo[mt][2]);
            split2(x3.x, x3.y, ahi[mt][3], alo[mt][3]);
        }

#pragma unroll
        for (int mat = 0; mat < 2; mat++) {
#pragma unroll
            for (int nt = 0; nt < 4; nt++) {
                int col = mat * 64 + warp_n * 32 + nt * 8 + gid;
                uint32_t bh0 = bh[tig * BPAD2 + col];
                uint32_t bh1 = bh[(tig + 4) * BPAD2 + col];
                uint32_t bl0 = bl[tig * BPAD2 + col];
                uint32_t bl1 = bl[(tig + 4) * BPAD2 + col];
#pragma unroll
                for (int mt = 0; mt < 2; mt++) {
                    float* d = acc[mat][mt][nt];
                    mma_f16(d, ahi[mt][0], ahi[mt][1], ahi[mt][2], ahi[mt][3], bh0, bh1);
                    mma_f16(d, ahi[mt][0], ahi[mt][1], ahi[mt][2], ahi[mt][3], bl0, bl1);
                    mma_f16(d, alo[mt][0], alo[mt][1], alo[mt][2], alo[mt][3], bh0, bh1);
                }
            }
        }
        __syncthreads();
    }

    // ---- epilogue: bias + relu + att + norms -> fp16 messages ----
#pragma unroll
    for (int nt = 0; nt < 4; nt++) {
        int cl = warp_n * 32 + nt * 8 + tig * 2;
        int gc = col_half + cl;
        float bm0 = bm[gc], bm1 = bm[gc + 1];
        float bv0 = bv[gc], bv1 = bv[gc + 1];
#pragma unroll
        for (int mt = 0; mt < 2; mt++) {
#pragma unroll
            for (int half = 0; half < 2; half++) {
                int gm = bm_base + warp_m * 32 + mt * 16 + gid + half * 8;
                float n1 = g_norm1[gm];
                float n2 = g_norm2[gm];
                float mean0 = fmaxf(acc[0][mt][nt][half * 2 + 0] + bm0, 0.f);
                float mean1 = fmaxf(acc[0][mt][nt][half * 2 + 1] + bm1, 0.f);
                float var0  = fmaxf(acc[1][mt][nt][half * 2 + 0] + bv0, 0.f);
                float var1  = fmaxf(acc[1][mt][nt][half * 2 + 1] + bv1, 0.f);
                float att0 = expf(-var0), att1 = expf(-var1);
                float2 om = make_float2(mean0 * att0 * n1, mean1 * att1 * n1);
                float2 ov = make_float2(var0 * att0 * att0 * n2, var1 * att1 * att1 * n2);
                *reinterpret_cast<__half2*>(Cm + (size_t)gm * HID + gc) = __float22half2_rn(om);
                *reinterpret_cast<__half2*>(Cv + (size_t)gm * HID + gc) = __float22half2_rn(ov);
            }
        }
    }
}

// ================= layer-2: dual-A (fp16) dual GEMM, 2-term, pre-split B =================
__global__ void __launch_bounds__(256)
k_l2_f16(const __half* __restrict__ Am, const __half* __restrict__ Av,   // [M_PAD][128] fp16
         const float* __restrict__ bm, const float* __restrict__ bv,
         __half* __restrict__ Cm, __half* __restrict__ Cv) {
    __shared__ __half   As[2][2][128 * A2PAD];   // [stage][matrix]
    __shared__ uint32_t Bh[2][8 * BPAD2];
    __shared__ uint32_t Bl[2][8 * BPAD2];

    const int tid = threadIdx.x;
    const int lane = tid & 31;
    const int wid = tid >> 5;
    const int warp_m = wid & 3;
    const int warp_n = wid >> 2;
    const int gid = lane >> 2;
    const int tig = lane & 3;
    const int bm_base = blockIdx.x * 128;

    float acc[2][2][4][4];
#pragma unroll
    for (int a = 0; a < 2; a++)
#pragma unroll
        for (int b = 0; b < 2; b++)
#pragma unroll
            for (int c = 0; c < 4; c++)
#pragma unroll
                for (int d = 0; d < 4; d++) acc[a][b][c][d] = 0.f;

    uint32_t asb[2][2], bhb[2], blb[2];
#pragma unroll
    for (int s = 0; s < 2; s++) {
        asb[s][0] = (uint32_t)__cvta_generic_to_shared(&As[s][0][0]);
        asb[s][1] = (uint32_t)__cvta_generic_to_shared(&As[s][1][0]);
        bhb[s] = (uint32_t)__cvta_generic_to_shared(&Bh[s][0]);
        blb[s] = (uint32_t)__cvta_generic_to_shared(&Bl[s][0]);
    }

    auto issue = [&](int stage, int k0) {
        int kk0 = k0 >> 1;
        // A tiles: 2 mats x 128 rows x 2 chunks (16 halfs/row) = 512 x 16B
#pragma unroll
        for (int c = tid; c < 512; c += 256) {
            int mat = c >> 8;
            int r = (c >> 1) & 127;
            int q = c & 1;
            const __half* srca = (mat ? Av : Am) + (size_t)(bm_base + r) * HID + k0 + q * 8;
            cp16(asb[stage][mat] + (uint32_t)(r * A2PAD + q * 8) * 2, srca, 16);
        }
        // B tiles (hi+lo): 512 x 16B
#pragma unroll
        for (int c = tid; c < 512; c += 256) {
            int arr = c >> 8;
            int rem = c & 255;
            int mat = rem >> 7;
            int pr = (rem >> 4) & 7;
            int q = rem & 15;
            const __half2* srcb = (arr ? g_w2lo : g_w2hi)
                + ((mat * 64 + kk0 + pr) * 64 + q * 4);
            uint32_t dstb = (arr ? blb[stage] : bhb[stage])
                + (uint32_t)(pr * BPAD2 + mat * 64 + q * 4) * 4;
            cp16(dstb, srcb, 16);
        }
        cp_commit();
    };

    issue(0, 0);

    const int NITER = HID / 16;   // 8
    for (int it = 0; it < NITER; it++) {
        int stage = it & 1;
        if (it + 1 < NITER) {
            issue(stage ^ 1, (it + 1) * 16);
            cp_wait<1>();
        } else {
            cp_wait<0>();
        }
        __syncthreads();

        const uint32_t* bh = Bh[stage];
        const uint32_t* bl = Bl[stage];

#pragma unroll
        for (int mat = 0; mat < 2; mat++) {
            const __half* as = As[stage][mat];
            uint32_t a[2][4];
#pragma unroll
            for (int mt = 0; mt < 2; mt++) {
                int rb = warp_m * 32 + mt * 16;
                const __half* r0 = as + (rb + gid) * A2PAD;
                const __half* r1 = as + (rb + gid + 8) * A2PAD;
                a[mt][0] = *reinterpret_cast<const uint32_t*>(r0 + 2 * tig);
                a[mt][1] = *reinterpret_cast<const uint32_t*>(r1 + 2 * tig);
                a[mt][2] = *reinterpret_cast<const uint32_t*>(r0 + 2 * tig + 8);
                a[mt][3] = *reinterpret_cast<const uint32_t*>(r1 + 2 * tig + 8);
            }
#pragma unroll
            for (int nt = 0; nt < 4; nt++) {
                int col = mat * 64 + warp_n * 32 + nt * 8 + gid;
                uint32_t bh0 = bh[tig * BPAD2 + col];
                uint32_t bh1 = bh[(tig + 4) * BPAD2 + col];
                uint32_t bl0 = bl[tig * BPAD2 + col];
                uint32_t bl1 = bl[(tig + 4) * BPAD2 + col];
#pragma unroll
                for (int mt = 0; mt < 2; mt++) {
                    float* d = acc[mat][mt][nt];
                    mma_f16(d, a[mt][0], a[mt][1], a[mt][2], a[mt][3], bh0, bh1);
                    mma_f16(d, a[mt][0], a[mt][1], a[mt][2], a[mt][3], bl0, bl1);
                }
            }
        }
        __syncthreads();
    }

    // ---- epilogue -> fp16 messages [M_PAD][64] ----
#pragma unroll
    for (int nt = 0; nt < 4; nt++) {
        int gc = warp_n * 32 + nt * 8 + tig * 2;
        float bm0 = bm[gc], bm1 = bm[gc + 1];
        float bv0 = bv[gc], bv1 = bv[gc + 1];
#pragma unroll
        for (int mt = 0; mt < 2; mt++) {
#pragma unroll
            for (int half = 0; half < 2; half++) {
                int gm = bm_base + warp_m * 32 + mt * 16 + gid + half * 8;
                float n1 = g_norm1[gm];
                float n2 = g_norm2[gm];
                float mean0 = fmaxf(acc[0][mt][nt][half * 2 + 0] + bm0, 0.f);
                float mean1 = fmaxf(acc[0][mt][nt][half * 2 + 1] + bm1, 0.f);
                float var0  = fmaxf(acc[1][mt][nt][half * 2 + 0] + bv0, 0.f);
                float var1  = fmaxf(acc[1][mt][nt][half * 2 + 1] + bv1, 0.f);
                float att0 = expf(-var0), att1 = expf(-var1);
                float2 om = make_float2(mean0 * att0 * n1, mean1 * att1 * n1);
                float2 ov = make_float2(var0 * att0 * att0 * n2, var1 * att1 * att1 * n2);
                *reinterpret_cast<__half2*>(Cm + (size_t)gm * OUTF + gc) = __float22half2_rn(om);
                *reinterpret_cast<__half2*>(Cv + (size_t)gm * OUTF + gc) = __float22half2_rn(ov);
            }
        }
    }
}

// ---------------- aggregation: warp per node, CSR pure-read reduce (fp16 in/out) ----------------
__global__ void k_agg1(const __half* __restrict__ msrc, const __half* __restrict__ vsrc,
                       __half* __restrict__ mdst, __half* __restrict__ vdst, int n) {
    int warp = (blockIdx.x * blockDim.x + threadIdx.x) >> 5;
    int lane = threadIdx.x & 31;
    if (warp >= n) return;
    const int D = 128;
    int start = g_offs[warp], end = g_offs[warp + 1];

    float am[4] = {0.f, 0.f, 0.f, 0.f};
    float av[4] = {0.f, 0.f, 0.f, 0.f};
    for (int e = start; e < end; e++) {
        int s = g_csr[e];
        uint2 ar = __ldg(reinterpret_cast<const uint2*>(msrc + (size_t)s * D + lane * 4));
        uint2 br = __ldg(reinterpret_cast<const uint2*>(vsrc + (size_t)s * D + lane * 4));
        float2 a0 = __half22float2(*reinterpret_cast<__half2*>(&ar.x));
        float2 a1 = __half22float2(*reinterpret_cast<__half2*>(&ar.y));
        float2 b0 = __half22float2(*reinterpret_cast<__half2*>(&br.x));
        float2 b1 = __half22float2(*reinterpret_cast<__half2*>(&br.y));
        am[0] += a0.x; am[1] += a0.y; am[2] += a1.x; am[3] += a1.y;
        av[0] += b0.x; av[1] += b0.y; av[2] += b1.x; av[3] += b1.y;
    }
    float n1 = g_norm1[warp], n2 = g_norm2[warp];
#pragma unroll
    for (int j = 0; j < 4; j++) {
        am[j] = fmaxf(am[j] * n1, 0.f);
        av[j] = fmaxf(av[j] * n2, 0.f);
    }
    __half2 m01 = __floats2half2_rn(am[0], am[1]);
    __half2 m23 = __floats2half2_rn(am[2], am[3]);
    __half2 v01 = __floats2half2_rn(av[0], av[1]);
    __half2 v23 = __floats2half2_rn(av[2], av[3]);
    uint2 mo, vo;
    mo.x = *reinterpret_cast<uint32_t*>(&m01); mo.y = *reinterpret_cast<uint32_t*>(&m23);
    vo.x = *reinterpret_cast<uint32_t*>(&v01); vo.y = *reinterpret_cast<uint32_t*>(&v23);
    *reinterpret_cast<uint2*>(mdst + (size_t)warp * D + lane * 4) = mo;
    *reinterpret_cast<uint2*>(vdst + (size_t)warp * D + lane * 4) = vo;
}

// ---------------- threefry-2x32-20 (KAT-verified) ----------------
__device__ __forceinline__ uint32_t rotl32(uint32_t x, int d) {
    return (x << d) | (x >> (32 - d));
}

__device__ __forceinline__ void threefry2x32(uint32_t k0, uint32_t k1,
                                             uint32_t& x0, uint32_t& x1) {
    uint32_t s0 = k0, s1 = k1, s2 = k0 ^ k1 ^ 0x1BD11BDAu;
    x0 += s0; x1 += s1;
#define TFR(r) { x0 += x1; x1 = rotl32(x1, r); x1 ^= x0; }
    TFR(13) TFR(15) TFR(26) TFR(6)   x0 += s1; x1 += s2 + 1u;
    TFR(17) TFR(29) TFR(16) TFR(24)  x0 += s2; x1 += s0 + 2u;
    TFR(13) TFR(15) TFR(26) TFR(6)   x0 += s0; x1 += s1 + 3u;
    TFR(17) TFR(29) TFR(16) TFR(24)  x0 += s1; x1 += s2 + 4u;
    TFR(13) TFR(15) TFR(26) TFR(6)   x0 += s2; x1 += s0 + 5u;
#undef TFR
}

__device__ __forceinline__ float jax_normal_elem(uint32_t idx) {
    uint32_t x0 = 0u, x1 = idx;
    threefry2x32(0u, 42u, x0, x1);
    uint32_t bits = x0 ^ x1;
    uint32_t fb = (bits >> 9) | 0x3F800000u;
    float u01 = __uint_as_float(fb) - 1.0f;
    const float lo = -0.99999994f;
    float u = fmaxf(u01 * 2.0f + lo, lo);
    return 1.41421356f * erfinvf(u);
}

// layer-2 aggregation fused with reparameterization (fp16 msgs): warp per node, D=64
__global__ void k_agg2_final(const __half* __restrict__ msrc, const __half* __restrict__ vsrc,
                             float* __restrict__ out, int n) {
    int warp = (blockIdx.x * blockDim.x + threadIdx.x) >> 5;
    int lane = threadIdx.x & 31;
    if (warp >= n) return;
    const int D = 64;
    int start = g_offs[warp], end = g_offs[warp + 1];

    float am0 = 0.f, am1 = 0.f, av0 = 0.f, av1 = 0.f;
    for (int e = start; e < end; e++) {
        int s = g_csr[e];
        __half2 ah = __ldg(reinterpret_cast<const __half2*>(msrc + (size_t)s * D + lane * 2));
        __half2 bh = __ldg(reinterpret_cast<const __half2*>(vsrc + (size_t)s * D + lane * 2));
        float2 a = __half22float2(ah);
        float2 b = __half22float2(bh);
        am0 += a.x; am1 += a.y;
        av0 += b.x; av1 += b.y;
    }
    float n1 = g_norm1[warp], n2 = g_norm2[warp];
    float m0 = am0 * n1, m1 = am1 * n1;
    float v0 = av0 * n2, v1 = av1 * n2;

    uint32_t t0 = (uint32_t)(warp * D + lane * 2);
    float e0 = jax_normal_elem(t0);
    float e1 = jax_normal_elem(t0 + 1u);
    float2 o;
    o.x = e0 * sqrtf(v0 + 1e-8f) + m0;
    o.y = e1 * sqrtf(v1 + 1e-8f) + m1;
    *reinterpret_cast<float2*>(out + (size_t)warp * D + lane * 2) = o;
}

// ---------------- launch ----------------
extern "C" void kernel_launch(void* const* d_in, const int* in_sizes, int n_in,
                              void* d_out, int out_size) {
    const float* x       = (const float*)d_in[0];
    const int*   src     = (const int*)d_in[1];
    const int*   dst     = (const int*)d_in[2];
    const float* w_mean1 = (const float*)d_in[3];
    const float* w_var1  = (const float*)d_in[4];
    const float* b_mean1 = (const float*)d_in[5];
    const float* b_var1  = (const float*)d_in[6];
    const float* w_mean2 = (const float*)d_in[7];
    const float* w_var2  = (const float*)d_in[8];
    const float* b_mean2 = (const float*)d_in[9];
    const float* b_var2  = (const float*)d_in[10];
    float* out = (float*)d_out;

    const int N = in_sizes[0] / IN_F;   // 100000
    const int E = in_sizes[1];          // 1600000

    __half* bufA = nullptr; __half* bufB = nullptr;
    __half* aggM = nullptr; __half* aggV = nullptr;
    cudaGetSymbolAddress((void**)&bufA, g_bufA);
    cudaGetSymbolAddress((void**)&bufB, g_bufB);
    cudaGetSymbolAddress((void**)&aggM, g_aggM);
    cudaGetSymbolAddress((void**)&aggV, g_aggV);

    const int T = 256;
    const int NB = (N + 1023) / 1024;

    // weight pre-split (independent of graph work)
    k_cvtw<<<(2 * 128 * 128 + 2 * 64 * 64 + T - 1) / T, T>>>(w_mean1, w_var1, w_mean2, w_var2);

    // degrees, norms, CSR
    k_zero<<<(N + T - 1) / T, T>>>(N);
    k_count<<<(E + T - 1) / T, T>>>(dst, E);
    k_norm<<<(N + T - 1) / T, T>>>(N);
    k_scan1<<<NB, 1024>>>(N);
    k_scan2<<<1, 128>>>(NB, N);
    k_scan3<<<NB, 1024>>>(N);
    k_fill<<<(E + T - 1) / T, T>>>(src, dst, E);

    // ---- layer 1: tensor-core dual GEMM (pre-split B) + fp16 msg epilogue ----
    {
        dim3 grid((N + 127) / 128, 2);
        k_l1_f16<<<grid, 256>>>(x, b_mean1, b_var1, bufA, bufB, N);
    }
    {
        int blocks = (N * 32 + T - 1) / T;   // warp per node
        k_agg1<<<blocks, T>>>(bufA, bufB, aggM, aggV, N);
    }

    // ---- layer 2: tensor-core dual-A GEMM (fp16 A, 2-term) + fp16 msg epilogue ----
    {
        int blocks = (N + 127) / 128;   // 782, covers M_PAD exactly
        k_l2_f16<<<blocks, 256>>>(aggM, aggV, b_mean2, b_var2, bufA, bufB);
    }
    // ---- layer-2 aggregation fused with threefry reparameterization ----
    {
        int blocks = (N * 32 + T - 1) / T;
        k_agg2_final<<<blocks, T>>>(bufA, bufB, out, N);
    }
}

// round 10
// speedup vs baseline: 2.6102x; 1.0340x over previous
#include <cuda_runtime.h>
#include <cuda_fp16.h>
#include <stdint.h>
#include <math.h>

#define NODES_MAX 100000
#define M_PAD     100096   // 782 * 128
#define EDGES_MAX 1600000
#define IN_F 256
#define HID 128
#define OUTF 64

// ---------------- scratch (static __device__, no allocs) ----------------
__device__ __half  g_bufA[(size_t)M_PAD * HID];   // messages m (fp16)
__device__ __half  g_bufB[(size_t)M_PAD * HID];   // messages v (fp16)
__device__ __half  g_aggM[(size_t)M_PAD * HID];   // aggregated mean (fp16)
__device__ __half  g_aggV[(size_t)M_PAD * HID];
__device__ float   g_norm1[M_PAD];
__device__ float   g_norm2[M_PAD];
__device__ int     g_deg[NODES_MAX];
__device__ int     g_cursor[NODES_MAX];
__device__ int     g_offs[NODES_MAX + 1];
__device__ int     g_csr[EDGES_MAX];
__device__ int     g_bsum[128];
__device__ int     g_boff[128];
// pre-split weights, packed as k-pair half2: [mat][K/2][N]
__device__ __half2 g_w1hi[2 * 128 * 128];
__device__ __half2 g_w1lo[2 * 128 * 128];
__device__ __half2 g_w2hi[2 * 64 * 64];
__device__ __half2 g_w2lo[2 * 64 * 64];

// ---------------- init: zero counters + weight pre-split (fused) ----------------
__global__ void k_init(const float* __restrict__ Wm1, const float* __restrict__ Wv1,
                       const float* __restrict__ Wm2, const float* __restrict__ Wv2, int n) {
    int i = blockIdx.x * blockDim.x + threadIdx.x;
    if (i < n) { g_deg[i] = 0; g_cursor[i] = 0; }
    if (i < 2 * 128 * 128) {   // W1: K=256 -> 128 k-pairs, N=128
        int mat = i >> 14;
        int rem = i & 16383;
        int kk = rem >> 7;
        int nn = rem & 127;
        const float* W = mat ? Wv1 : Wm1;
        float a = W[(2 * kk) * HID + nn];
        float b = W[(2 * kk + 1) * HID + nn];
        __half2 h = __floats2half2_rn(a, b);
        float2 hf = __half22float2(h);
        g_w1hi[i] = h;
        g_w1lo[i] = __floats2half2_rn(a - hf.x, b - hf.y);
    }
    if (i < 2 * 64 * 64) {     // W2: K=128 -> 64 k-pairs, N=64
        int mat = i >> 12;
        int rem = i & 4095;
        int kk = rem >> 6;
        int nn = rem & 63;
        const float* W = mat ? Wv2 : Wm2;
        float a = W[(2 * kk) * OUTF + nn];
        float b = W[(2 * kk + 1) * OUTF + nn];
        __half2 h = __floats2half2_rn(a, b);
        float2 hf = __half22float2(h);
        g_w2hi[i] = h;
        g_w2lo[i] = __floats2half2_rn(a - hf.x, b - hf.y);
    }
}

__global__ void k_count(const int* __restrict__ dst, int E) {
    int e = blockIdx.x * blockDim.x + threadIdx.x;
    if (e < E) atomicAdd(&g_deg[dst[e]], 1);
}

// ---------------- scan phase 1 (+ fused norm computation) ----------------
__global__ void k_scan1(int n) {
    __shared__ int sm[1024];
    int t = threadIdx.x;
    int i = blockIdx.x * 1024 + t;
    int v = (i < n) ? g_deg[i] : 0;
    if (i < n) {
        float d = fmaxf((float)v, 1.0f);
        float n1 = 1.0f / sqrtf(d);
        g_norm1[i] = n1;
        g_norm2[i] = n1 * n1;
    }
    sm[t] = v;
    __syncthreads();
#pragma unroll
    for (int d = 1; d < 1024; d <<= 1) {
        int u = (t >= d) ? sm[t - d] : 0;
        __syncthreads();
        sm[t] += u;
        __syncthreads();
    }
    if (i < n) g_offs[i] = sm[t] - v;
    if (t == 1023) g_bsum[blockIdx.x] = sm[1023];
}

__global__ void k_scan2(int nb, int n) {
    __shared__ int sm[128];
    int t = threadIdx.x;
    int v = (t < nb) ? g_bsum[t] : 0;
    sm[t] = v;
    __syncthreads();
#pragma unroll
    for (int d = 1; d < 128; d <<= 1) {
        int u = (t >= d) ? sm[t - d] : 0;
        __syncthreads();
        sm[t] += u;
        __syncthreads();
    }
    if (t < nb) g_boff[t] = sm[t] - v;
    if (t == 127) g_offs[n] = sm[127];
}

__global__ void k_scan3(int n) {
    int i = blockIdx.x * 1024 + threadIdx.x;
    if (i < n) g_offs[i] += g_boff[blockIdx.x];
}

__global__ void k_fill(const int* __restrict__ src, const int* __restrict__ dst, int E) {
    int e = blockIdx.x * blockDim.x + threadIdx.x;
    if (e < E) {
        int d = dst[e];
        int p = atomicAdd(&g_cursor[d], 1);
        g_csr[g_offs[d] + p] = src[e];
    }
}

// ================= tensor-core helpers =================
__device__ __forceinline__ void mma_f16(float* d, uint32_t a0, uint32_t a1,
                                        uint32_t a2, uint32_t a3,
                                        uint32_t b0, uint32_t b1) {
    asm volatile(
        "mma.sync.aligned.m16n8k16.row.col.f32.f16.f16.f32 "
        "{%0,%1,%2,%3},{%4,%5,%6,%7},{%8,%9},{%0,%1,%2,%3};"
        : "+f"(d[0]), "+f"(d[1]), "+f"(d[2]), "+f"(d[3])
        : "r"(a0), "r"(a1), "r"(a2), "r"(a3), "r"(b0), "r"(b1));
}

__device__ __forceinline__ void cp16(uint32_t dst, const void* src, int sz) {
    asm volatile("cp.async.cg.shared.global [%0], [%1], 16, %2;"
                 :: "r"(dst), "l"(src), "r"(sz));
}
__device__ __forceinline__ void cp_commit() {
    asm volatile("cp.async.commit_group;");
}
template <int N> __device__ __forceinline__ void cp_wait() {
    asm volatile("cp.async.wait_group %0;" :: "n"(N));
}

#define APAD 20     // floats per A smem row (16 + 4)  [L1 fp32 A]
#define BPAD2 136   // half2 words per B pair-row (128 cols + 8)
#define A2PAD 24    // halfs per A smem row (16 + 8)   [L2 fp16 A]

// ================= layer-1: shared-A dual GEMM, 2-term (A fp16-rounded), pre-split B =================
__global__ void __launch_bounds__(256)
k_l1_f16(const float* __restrict__ X,
         const float* __restrict__ bm, const float* __restrict__ bv,
         __half* __restrict__ Cm, __half* __restrict__ Cv, int M) {
    __shared__ float    As[2][128 * APAD];
    __shared__ uint32_t Bh[2][8 * BPAD2];
    __shared__ uint32_t Bl[2][8 * BPAD2];

    const int tid = threadIdx.x;
    const int lane = tid & 31;
    const int wid = tid >> 5;
    const int warp_m = wid & 3;
    const int warp_n = wid >> 2;
    const int gid = lane >> 2;
    const int tig = lane & 3;
    const int bm_base = blockIdx.x * 128;
    const int col_half = blockIdx.y * 64;

    float acc[2][2][4][4];
#pragma unroll
    for (int a = 0; a < 2; a++)
#pragma unroll
        for (int b = 0; b < 2; b++)
#pragma unroll
            for (int c = 0; c < 4; c++)
#pragma unroll
                for (int d = 0; d < 4; d++) acc[a][b][c][d] = 0.f;

    uint32_t asb[2], bhb[2], blb[2];
#pragma unroll
    for (int s = 0; s < 2; s++) {
        asb[s] = (uint32_t)__cvta_generic_to_shared(&As[s][0]);
        bhb[s] = (uint32_t)__cvta_generic_to_shared(&Bh[s][0]);
        blb[s] = (uint32_t)__cvta_generic_to_shared(&Bl[s][0]);
    }

    auto issue = [&](int stage, int k0) {
        int kk0 = k0 >> 1;
#pragma unroll
        for (int c = tid; c < 512; c += 256) {
            int r = c >> 2, kq = c & 3;
            int gm = bm_base + r;
            int ok = (gm < M) ? 16 : 0;
            const float* srca = X + (size_t)min(gm, M - 1) * IN_F + k0 + kq * 4;
            cp16(asb[stage] + (uint32_t)(r * APAD + kq * 4) * 4, srca, ok);
        }
#pragma unroll
        for (int c = tid; c < 512; c += 256) {
            int arr = c >> 8;
            int rem = c & 255;
            int mat = rem >> 7;
            int pr = (rem >> 4) & 7;
            int q = rem & 15;
            const __half2* srcb = (arr ? g_w1lo : g_w1hi)
                + ((mat * 128 + kk0 + pr) * 128 + col_half + q * 4);
            uint32_t dstb = (arr ? blb[stage] : bhb[stage])
                + (uint32_t)(pr * BPAD2 + mat * 64 + q * 4) * 4;
            cp16(dstb, srcb, 16);
        }
        cp_commit();
    };

    issue(0, 0);

    const int NITER = IN_F / 16;   // 16
    for (int it = 0; it < NITER; it++) {
        int stage = it & 1;
        if (it + 1 < NITER) {
            issue(stage ^ 1, (it + 1) * 16);
            cp_wait<1>();
        } else {
            cp_wait<0>();
        }
        __syncthreads();

        const float* as = As[stage];
        const uint32_t* bh = Bh[stage];
        const uint32_t* bl = Bl[stage];

        // A fragments: fp32 -> fp16 (hi only), shared across both matrices
        uint32_t ahi[2][4];
#pragma unroll
        for (int mt = 0; mt < 2; mt++) {
            int rb = warp_m * 32 + mt * 16;
            const float* r0 = as + (rb + gid) * APAD;
            const float* r1 = as + (rb + gid + 8) * APAD;
            float2 x0 = *reinterpret_cast<const float2*>(r0 + 2 * tig);
            float2 x1 = *reinterpret_cast<const float2*>(r1 + 2 * tig);
            float2 x2 = *reinterpret_cast<const float2*>(r0 + 2 * tig + 8);
            float2 x3 = *reinterpret_cast<const float2*>(r1 + 2 * tig + 8);
            __half2 h;
            h = __floats2half2_rn(x0.x, x0.y); ahi[mt][0] = *reinterpret_cast<uint32_t*>(&h);
            h = __floats2half2_rn(x1.x, x1.y); ahi[mt][1] = *reinterpret_cast<uint32_t*>(&h);
            h = __floats2half2_rn(x2.x, x2.y); ahi[mt][2] = *reinterpret_cast<uint32_t*>(&h);
            h = __floats2half2_rn(x3.x, x3.y); ahi[mt][3] = *reinterpret_cast<uint32_t*>(&h);
        }

#pragma unroll
        for (int mat = 0; mat < 2; mat++) {
#pragma unroll
            for (int nt = 0; nt < 4; nt++) {
                int col = mat * 64 + warp_n * 32 + nt * 8 + gid;
                uint32_t bh0 = bh[tig * BPAD2 + col];
                uint32_t bh1 = bh[(tig + 4) * BPAD2 + col];
                uint32_t bl0 = bl[tig * BPAD2 + col];
                uint32_t bl1 = bl[(tig + 4) * BPAD2 + col];
#pragma unroll
                for (int mt = 0; mt < 2; mt++) {
                    float* d = acc[mat][mt][nt];
                    mma_f16(d, ahi[mt][0], ahi[mt][1], ahi[mt][2], ahi[mt][3], bh0, bh1);
                    mma_f16(d, ahi[mt][0], ahi[mt][1], ahi[mt][2], ahi[mt][3], bl0, bl1);
                }
            }
        }
        __syncthreads();
    }

    // ---- epilogue: bias + relu + att + norms -> fp16 messages ----
#pragma unroll
    for (int nt = 0; nt < 4; nt++) {
        int cl = warp_n * 32 + nt * 8 + tig * 2;
        int gc = col_half + cl;
        float bm0 = bm[gc], bm1 = bm[gc + 1];
        float bv0 = bv[gc], bv1 = bv[gc + 1];
#pragma unroll
        for (int mt = 0; mt < 2; mt++) {
#pragma unroll
            for (int half = 0; half < 2; half++) {
                int gm = bm_base + warp_m * 32 + mt * 16 + gid + half * 8;
                float n1 = g_norm1[gm];
                float n2 = g_norm2[gm];
                float mean0 = fmaxf(acc[0][mt][nt][half * 2 + 0] + bm0, 0.f);
                float mean1 = fmaxf(acc[0][mt][nt][half * 2 + 1] + bm1, 0.f);
                float var0  = fmaxf(acc[1][mt][nt][half * 2 + 0] + bv0, 0.f);
                float var1  = fmaxf(acc[1][mt][nt][half * 2 + 1] + bv1, 0.f);
                float att0 = expf(-var0), att1 = expf(-var1);
                float2 om = make_float2(mean0 * att0 * n1, mean1 * att1 * n1);
                float2 ov = make_float2(var0 * att0 * att0 * n2, var1 * att1 * att1 * n2);
                *reinterpret_cast<__half2*>(Cm + (size_t)gm * HID + gc) = __float22half2_rn(om);
                *reinterpret_cast<__half2*>(Cv + (size_t)gm * HID + gc) = __float22half2_rn(ov);
            }
        }
    }
}

// ================= layer-2: dual-A (fp16) dual GEMM, 2-term, pre-split B =================
__global__ void __launch_bounds__(256)
k_l2_f16(const __half* __restrict__ Am, const __half* __restrict__ Av,   // [M_PAD][128] fp16
         const float* __restrict__ bm, const float* __restrict__ bv,
         __half* __restrict__ Cm, __half* __restrict__ Cv) {
    __shared__ __half   As[2][2][128 * A2PAD];   // [stage][matrix]
    __shared__ uint32_t Bh[2][8 * BPAD2];
    __shared__ uint32_t Bl[2][8 * BPAD2];

    const int tid = threadIdx.x;
    const int lane = tid & 31;
    const int wid = tid >> 5;
    const int warp_m = wid & 3;
    const int warp_n = wid >> 2;
    const int gid = lane >> 2;
    const int tig = lane & 3;
    const int bm_base = blockIdx.x * 128;

    float acc[2][2][4][4];
#pragma unroll
    for (int a = 0; a < 2; a++)
#pragma unroll
        for (int b = 0; b < 2; b++)
#pragma unroll
            for (int c = 0; c < 4; c++)
#pragma unroll
                for (int d = 0; d < 4; d++) acc[a][b][c][d] = 0.f;

    uint32_t asb[2][2], bhb[2], blb[2];
#pragma unroll
    for (int s = 0; s < 2; s++) {
        asb[s][0] = (uint32_t)__cvta_generic_to_shared(&As[s][0][0]);
        asb[s][1] = (uint32_t)__cvta_generic_to_shared(&As[s][1][0]);
        bhb[s] = (uint32_t)__cvta_generic_to_shared(&Bh[s][0]);
        blb[s] = (uint32_t)__cvta_generic_to_shared(&Bl[s][0]);
    }

    auto issue = [&](int stage, int k0) {
        int kk0 = k0 >> 1;
#pragma unroll
        for (int c = tid; c < 512; c += 256) {
            int mat = c >> 8;
            int r = (c >> 1) & 127;
            int q = c & 1;
            const __half* srca = (mat ? Av : Am) + (size_t)(bm_base + r) * HID + k0 + q * 8;
            cp16(asb[stage][mat] + (uint32_t)(r * A2PAD + q * 8) * 2, srca, 16);
        }
#pragma unroll
        for (int c = tid; c < 512; c += 256) {
            int arr = c >> 8;
            int rem = c & 255;
            int mat = rem >> 7;
            int pr = (rem >> 4) & 7;
            int q = rem & 15;
            const __half2* srcb = (arr ? g_w2lo : g_w2hi)
                + ((mat * 64 + kk0 + pr) * 64 + q * 4);
            uint32_t dstb = (arr ? blb[stage] : bhb[stage])
                + (uint32_t)(pr * BPAD2 + mat * 64 + q * 4) * 4;
            cp16(dstb, srcb, 16);
        }
        cp_commit();
    };

    issue(0, 0);

    const int NITER = HID / 16;   // 8
    for (int it = 0; it < NITER; it++) {
        int stage = it & 1;
        if (it + 1 < NITER) {
            issue(stage ^ 1, (it + 1) * 16);
            cp_wait<1>();
        } else {
            cp_wait<0>();
        }
        __syncthreads();

        const uint32_t* bh = Bh[stage];
        const uint32_t* bl = Bl[stage];

#pragma unroll
        for (int mat = 0; mat < 2; mat++) {
            const __half* as = As[stage][mat];
            uint32_t a[2][4];
#pragma unroll
            for (int mt = 0; mt < 2; mt++) {
                int rb = warp_m * 32 + mt * 16;
                const __half* r0 = as + (rb + gid) * A2PAD;
                const __half* r1 = as + (rb + gid + 8) * A2PAD;
                a[mt][0] = *reinterpret_cast<const uint32_t*>(r0 + 2 * tig);
                a[mt][1] = *reinterpret_cast<const uint32_t*>(r1 + 2 * tig);
                a[mt][2] = *reinterpret_cast<const uint32_t*>(r0 + 2 * tig + 8);
                a[mt][3] = *reinterpret_cast<const uint32_t*>(r1 + 2 * tig + 8);
            }
#pragma unroll
            for (int nt = 0; nt < 4; nt++) {
                int col = mat * 64 + warp_n * 32 + nt * 8 + gid;
                uint32_t bh0 = bh[tig * BPAD2 + col];
                uint32_t bh1 = bh[(tig + 4) * BPAD2 + col];
                uint32_t bl0 = bl[tig * BPAD2 + col];
                uint32_t bl1 = bl[(tig + 4) * BPAD2 + col];
#pragma unroll
                for (int mt = 0; mt < 2; mt++) {
                    float* d = acc[mat][mt][nt];
                    mma_f16(d, a[mt][0], a[mt][1], a[mt][2], a[mt][3], bh0, bh1);
                    mma_f16(d, a[mt][0], a[mt][1], a[mt][2], a[mt][3], bl0, bl1);
                }
            }
        }
        __syncthreads();
    }

    // ---- epilogue -> fp16 messages [M_PAD][64] ----
#pragma unroll
    for (int nt = 0; nt < 4; nt++) {
        int gc = warp_n * 32 + nt * 8 + tig * 2;
        float bm0 = bm[gc], bm1 = bm[gc + 1];
        float bv0 = bv[gc], bv1 = bv[gc + 1];
#pragma unroll
        for (int mt = 0; mt < 2; mt++) {
#pragma unroll
            for (int half = 0; half < 2; half++) {
                int gm = bm_base + warp_m * 32 + mt * 16 + gid + half * 8;
                float n1 = g_norm1[gm];
                float n2 = g_norm2[gm];
                float mean0 = fmaxf(acc[0][mt][nt][half * 2 + 0] + bm0, 0.f);
                float mean1 = fmaxf(acc[0][mt][nt][half * 2 + 1] + bm1, 0.f);
                float var0  = fmaxf(acc[1][mt][nt][half * 2 + 0] + bv0, 0.f);
                float var1  = fmaxf(acc[1][mt][nt][half * 2 + 1] + bv1, 0.f);
                float att0 = expf(-var0), att1 = expf(-var1);
                float2 om = make_float2(mean0 * att0 * n1, mean1 * att1 * n1);
                float2 ov = make_float2(var0 * att0 * att0 * n2, var1 * att1 * att1 * n2);
                *reinterpret_cast<__half2*>(Cm + (size_t)gm * OUTF + gc) = __float22half2_rn(om);
                *reinterpret_cast<__half2*>(Cv + (size_t)gm * OUTF + gc) = __float22half2_rn(ov);
            }
        }
    }
}

// ---------------- aggregation: warp per node, CSR pure-read reduce (fp16 in/out) ----------------
__global__ void k_agg1(const __half* __restrict__ msrc, const __half* __restrict__ vsrc,
                       __half* __restrict__ mdst, __half* __restrict__ vdst, int n) {
    int warp = (blockIdx.x * blockDim.x + threadIdx.x) >> 5;
    int lane = threadIdx.x & 31;
    if (warp >= n) return;
    const int D = 128;
    int start = g_offs[warp], end = g_offs[warp + 1];

    float am[4] = {0.f, 0.f, 0.f, 0.f};
    float av[4] = {0.f, 0.f, 0.f, 0.f};
    for (int e = start; e < end; e++) {
        int s = g_csr[e];
        uint2 ar = __ldg(reinterpret_cast<const uint2*>(msrc + (size_t)s * D + lane * 4));
        uint2 br = __ldg(reinterpret_cast<const uint2*>(vsrc + (size_t)s * D + lane * 4));
        float2 a0 = __half22float2(*reinterpret_cast<__half2*>(&ar.x));
        float2 a1 = __half22float2(*reinterpret_cast<__half2*>(&ar.y));
        float2 b0 = __half22float2(*reinterpret_cast<__half2*>(&br.x));
        float2 b1 = __half22float2(*reinterpret_cast<__half2*>(&br.y));
        am[0] += a0.x; am[1] += a0.y; am[2] += a1.x; am[3] += a1.y;
        av[0] += b0.x; av[1] += b0.y; av[2] += b1.x; av[3] += b1.y;
    }
    float n1 = g_norm1[warp], n2 = g_norm2[warp];
#pragma unroll
    for (int j = 0; j < 4; j++) {
        am[j] = fmaxf(am[j] * n1, 0.f);
        av[j] = fmaxf(av[j] * n2, 0.f);
    }
    __half2 m01 = __floats2half2_rn(am[0], am[1]);
    __half2 m23 = __floats2half2_rn(am[2], am[3]);
    __half2 v01 = __floats2half2_rn(av[0], av[1]);
    __half2 v23 = __floats2half2_rn(av[2], av[3]);
    uint2 mo, vo;
    mo.x = *reinterpret_cast<uint32_t*>(&m01); mo.y = *reinterpret_cast<uint32_t*>(&m23);
    vo.x = *reinterpret_cast<uint32_t*>(&v01); vo.y = *reinterpret_cast<uint32_t*>(&v23);
    *reinterpret_cast<uint2*>(mdst + (size_t)warp * D + lane * 4) = mo;
    *reinterpret_cast<uint2*>(vdst + (size_t)warp * D + lane * 4) = vo;
}

// ---------------- threefry-2x32-20 (KAT-verified) ----------------
__device__ __forceinline__ uint32_t rotl32(uint32_t x, int d) {
    return (x << d) | (x >> (32 - d));
}

__device__ __forceinline__ void threefry2x32(uint32_t k0, uint32_t k1,
                                             uint32_t& x0, uint32_t& x1) {
    uint32_t s0 = k0, s1 = k1, s2 = k0 ^ k1 ^ 0x1BD11BDAu;
    x0 += s0; x1 += s1;
#define TFR(r) { x0 += x1; x1 = rotl32(x1, r); x1 ^= x0; }
    TFR(13) TFR(15) TFR(26) TFR(6)   x0 += s1; x1 += s2 + 1u;
    TFR(17) TFR(29) TFR(16) TFR(24)  x0 += s2; x1 += s0 + 2u;
    TFR(13) TFR(15) TFR(26) TFR(6)   x0 += s0; x1 += s1 + 3u;
    TFR(17) TFR(29) TFR(16) TFR(24)  x0 += s1; x1 += s2 + 4u;
    TFR(13) TFR(15) TFR(26) TFR(6)   x0 += s2; x1 += s0 + 5u;
#undef TFR
}

__device__ __forceinline__ float jax_normal_elem(uint32_t idx) {
    uint32_t x0 = 0u, x1 = idx;
    threefry2x32(0u, 42u, x0, x1);
    uint32_t bits = x0 ^ x1;
    uint32_t fb = (bits >> 9) | 0x3F800000u;
    float u01 = __uint_as_float(fb) - 1.0f;
    const float lo = -0.99999994f;
    float u = fmaxf(u01 * 2.0f + lo, lo);
    return 1.41421356f * erfinvf(u);
}

// layer-2 aggregation fused with reparameterization (fp16 msgs): warp per node, D=64
__global__ void k_agg2_final(const __half* __restrict__ msrc, const __half* __restrict__ vsrc,
                             float* __restrict__ out, int n) {
    int warp = (blockIdx.x * blockDim.x + threadIdx.x) >> 5;
    int lane = threadIdx.x & 31;
    if (warp >= n) return;
    const int D = 64;
    int start = g_offs[warp], end = g_offs[warp + 1];

    float am0 = 0.f, am1 = 0.f, av0 = 0.f, av1 = 0.f;
    for (int e = start; e < end; e++) {
        int s = g_csr[e];
        __half2 ah = __ldg(reinterpret_cast<const __half2*>(msrc + (size_t)s * D + lane * 2));
        __half2 bh = __ldg(reinterpret_cast<const __half2*>(vsrc + (size_t)s * D + lane * 2));
        float2 a = __half22float2(ah);
        float2 b = __half22float2(bh);
        am0 += a.x; am1 += a.y;
        av0 += b.x; av1 += b.y;
    }
    float n1 = g_norm1[warp], n2 = g_norm2[warp];
    float m0 = am0 * n1, m1 = am1 * n1;
    float v0 = av0 * n2, v1 = av1 * n2;

    uint32_t t0 = (uint32_t)(warp * D + lane * 2);
    float e0 = jax_normal_elem(t0);
    float e1 = jax_normal_elem(t0 + 1u);
    float2 o;
    o.x = e0 * sqrtf(v0 + 1e-8f) + m0;
    o.y = e1 * sqrtf(v1 + 1e-8f) + m1;
    *reinterpret_cast<float2*>(out + (size_t)warp * D + lane * 2) = o;
}

// ---------------- launch ----------------
extern "C" void kernel_launch(void* const* d_in, const int* in_sizes, int n_in,
                              void* d_out, int out_size) {
    const float* x       = (const float*)d_in[0];
    const int*   src     = (const int*)d_in[1];
    const int*   dst     = (const int*)d_in[2];
    const float* w_mean1 = (const float*)d_in[3];
    const float* w_var1  = (const float*)d_in[4];
    const float* b_mean1 = (const float*)d_in[5];
    const float* b_var1  = (const float*)d_in[6];
    const float* w_mean2 = (const float*)d_in[7];
    const float* w_var2  = (const float*)d_in[8];
    const float* b_mean2 = (const float*)d_in[9];
    const float* b_var2  = (const float*)d_in[10];
    float* out = (float*)d_out;

    const int N = in_sizes[0] / IN_F;   // 100000
    const int E = in_sizes[1];          // 1600000

    __half* bufA = nullptr; __half* bufB = nullptr;
    __half* aggM = nullptr; __half* aggV = nullptr;
    cudaGetSymbolAddress((void**)&bufA, g_bufA);
    cudaGetSymbolAddress((void**)&bufB, g_bufB);
    cudaGetSymbolAddress((void**)&aggM, g_aggM);
    cudaGetSymbolAddress((void**)&aggV, g_aggV);

    const int T = 256;
    const int NB = (N + 1023) / 1024;

    // init (zero + weight pre-split), degrees, norms+scan, CSR
    k_init<<<(N + T - 1) / T, T>>>(w_mean1, w_var1, w_mean2, w_var2, N);
    k_count<<<(E + T - 1) / T, T>>>(dst, E);
    k_scan1<<<NB, 1024>>>(N);
    k_scan2<<<1, 128>>>(NB, N);
    k_scan3<<<NB, 1024>>>(N);
    k_fill<<<(E + T - 1) / T, T>>>(src, dst, E);

    // ---- layer 1: tensor-core dual GEMM (2-term, pre-split B) + fp16 msg epilogue ----
    {
        dim3 grid((N + 127) / 128, 2);
        k_l1_f16<<<grid, 256>>>(x, b_mean1, b_var1, bufA, bufB, N);
    }
    {
        int blocks = (N * 32 + T - 1) / T;   // warp per node
        k_agg1<<<blocks, T>>>(bufA, bufB, aggM, aggV, N);
    }

    // ---- layer 2: tensor-core dual-A GEMM (fp16 A, 2-term) + fp16 msg epilogue ----
    {
        int blocks = (N + 127) / 128;   // 782, covers M_PAD exactly
        k_l2_f16<<<blocks, 256>>>(aggM, aggV, b_mean2, b_var2, bufA, bufB);
    }
    // ---- layer-2 aggregation fused with threefry reparameterization ----
    {
        int blocks = (N * 32 + T - 1) / T;
        k_agg2_final<<<blocks, T>>>(bufA, bufB, out, N);
    }
}

// round 11
// speedup vs baseline: 2.6553x; 1.0173x over previous
#include <cuda_runtime.h>
#include <cuda_fp16.h>
#include <stdint.h>
#include <math.h>

#define NODES_MAX 100000
#define M_PAD     100096   // 782 * 128 (also multiple of 64)
#define EDGES_MAX 1600000
#define IN_F 256
#define HID 128
#define OUTF 64

// ---------------- scratch (static __device__, no allocs) ----------------
__device__ __half  g_bufA[(size_t)M_PAD * HID];   // messages m (fp16)
__device__ __half  g_bufB[(size_t)M_PAD * HID];   // messages v (fp16)
__device__ __half  g_aggM[(size_t)M_PAD * HID];   // aggregated mean (fp16)
__device__ __half  g_aggV[(size_t)M_PAD * HID];
__device__ float   g_norm1[M_PAD];
__device__ float   g_norm2[M_PAD];
__device__ int     g_deg[NODES_MAX];
__device__ int     g_cursor[NODES_MAX];
__device__ int     g_offs[NODES_MAX + 1];
__device__ int     g_csr[EDGES_MAX];
__device__ int     g_bsum[128];
// pre-split weights, packed as k-pair half2: [mat][K/2][N]
__device__ __half2 g_w1hi[2 * 128 * 128];
__device__ __half2 g_w1lo[2 * 128 * 128];
__device__ __half2 g_w2hi[2 * 64 * 64];
__device__ __half2 g_w2lo[2 * 64 * 64];

// ---------------- init: zero counters + weight pre-split (fused) ----------------
__global__ void k_init(const float* __restrict__ Wm1, const float* __restrict__ Wv1,
                       const float* __restrict__ Wm2, const float* __restrict__ Wv2, int n) {
    int i = blockIdx.x * blockDim.x + threadIdx.x;
    if (i < n) { g_deg[i] = 0; g_cursor[i] = 0; }
    if (i < 2 * 128 * 128) {   // W1: K=256 -> 128 k-pairs, N=128
        int mat = i >> 14;
        int rem = i & 16383;
        int kk = rem >> 7;
        int nn = rem & 127;
        const float* W = mat ? Wv1 : Wm1;
        float a = W[(2 * kk) * HID + nn];
        float b = W[(2 * kk + 1) * HID + nn];
        __half2 h = __floats2half2_rn(a, b);
        float2 hf = __half22float2(h);
        g_w1hi[i] = h;
        g_w1lo[i] = __floats2half2_rn(a - hf.x, b - hf.y);
    }
    if (i < 2 * 64 * 64) {     // W2: K=128 -> 64 k-pairs, N=64
        int mat = i >> 12;
        int rem = i & 4095;
        int kk = rem >> 6;
        int nn = rem & 63;
        const float* W = mat ? Wv2 : Wm2;
        float a = W[(2 * kk) * OUTF + nn];
        float b = W[(2 * kk + 1) * OUTF + nn];
        __half2 h = __floats2half2_rn(a, b);
        float2 hf = __half22float2(h);
        g_w2hi[i] = h;
        g_w2lo[i] = __floats2half2_rn(a - hf.x, b - hf.y);
    }
}

__global__ void k_count(const int* __restrict__ dst, int E) {
    int e = blockIdx.x * blockDim.x + threadIdx.x;
    if (e < E) atomicAdd(&g_deg[dst[e]], 1);
}

// ---------------- scan phase 1 (+ fused norm computation) ----------------
__global__ void k_scan1(int n) {
    __shared__ int sm[1024];
    int t = threadIdx.x;
    int i = blockIdx.x * 1024 + t;
    int v = (i < n) ? g_deg[i] : 0;
    if (i < n) {
        float d = fmaxf((float)v, 1.0f);
        float n1 = 1.0f / sqrtf(d);
        g_norm1[i] = n1;
        g_norm2[i] = n1 * n1;
    }
    sm[t] = v;
    __syncthreads();
#pragma unroll
    for (int d = 1; d < 1024; d <<= 1) {
        int u = (t >= d) ? sm[t - d] : 0;
        __syncthreads();
        sm[t] += u;
        __syncthreads();
    }
    if (i < n) g_offs[i] = sm[t] - v;
    if (t == 1023) g_bsum[blockIdx.x] = sm[1023];
}

// scan phases 2+3 fused: each block reduces g_bsum[0..bid) itself, adds offset
__global__ void k_scan3(int n, int nb) {
    __shared__ int sw[32];
    int t = threadIdx.x;
    int bid = blockIdx.x;
    int acc = 0;
    for (int i = t; i < bid; i += 1024) acc += g_bsum[i];
#pragma unroll
    for (int o = 16; o; o >>= 1) acc += __shfl_down_sync(0xFFFFFFFFu, acc, o);
    if ((t & 31) == 0) sw[t >> 5] = acc;
    __syncthreads();
    if (t < 32) {
        int v = sw[t];
#pragma unroll
        for (int o = 16; o; o >>= 1) v += __shfl_down_sync(0xFFFFFFFFu, v, o);
        if (t == 0) sw[0] = v;
    }
    __syncthreads();
    int off = sw[0];
    int i = bid * 1024 + t;
    if (i < n) g_offs[i] += off;
    if (bid == nb - 1 && t == 0) g_offs[n] = off + g_bsum[bid];
}

__global__ void k_fill(const int* __restrict__ src, const int* __restrict__ dst, int E) {
    int e = blockIdx.x * blockDim.x + threadIdx.x;
    if (e < E) {
        int d = dst[e];
        int p = atomicAdd(&g_cursor[d], 1);
        g_csr[g_offs[d] + p] = src[e];
    }
}

// ================= tensor-core helpers =================
__device__ __forceinline__ void mma_f16(float* d, uint32_t a0, uint32_t a1,
                                        uint32_t a2, uint32_t a3,
                                        uint32_t b0, uint32_t b1) {
    asm volatile(
        "mma.sync.aligned.m16n8k16.row.col.f32.f16.f16.f32 "
        "{%0,%1,%2,%3},{%4,%5,%6,%7},{%8,%9},{%0,%1,%2,%3};"
        : "+f"(d[0]), "+f"(d[1]), "+f"(d[2]), "+f"(d[3])
        : "r"(a0), "r"(a1), "r"(a2), "r"(a3), "r"(b0), "r"(b1));
}

__device__ __forceinline__ void cp16(uint32_t dst, const void* src, int sz) {
    asm volatile("cp.async.cg.shared.global [%0], [%1], 16, %2;"
                 :: "r"(dst), "l"(src), "r"(sz));
}
__device__ __forceinline__ void cp_commit() {
    asm volatile("cp.async.commit_group;");
}
template <int N> __device__ __forceinline__ void cp_wait() {
    asm volatile("cp.async.wait_group %0;" :: "n"(N));
}

#define APAD 20      // floats per A smem row (16 + 4)   [L1 fp32 A]
#define BPAD2 136    // half2 words per B pair-row (128 + 8)   [L2]
#define BPAD2N 264   // half2 words per B pair-row (256 + 8)   [L1, both mats x 128 cols]
#define A2PAD 24     // halfs per A smem row (16 + 8)    [L2 fp16 A]

// ================= layer-1: BM=64 x all 128 cols, 2-term, pre-split B =================
// grid: ceil(M/64); 8 warps = 2 warp_m (32 rows) x 4 warp_n (32 cols). X read ONCE.
__global__ void __launch_bounds__(256)
k_l1_f16(const float* __restrict__ X,
         const float* __restrict__ bm, const float* __restrict__ bv,
         __half* __restrict__ Cm, __half* __restrict__ Cv, int M) {
    __shared__ float    As[2][64 * APAD];
    __shared__ uint32_t Bh[2][8 * BPAD2N];
    __shared__ uint32_t Bl[2][8 * BPAD2N];

    const int tid = threadIdx.x;
    const int lane = tid & 31;
    const int wid = tid >> 5;
    const int warp_m = wid & 1;       // 2 bands of 32 rows
    const int warp_n = wid >> 1;      // 4 bands of 32 cols
    const int gid = lane >> 2;
    const int tig = lane & 3;
    const int bm_base = blockIdx.x * 64;

    float acc[2][2][4][4];   // [matrix][mt][nt][reg]
#pragma unroll
    for (int a = 0; a < 2; a++)
#pragma unroll
        for (int b = 0; b < 2; b++)
#pragma unroll
            for (int c = 0; c < 4; c++)
#pragma unroll
                for (int d = 0; d < 4; d++) acc[a][b][c][d] = 0.f;

    uint32_t asb[2], bhb[2], blb[2];
#pragma unroll
    for (int s = 0; s < 2; s++) {
        asb[s] = (uint32_t)__cvta_generic_to_shared(&As[s][0]);
        bhb[s] = (uint32_t)__cvta_generic_to_shared(&Bh[s][0]);
        blb[s] = (uint32_t)__cvta_generic_to_shared(&Bl[s][0]);
    }

    auto issue = [&](int stage, int k0) {
        int kk0 = k0 >> 1;
        // A tile: 64 rows x 16 k fp32 = 256 x 16B (1 chunk/thread)
        {
            int c = tid;
            int r = c >> 2, kq = c & 3;
            int gm = bm_base + r;
            int ok = (gm < M) ? 16 : 0;
            const float* srca = X + (size_t)min(gm, M - 1) * IN_F + k0 + kq * 4;
            cp16(asb[stage] + (uint32_t)(r * APAD + kq * 4) * 4, srca, ok);
        }
        // B tiles (hi+lo): 2 arr x 2 mat x 8 prows x 32 chunks = 1024 x 16B
#pragma unroll
        for (int c = tid; c < 1024; c += 256) {
            int arr = c >> 9;
            int rem = c & 511;
            int mat = rem >> 8;
            int pr = (rem >> 5) & 7;
            int q = rem & 31;
            const __half2* srcb = (arr ? g_w1lo : g_w1hi)
                + ((mat * 128 + kk0 + pr) * 128 + q * 4);
            uint32_t dstb = (arr ? blb[stage] : bhb[stage])
                + (uint32_t)(pr * BPAD2N + mat * 128 + q * 4) * 4;
            cp16(dstb, srcb, 16);
        }
        cp_commit();
    };

    issue(0, 0);

    const int NITER = IN_F / 16;   // 16
    for (int it = 0; it < NITER; it++) {
        int stage = it & 1;
        if (it + 1 < NITER) {
            issue(stage ^ 1, (it + 1) * 16);
            cp_wait<1>();
        } else {
            cp_wait<0>();
        }
        __syncthreads();

        const float* as = As[stage];
        const uint32_t* bh = Bh[stage];
        const uint32_t* bl = Bl[stage];

        // A fragments: fp32 -> fp16, shared across both matrices
        uint32_t ahi[2][4];
#pragma unroll
        for (int mt = 0; mt < 2; mt++) {
            int rb = warp_m * 32 + mt * 16;
            const float* r0 = as + (rb + gid) * APAD;
            const float* r1 = as + (rb + gid + 8) * APAD;
            float2 x0 = *reinterpret_cast<const float2*>(r0 + 2 * tig);
            float2 x1 = *reinterpret_cast<const float2*>(r1 + 2 * tig);
            float2 x2 = *reinterpret_cast<const float2*>(r0 + 2 * tig + 8);
            float2 x3 = *reinterpret_cast<const float2*>(r1 + 2 * tig + 8);
            __half2 h;
            h = __floats2half2_rn(x0.x, x0.y); ahi[mt][0] = *reinterpret_cast<uint32_t*>(&h);
            h = __floats2half2_rn(x1.x, x1.y); ahi[mt][1] = *reinterpret_cast<uint32_t*>(&h);
            h = __floats2half2_rn(x2.x, x2.y); ahi[mt][2] = *reinterpret_cast<uint32_t*>(&h);
            h = __floats2half2_rn(x3.x, x3.y); ahi[mt][3] = *reinterpret_cast<uint32_t*>(&h);
        }

#pragma unroll
        for (int mat = 0; mat < 2; mat++) {
#pragma unroll
            for (int nt = 0; nt < 4; nt++) {
                int col = mat * 128 + warp_n * 32 + nt * 8 + gid;
                uint32_t bh0 = bh[tig * BPAD2N + col];
                uint32_t bh1 = bh[(tig + 4) * BPAD2N + col];
                uint32_t bl0 = bl[tig * BPAD2N + col];
                uint32_t bl1 = bl[(tig + 4) * BPAD2N + col];
#pragma unroll
                for (int mt = 0; mt < 2; mt++) {
                    float* d = acc[mat][mt][nt];
                    mma_f16(d, ahi[mt][0], ahi[mt][1], ahi[mt][2], ahi[mt][3], bh0, bh1);
                    mma_f16(d, ahi[mt][0], ahi[mt][1], ahi[mt][2], ahi[mt][3], bl0, bl1);
                }
            }
        }
        __syncthreads();
    }

    // ---- epilogue: bias + relu + att + norms -> fp16 messages ----
#pragma unroll
    for (int nt = 0; nt < 4; nt++) {
        int gc = warp_n * 32 + nt * 8 + tig * 2;
        float bm0 = bm[gc], bm1 = bm[gc + 1];
        float bv0 = bv[gc], bv1 = bv[gc + 1];
#pragma unroll
        for (int mt = 0; mt < 2; mt++) {
#pragma unroll
            for (int half = 0; half < 2; half++) {
                int gm = bm_base + warp_m * 32 + mt * 16 + gid + half * 8;
                float n1 = g_norm1[gm];
                float n2 = g_norm2[gm];
                float mean0 = fmaxf(acc[0][mt][nt][half * 2 + 0] + bm0, 0.f);
                float mean1 = fmaxf(acc[0][mt][nt][half * 2 + 1] + bm1, 0.f);
                float var0  = fmaxf(acc[1][mt][nt][half * 2 + 0] + bv0, 0.f);
                float var1  = fmaxf(acc[1][mt][nt][half * 2 + 1] + bv1, 0.f);
                float att0 = expf(-var0), att1 = expf(-var1);
                float2 om = make_float2(mean0 * att0 * n1, mean1 * att1 * n1);
                float2 ov = make_float2(var0 * att0 * att0 * n2, var1 * att1 * att1 * n2);
                *reinterpret_cast<__half2*>(Cm + (size_t)gm * HID + gc) = __float22half2_rn(om);
                *reinterpret_cast<__half2*>(Cv + (size_t)gm * HID + gc) = __float22half2_rn(ov);
            }
        }
    }
}

// ================= layer-2: dual-A (fp16) dual GEMM, 2-term, pre-split B =================
__global__ void __launch_bounds__(256)
k_l2_f16(const __half* __restrict__ Am, const __half* __restrict__ Av,   // [M_PAD][128] fp16
         const float* __restrict__ bm, const float* __restrict__ bv,
         __half* __restrict__ Cm, __half* __restrict__ Cv) {
    __shared__ __half   As[2][2][128 * A2PAD];   // [stage][matrix]
    __shared__ uint32_t Bh[2][8 * BPAD2];
    __shared__ uint32_t Bl[2][8 * BPAD2];

    const int tid = threadIdx.x;
    const int lane = tid & 31;
    const int wid = tid >> 5;
    const int warp_m = wid & 3;
    const int warp_n = wid >> 2;
    const int gid = lane >> 2;
    const int tig = lane & 3;
    const int bm_base = blockIdx.x * 128;

    float acc[2][2][4][4];
#pragma unroll
    for (int a = 0; a < 2; a++)
#pragma unroll
        for (int b = 0; b < 2; b++)
#pragma unroll
            for (int c = 0; c < 4; c++)
#pragma unroll
                for (int d = 0; d < 4; d++) acc[a][b][c][d] = 0.f;

    uint32_t asb[2][2], bhb[2], blb[2];
#pragma unroll
    for (int s = 0; s < 2; s++) {
        asb[s][0] = (uint32_t)__cvta_generic_to_shared(&As[s][0][0]);
        asb[s][1] = (uint32_t)__cvta_generic_to_shared(&As[s][1][0]);
        bhb[s] = (uint32_t)__cvta_generic_to_shared(&Bh[s][0]);
        blb[s] = (uint32_t)__cvta_generic_to_shared(&Bl[s][0]);
    }

    auto issue = [&](int stage, int k0) {
        int kk0 = k0 >> 1;
#pragma unroll
        for (int c = tid; c < 512; c += 256) {
            int mat = c >> 8;
            int r = (c >> 1) & 127;
            int q = c & 1;
            const __half* srca = (mat ? Av : Am) + (size_t)(bm_base + r) * HID + k0 + q * 8;
            cp16(asb[stage][mat] + (uint32_t)(r * A2PAD + q * 8) * 2, srca, 16);
        }
#pragma unroll
        for (int c = tid; c < 512; c += 256) {
            int arr = c >> 8;
            int rem = c & 255;
            int mat = rem >> 7;
            int pr = (rem >> 4) & 7;
            int q = rem & 15;
            const __half2* srcb = (arr ? g_w2lo : g_w2hi)
                + ((mat * 64 + kk0 + pr) * 64 + q * 4);
            uint32_t dstb = (arr ? blb[stage] : bhb[stage])
                + (uint32_t)(pr * BPAD2 + mat * 64 + q * 4) * 4;
            cp16(dstb, srcb, 16);
        }
        cp_commit();
    };

    issue(0, 0);

    const int NITER = HID / 16;   // 8
    for (int it = 0; it < NITER; it++) {
        int stage = it & 1;
        if (it + 1 < NITER) {
            issue(stage ^ 1, (it + 1) * 16);
            cp_wait<1>();
        } else {
            cp_wait<0>();
        }
        __syncthreads();

        const uint32_t* bh = Bh[stage];
        const uint32_t* bl = Bl[stage];

#pragma unroll
        for (int mat = 0; mat < 2; mat++) {
            const __half* as = As[stage][mat];
            uint32_t a[2][4];
#pragma unroll
            for (int mt = 0; mt < 2; mt++) {
                int rb = warp_m * 32 + mt * 16;
                const __half* r0 = as + (rb + gid) * A2PAD;
                const __half* r1 = as + (rb + gid + 8) * A2PAD;
                a[mt][0] = *reinterpret_cast<const uint32_t*>(r0 + 2 * tig);
                a[mt][1] = *reinterpret_cast<const uint32_t*>(r1 + 2 * tig);
                a[mt][2] = *reinterpret_cast<const uint32_t*>(r0 + 2 * tig + 8);
                a[mt][3] = *reinterpret_cast<const uint32_t*>(r1 + 2 * tig + 8);
            }
#pragma unroll
            for (int nt = 0; nt < 4; nt++) {
                int col = mat * 64 + warp_n * 32 + nt * 8 + gid;
                uint32_t bh0 = bh[tig * BPAD2 + col];
                uint32_t bh1 = bh[(tig + 4) * BPAD2 + col];
                uint32_t bl0 = bl[tig * BPAD2 + col];
                uint32_t bl1 = bl[(tig + 4) * BPAD2 + col];
#pragma unroll
                for (int mt = 0; mt < 2; mt++) {
                    float* d = acc[mat][mt][nt];
                    mma_f16(d, a[mt][0], a[mt][1], a[mt][2], a[mt][3], bh0, bh1);
                    mma_f16(d, a[mt][0], a[mt][1], a[mt][2], a[mt][3], bl0, bl1);
                }
            }
        }
        __syncthreads();
    }

    // ---- epilogue -> fp16 messages [M_PAD][64] ----
#pragma unroll
    for (int nt = 0; nt < 4; nt++) {
        int gc = warp_n * 32 + nt * 8 + tig * 2;
        float bm0 = bm[gc], bm1 = bm[gc + 1];
        float bv0 = bv[gc], bv1 = bv[gc + 1];
#pragma unroll
        for (int mt = 0; mt < 2; mt++) {
#pragma unroll
            for (int half = 0; half < 2; half++) {
                int gm = bm_base + warp_m * 32 + mt * 16 + gid + half * 8;
                float n1 = g_norm1[gm];
                float n2 = g_norm2[gm];
                float mean0 = fmaxf(acc[0][mt][nt][half * 2 + 0] + bm0, 0.f);
                float mean1 = fmaxf(acc[0][mt][nt][half * 2 + 1] + bm1, 0.f);
                float var0  = fmaxf(acc[1][mt][nt][half * 2 + 0] + bv0, 0.f);
                float var1  = fmaxf(acc[1][mt][nt][half * 2 + 1] + bv1, 0.f);
                float att0 = expf(-var0), att1 = expf(-var1);
                float2 om = make_float2(mean0 * att0 * n1, mean1 * att1 * n1);
                float2 ov = make_float2(var0 * att0 * att0 * n2, var1 * att1 * att1 * n2);
                *reinterpret_cast<__half2*>(Cm + (size_t)gm * OUTF + gc) = __float22half2_rn(om);
                *reinterpret_cast<__half2*>(Cv + (size_t)gm * OUTF + gc) = __float22half2_rn(ov);
            }
        }
    }
}

// ---------------- aggregation: warp per node, CSR pure-read reduce (fp16 in/out) ----------------
__global__ void k_agg1(const __half* __restrict__ msrc, const __half* __restrict__ vsrc,
                       __half* __restrict__ mdst, __half* __restrict__ vdst, int n) {
    int warp = (blockIdx.x * blockDim.x + threadIdx.x) >> 5;
    int lane = threadIdx.x & 31;
    if (warp >= n) return;
    const int D = 128;
    int start = g_offs[warp], end = g_offs[warp + 1];

    float am[4] = {0.f, 0.f, 0.f, 0.f};
    float av[4] = {0.f, 0.f, 0.f, 0.f};
    for (int e = start; e < end; e++) {
        int s = g_csr[e];
        uint2 ar = __ldg(reinterpret_cast<const uint2*>(msrc + (size_t)s * D + lane * 4));
        uint2 br = __ldg(reinterpret_cast<const uint2*>(vsrc + (size_t)s * D + lane * 4));
        float2 a0 = __half22float2(*reinterpret_cast<__half2*>(&ar.x));
        float2 a1 = __half22float2(*reinterpret_cast<__half2*>(&ar.y));
        float2 b0 = __half22float2(*reinterpret_cast<__half2*>(&br.x));
        float2 b1 = __half22float2(*reinterpret_cast<__half2*>(&br.y));
        am[0] += a0.x; am[1] += a0.y; am[2] += a1.x; am[3] += a1.y;
        av[0] += b0.x; av[1] += b0.y; av[2] += b1.x; av[3] += b1.y;
    }
    float n1 = g_norm1[warp], n2 = g_norm2[warp];
#pragma unroll
    for (int j = 0; j < 4; j++) {
        am[j] = fmaxf(am[j] * n1, 0.f);
        av[j] = fmaxf(av[j] * n2, 0.f);
    }
    __half2 m01 = __floats2half2_rn(am[0], am[1]);
    __half2 m23 = __floats2half2_rn(am[2], am[3]);
    __half2 v01 = __floats2half2_rn(av[0], av[1]);
    __half2 v23 = __floats2half2_rn(av[2], av[3]);
    uint2 mo, vo;
    mo.x = *reinterpret_cast<uint32_t*>(&m01); mo.y = *reinterpret_cast<uint32_t*>(&m23);
    vo.x = *reinterpret_cast<uint32_t*>(&v01); vo.y = *reinterpret_cast<uint32_t*>(&v23);
    *reinterpret_cast<uint2*>(mdst + (size_t)warp * D + lane * 4) = mo;
    *reinterpret_cast<uint2*>(vdst + (size_t)warp * D + lane * 4) = vo;
}

// ---------------- threefry-2x32-20 (KAT-verified) ----------------
__device__ __forceinline__ uint32_t rotl32(uint32_t x, int d) {
    return (x << d) | (x >> (32 - d));
}

__device__ __forceinline__ void threefry2x32(uint32_t k0, uint32_t k1,
                                             uint32_t& x0, uint32_t& x1) {
    uint32_t s0 = k0, s1 = k1, s2 = k0 ^ k1 ^ 0x1BD11BDAu;
    x0 += s0; x1 += s1;
#define TFR(r) { x0 += x1; x1 = rotl32(x1, r); x1 ^= x0; }
    TFR(13) TFR(15) TFR(26) TFR(6)   x0 += s1; x1 += s2 + 1u;
    TFR(17) TFR(29) TFR(16) TFR(24)  x0 += s2; x1 += s0 + 2u;
    TFR(13) TFR(15) TFR(26) TFR(6)   x0 += s0; x1 += s1 + 3u;
    TFR(17) TFR(29) TFR(16) TFR(24)  x0 += s1; x1 += s2 + 4u;
    TFR(13) TFR(15) TFR(26) TFR(6)   x0 += s2; x1 += s0 + 5u;
#undef TFR
}

__device__ __forceinline__ float jax_normal_elem(uint32_t idx) {
    uint32_t x0 = 0u, x1 = idx;
    threefry2x32(0u, 42u, x0, x1);
    uint32_t bits = x0 ^ x1;
    uint32_t fb = (bits >> 9) | 0x3F800000u;
    float u01 = __uint_as_float(fb) - 1.0f;
    const float lo = -0.99999994f;
    float u = fmaxf(u01 * 2.0f + lo, lo);
    return 1.41421356f * erfinvf(u);
}

// layer-2 aggregation fused with reparameterization (fp16 msgs): warp per node, D=64
__global__ void k_agg2_final(const __half* __restrict__ msrc, const __half* __restrict__ vsrc,
                             float* __restrict__ out, int n) {
    int warp = (blockIdx.x * blockDim.x + threadIdx.x) >> 5;
    int lane = threadIdx.x & 31;
    if (warp >= n) return;
    const int D = 64;
    int start = g_offs[warp], end = g_offs[warp + 1];

    float am0 = 0.f, am1 = 0.f, av0 = 0.f, av1 = 0.f;
    for (int e = start; e < end; e++) {
        int s = g_csr[e];
        __half2 ah = __ldg(reinterpret_cast<const __half2*>(msrc + (size_t)s * D + lane * 2));
        __half2 bh = __ldg(reinterpret_cast<const __half2*>(vsrc + (size_t)s * D + lane * 2));
        float2 a = __half22float2(ah);
        float2 b = __half22float2(bh);
        am0 += a.x; am1 += a.y;
        av0 += b.x; av1 += b.y;
    }
    float n1 = g_norm1[warp], n2 = g_norm2[warp];
    float m0 = am0 * n1, m1 = am1 * n1;
    float v0 = av0 * n2, v1 = av1 * n2;

    uint32_t t0 = (uint32_t)(warp * D + lane * 2);
    float e0 = jax_normal_elem(t0);
    float e1 = jax_normal_elem(t0 + 1u);
    float2 o;
    o.x = e0 * sqrtf(v0 + 1e-8f) + m0;
    o.y = e1 * sqrtf(v1 + 1e-8f) + m1;
    *reinterpret_cast<float2*>(out + (size_t)warp * D + lane * 2) = o;
}

// ---------------- launch ----------------
extern "C" void kernel_launch(void* const* d_in, const int* in_sizes, int n_in,
                              void* d_out, int out_size) {
    const float* x       = (const float*)d_in[0];
    const int*   src     = (const int*)d_in[1];
    const int*   dst     = (const int*)d_in[2];
    const float* w_mean1 = (const float*)d_in[3];
    const float* w_var1  = (const float*)d_in[4];
    const float* b_mean1 = (const float*)d_in[5];
    const float* b_var1  = (const float*)d_in[6];
    const float* w_mean2 = (const float*)d_in[7];
    const float* w_var2  = (const float*)d_in[8];
    const float* b_mean2 = (const float*)d_in[9];
    const float* b_var2  = (const float*)d_in[10];
    float* out = (float*)d_out;

    const int N = in_sizes[0] / IN_F;   // 100000
    const int E = in_sizes[1];          // 1600000

    __half* bufA = nullptr; __half* bufB = nullptr;
    __half* aggM = nullptr; __half* aggV = nullptr;
    cudaGetSymbolAddress((void**)&bufA, g_bufA);
    cudaGetSymbolAddress((void**)&bufB, g_bufB);
    cudaGetSymbolAddress((void**)&aggM, g_aggM);
    cudaGetSymbolAddress((void**)&aggV, g_aggV);

    const int T = 256;
    const int NB = (N + 1023) / 1024;

    // init (zero + weight pre-split), degrees, norms+scan (2 kernels), CSR
    k_init<<<(N + T - 1) / T, T>>>(w_mean1, w_var1, w_mean2, w_var2, N);
    k_count<<<(E + T - 1) / T, T>>>(dst, E);
    k_scan1<<<NB, 1024>>>(N);
    k_scan3<<<NB, 1024>>>(N, NB);
    k_fill<<<(E + T - 1) / T, T>>>(src, dst, E);

    // ---- layer 1: BM=64 x 128 cols dual GEMM (2-term) + fp16 msg epilogue ----
    {
        int blocks = (N + 63) / 64;   // 1563
        k_l1_f16<<<blocks, 256>>>(x, b_mean1, b_var1, bufA, bufB, N);
    }
    {
        int blocks = (N * 32 + T - 1) / T;   // warp per node
        k_agg1<<<blocks, T>>>(bufA, bufB, aggM, aggV, N);
    }

    // ---- layer 2: tensor-core dual-A GEMM (fp16 A, 2-term) + fp16 msg epilogue ----
    {
        int blocks = (N + 127) / 128;   // 782, covers M_PAD exactly
        k_l2_f16<<<blocks, 256>>>(aggM, aggV, b_mean2, b_var2, bufA, bufB);
    }
    // ---- layer-2 aggregation fused with threefry reparameterization ----
    {
        int blocks = (N * 32 + T - 1) / T;
        k_agg2_final<<<blocks, T>>>(bufA, bufB, out, N);
    }
}

// round 12
// speedup vs baseline: 3.0345x; 1.1428x over previous
#include <cuda_runtime.h>
#include <cuda_fp16.h>
#include <stdint.h>
#include <math.h>

#define NODES_MAX 100000
#define M_PAD     100096   // 782 * 128 (also multiple of 64)
#define EDGES_MAX 1600000
#define IN_F 256
#define HID 128
#define OUTF 64

// ---------------- scratch (static __device__, no allocs) ----------------
__device__ __half  g_bufA[(size_t)M_PAD * HID];   // messages m (fp16)
__device__ __half  g_bufB[(size_t)M_PAD * HID];   // messages v (fp16)
__device__ __half  g_aggM[(size_t)M_PAD * HID];   // aggregated mean (fp16)
__device__ __half  g_aggV[(size_t)M_PAD * HID];
__device__ float   g_norm1[M_PAD];
__device__ float   g_norm2[M_PAD];
__device__ int     g_deg[NODES_MAX];
__device__ int     g_cursor[NODES_MAX];
__device__ int     g_offs[NODES_MAX + 1];
__device__ int     g_csr[EDGES_MAX];
__device__ int     g_bsum[128];
__device__ int     g_flag[128];
// fp16 weights, packed as k-pair half2: [mat][K/2][N]
__device__ __half2 g_w1[2 * 128 * 128];
__device__ __half2 g_w2[2 * 64 * 64];

// ---------------- init: zero counters/flags + weight fp16 pack ----------------
__global__ void k_init(const float* __restrict__ Wm1, const float* __restrict__ Wv1,
                       const float* __restrict__ Wm2, const float* __restrict__ Wv2, int n) {
    int i = blockIdx.x * blockDim.x + threadIdx.x;
    if (i < n) { g_deg[i] = 0; g_cursor[i] = 0; }
    if (i < 128) g_flag[i] = 0;
    if (i < 2 * 128 * 128) {   // W1: K=256 -> 128 k-pairs, N=128
        int mat = i >> 14;
        int rem = i & 16383;
        int kk = rem >> 7;
        int nn = rem & 127;
        const float* W = mat ? Wv1 : Wm1;
        g_w1[i] = __floats2half2_rn(W[(2 * kk) * HID + nn], W[(2 * kk + 1) * HID + nn]);
    }
    if (i < 2 * 64 * 64) {     // W2: K=128 -> 64 k-pairs, N=64
        int mat = i >> 12;
        int rem = i & 4095;
        int kk = rem >> 6;
        int nn = rem & 63;
        const float* W = mat ? Wv2 : Wm2;
        g_w2[i] = __floats2half2_rn(W[(2 * kk) * OUTF + nn], W[(2 * kk + 1) * OUTF + nn]);
    }
}

__global__ void k_count(const int* __restrict__ dst, int E) {
    int e = blockIdx.x * blockDim.x + threadIdx.x;
    if (e < E) atomicAdd(&g_deg[dst[e]], 1);
}

// ---------------- single-pass scan (+ fused norms), chained lookback ----------------
// 98 blocks, all resident concurrently -> spin-wait is safe.
__global__ void k_scan(int n, int nb) {
    __shared__ int sm[1024];
    __shared__ int soff;
    int t = threadIdx.x;
    int bid = blockIdx.x;
    int i = bid * 1024 + t;
    int v = (i < n) ? g_deg[i] : 0;
    if (i < n) {
        float d = fmaxf((float)v, 1.0f);
        float n1 = 1.0f / sqrtf(d);
        g_norm1[i] = n1;
        g_norm2[i] = n1 * n1;
    }
    sm[t] = v;
    __syncthreads();
#pragma unroll
    for (int d = 1; d < 1024; d <<= 1) {
        int u = (t >= d) ? sm[t - d] : 0;
        __syncthreads();
        sm[t] += u;
        __syncthreads();
    }
    // publish this block's total
    if (t == 1023) {
        g_bsum[bid] = sm[1023];
        __threadfence();
        atomicExch(&g_flag[bid], 1);
    }
    // lookback: sum totals of all previous blocks
    int acc = 0;
    for (int b = t; b < bid; b += 1024) {
        while (atomicAdd(&g_flag[b], 0) == 0) {}
        acc += g_bsum[b];
    }
#pragma unroll
    for (int o = 16; o; o >>= 1) acc += __shfl_down_sync(0xFFFFFFFFu, acc, o);
    __shared__ int sw[32];
    if ((t & 31) == 0) sw[t >> 5] = acc;
    __syncthreads();
    if (t < 32) {
        int vv = sw[t];
#pragma unroll
        for (int o = 16; o; o >>= 1) vv += __shfl_down_sync(0xFFFFFFFFu, vv, o);
        if (t == 0) soff = vv;
    }
    __syncthreads();
    int off = soff;
    if (i < n) g_offs[i] = off + sm[t] - v;   // exclusive
    if (bid == nb - 1 && t == 1023) g_offs[n] = off + sm[1023];
}

__global__ void k_fill(const int* __restrict__ src, const int* __restrict__ dst, int E) {
    int e = blockIdx.x * blockDim.x + threadIdx.x;
    if (e < E) {
        int d = dst[e];
        int p = atomicAdd(&g_cursor[d], 1);
        g_csr[g_offs[d] + p] = src[e];
    }
}

// ================= tensor-core helpers =================
__device__ __forceinline__ void mma_f16(float* d, uint32_t a0, uint32_t a1,
                                        uint32_t a2, uint32_t a3,
                                        uint32_t b0, uint32_t b1) {
    asm volatile(
        "mma.sync.aligned.m16n8k16.row.col.f32.f16.f16.f32 "
        "{%0,%1,%2,%3},{%4,%5,%6,%7},{%8,%9},{%0,%1,%2,%3};"
        : "+f"(d[0]), "+f"(d[1]), "+f"(d[2]), "+f"(d[3])
        : "r"(a0), "r"(a1), "r"(a2), "r"(a3), "r"(b0), "r"(b1));
}

__device__ __forceinline__ void cp16(uint32_t dst, const void* src, int sz) {
    asm volatile("cp.async.cg.shared.global [%0], [%1], 16, %2;"
                 :: "r"(dst), "l"(src), "r"(sz));
}
__device__ __forceinline__ void cp_commit() {
    asm volatile("cp.async.commit_group;");
}
template <int N> __device__ __forceinline__ void cp_wait() {
    asm volatile("cp.async.wait_group %0;" :: "n"(N));
}

#define APAD 20      // floats per A smem row (16 + 4)   [L1 fp32 A]
#define BPAD2 136    // half2 words per B pair-row (128 + 8)   [L2]
#define BPAD2N 264   // half2 words per B pair-row (256 + 8)   [L1]
#define A2PAD 24     // halfs per A smem row (16 + 8)    [L2 fp16 A]

// ================= layer-1: BM=64 x 128 cols, 1-term fp16, fp16 weights =================
// grid: ceil(M/64); 8 warps = 2 warp_m (32 rows) x 4 warp_n (32 cols). X read once.
__global__ void __launch_bounds__(256)
k_l1_f16(const float* __restrict__ X,
         const float* __restrict__ bm, const float* __restrict__ bv,
         __half* __restrict__ Cm, __half* __restrict__ Cv, int M) {
    __shared__ float    As[2][64 * APAD];
    __shared__ uint32_t Bh[2][8 * BPAD2N];

    const int tid = threadIdx.x;
    const int lane = tid & 31;
    const int wid = tid >> 5;
    const int warp_m = wid & 1;
    const int warp_n = wid >> 1;
    const int gid = lane >> 2;
    const int tig = lane & 3;
    const int bm_base = blockIdx.x * 64;

    float acc[2][2][4][4];   // [matrix][mt][nt][reg]
#pragma unroll
    for (int a = 0; a < 2; a++)
#pragma unroll
        for (int b = 0; b < 2; b++)
#pragma unroll
            for (int c = 0; c < 4; c++)
#pragma unroll
                for (int d = 0; d < 4; d++) acc[a][b][c][d] = 0.f;

    uint32_t asb[2], bhb[2];
#pragma unroll
    for (int s = 0; s < 2; s++) {
        asb[s] = (uint32_t)__cvta_generic_to_shared(&As[s][0]);
        bhb[s] = (uint32_t)__cvta_generic_to_shared(&Bh[s][0]);
    }

    auto issue = [&](int stage, int k0) {
        int kk0 = k0 >> 1;
        // A tile: 64 rows x 16 k fp32 = 256 x 16B (1 chunk/thread)
        {
            int c = tid;
            int r = c >> 2, kq = c & 3;
            int gm = bm_base + r;
            int ok = (gm < M) ? 16 : 0;
            const float* srca = X + (size_t)min(gm, M - 1) * IN_F + k0 + kq * 4;
            cp16(asb[stage] + (uint32_t)(r * APAD + kq * 4) * 4, srca, ok);
        }
        // B tile: 2 mat x 8 prows x 32 chunks = 512 x 16B (2 chunks/thread)
#pragma unroll
        for (int c = tid; c < 512; c += 256) {
            int mat = c >> 8;
            int pr = (c >> 5) & 7;
            int q = c & 31;
            const __half2* srcb = g_w1 + ((mat * 128 + kk0 + pr) * 128 + q * 4);
            uint32_t dstb = bhb[stage] + (uint32_t)(pr * BPAD2N + mat * 128 + q * 4) * 4;
            cp16(dstb, srcb, 16);
        }
        cp_commit();
    };

    issue(0, 0);

    const int NITER = IN_F / 16;   // 16
    for (int it = 0; it < NITER; it++) {
        int stage = it & 1;
        if (it + 1 < NITER) {
            issue(stage ^ 1, (it + 1) * 16);
            cp_wait<1>();
        } else {
            cp_wait<0>();
        }
        __syncthreads();

        const float* as = As[stage];
        const uint32_t* bh = Bh[stage];

        // A fragments: fp32 -> fp16, shared across both matrices
        uint32_t ahi[2][4];
#pragma unroll
        for (int mt = 0; mt < 2; mt++) {
            int rb = warp_m * 32 + mt * 16;
            const float* r0 = as + (rb + gid) * APAD;
            const float* r1 = as + (rb + gid + 8) * APAD;
            float2 x0 = *reinterpret_cast<const float2*>(r0 + 2 * tig);
            float2 x1 = *reinterpret_cast<const float2*>(r1 + 2 * tig);
            float2 x2 = *reinterpret_cast<const float2*>(r0 + 2 * tig + 8);
            float2 x3 = *reinterpret_cast<const float2*>(r1 + 2 * tig + 8);
            __half2 h;
            h = __floats2half2_rn(x0.x, x0.y); ahi[mt][0] = *reinterpret_cast<uint32_t*>(&h);
            h = __floats2half2_rn(x1.x, x1.y); ahi[mt][1] = *reinterpret_cast<uint32_t*>(&h);
            h = __floats2half2_rn(x2.x, x2.y); ahi[mt][2] = *reinterpret_cast<uint32_t*>(&h);
            h = __floats2half2_rn(x3.x, x3.y); ahi[mt][3] = *reinterpret_cast<uint32_t*>(&h);
        }

#pragma unroll
        for (int mat = 0; mat < 2; mat++) {
#pragma unroll
            for (int nt = 0; nt < 4; nt++) {
                int col = mat * 128 + warp_n * 32 + nt * 8 + gid;
                uint32_t bh0 = bh[tig * BPAD2N + col];
                uint32_t bh1 = bh[(tig + 4) * BPAD2N + col];
#pragma unroll
                for (int mt = 0; mt < 2; mt++) {
                    mma_f16(acc[mat][mt][nt], ahi[mt][0], ahi[mt][1], ahi[mt][2], ahi[mt][3],
                            bh0, bh1);
                }
            }
        }
        __syncthreads();
    }

    // ---- epilogue: bias + relu + att + norms -> fp16 messages ----
#pragma unroll
    for (int nt = 0; nt < 4; nt++) {
        int gc = warp_n * 32 + nt * 8 + tig * 2;
        float bm0 = bm[gc], bm1 = bm[gc + 1];
        float bv0 = bv[gc], bv1 = bv[gc + 1];
#pragma unroll
        for (int mt = 0; mt < 2; mt++) {
#pragma unroll
            for (int half = 0; half < 2; half++) {
                int gm = bm_base + warp_m * 32 + mt * 16 + gid + half * 8;
                float n1 = g_norm1[gm];
                float n2 = g_norm2[gm];
                float mean0 = fmaxf(acc[0][mt][nt][half * 2 + 0] + bm0, 0.f);
                float mean1 = fmaxf(acc[0][mt][nt][half * 2 + 1] + bm1, 0.f);
                float var0  = fmaxf(acc[1][mt][nt][half * 2 + 0] + bv0, 0.f);
                float var1  = fmaxf(acc[1][mt][nt][half * 2 + 1] + bv1, 0.f);
                float att0 = expf(-var0), att1 = expf(-var1);
                float2 om = make_float2(mean0 * att0 * n1, mean1 * att1 * n1);
                float2 ov = make_float2(var0 * att0 * att0 * n2, var1 * att1 * att1 * n2);
                *reinterpret_cast<__half2*>(Cm + (size_t)gm * HID + gc) = __float22half2_rn(om);
                *reinterpret_cast<__half2*>(Cv + (size_t)gm * HID + gc) = __float22half2_rn(ov);
            }
        }
    }
}

// ================= layer-2: dual-A (fp16) GEMM, 1-term, fp16 weights =================
__global__ void __launch_bounds__(256)
k_l2_f16(const __half* __restrict__ Am, const __half* __restrict__ Av,   // [M_PAD][128] fp16
         const float* __restrict__ bm, const float* __restrict__ bv,
         __half* __restrict__ Cm, __half* __restrict__ Cv) {
    __shared__ __half   As[2][2][128 * A2PAD];   // [stage][matrix]
    __shared__ uint32_t Bh[2][8 * BPAD2];

    const int tid = threadIdx.x;
    const int lane = tid & 31;
    const int wid = tid >> 5;
    const int warp_m = wid & 3;
    const int warp_n = wid >> 2;
    const int gid = lane >> 2;
    const int tig = lane & 3;
    const int bm_base = blockIdx.x * 128;

    float acc[2][2][4][4];
#pragma unroll
    for (int a = 0; a < 2; a++)
#pragma unroll
        for (int b = 0; b < 2; b++)
#pragma unroll
            for (int c = 0; c < 4; c++)
#pragma unroll
                for (int d = 0; d < 4; d++) acc[a][b][c][d] = 0.f;

    uint32_t asb[2][2], bhb[2];
#pragma unroll
    for (int s = 0; s < 2; s++) {
        asb[s][0] = (uint32_t)__cvta_generic_to_shared(&As[s][0][0]);
        asb[s][1] = (uint32_t)__cvta_generic_to_shared(&As[s][1][0]);
        bhb[s] = (uint32_t)__cvta_generic_to_shared(&Bh[s][0]);
    }

    auto issue = [&](int stage, int k0) {
        int kk0 = k0 >> 1;
#pragma unroll
        for (int c = tid; c < 512; c += 256) {
            int mat = c >> 8;
            int r = (c >> 1) & 127;
            int q = c & 1;
            const __half* srca = (mat ? Av : Am) + (size_t)(bm_base + r) * HID + k0 + q * 8;
            cp16(asb[stage][mat] + (uint32_t)(r * A2PAD + q * 8) * 2, srca, 16);
        }
        // B tile: 2 mat x 8 prows x 16 chunks = 256 x 16B (1 chunk/thread)
        {
            int c = tid;
            int mat = c >> 7;
            int pr = (c >> 4) & 7;
            int q = c & 15;
            const __half2* srcb = g_w2 + ((mat * 64 + kk0 + pr) * 64 + q * 4);
            uint32_t dstb = bhb[stage] + (uint32_t)(pr * BPAD2 + mat * 64 + q * 4) * 4;
            cp16(dstb, srcb, 16);
        }
        cp_commit();
    };

    issue(0, 0);

    const int NITER = HID / 16;   // 8
    for (int it = 0; it < NITER; it++) {
        int stage = it & 1;
        if (it + 1 < NITER) {
            issue(stage ^ 1, (it + 1) * 16);
            cp_wait<1>();
        } else {
            cp_wait<0>();
        }
        __syncthreads();

        const uint32_t* bh = Bh[stage];

#pragma unroll
        for (int mat = 0; mat < 2; mat++) {
            const __half* as = As[stage][mat];
            uint32_t a[2][4];
#pragma unroll
            for (int mt = 0; mt < 2; mt++) {
                int rb = warp_m * 32 + mt * 16;
                const __half* r0 = as + (rb + gid) * A2PAD;
                const __half* r1 = as + (rb + gid + 8) * A2PAD;
                a[mt][0] = *reinterpret_cast<const uint32_t*>(r0 + 2 * tig);
                a[mt][1] = *reinterpret_cast<const uint32_t*>(r1 + 2 * tig);
                a[mt][2] = *reinterpret_cast<const uint32_t*>(r0 + 2 * tig + 8);
                a[mt][3] = *reinterpret_cast<const uint32_t*>(r1 + 2 * tig + 8);
            }
#pragma unroll
            for (int nt = 0; nt < 4; nt++) {
                int col = mat * 64 + warp_n * 32 + nt * 8 + gid;
                uint32_t bh0 = bh[tig * BPAD2 + col];
                uint32_t bh1 = bh[(tig + 4) * BPAD2 + col];
#pragma unroll
                for (int mt = 0; mt < 2; mt++) {
                    mma_f16(acc[mat][mt][nt], a[mt][0], a[mt][1], a[mt][2], a[mt][3], bh0, bh1);
                }
            }
        }
        __syncthreads();
    }

    // ---- epilogue -> fp16 messages [M_PAD][64] ----
#pragma unroll
    for (int nt = 0; nt < 4; nt++) {
        int gc = warp_n * 32 + nt * 8 + tig * 2;
        float bm0 = bm[gc], bm1 = bm[gc + 1];
        float bv0 = bv[gc], bv1 = bv[gc + 1];
#pragma unroll
        for (int mt = 0; mt < 2; mt++) {
#pragma unroll
            for (int half = 0; half < 2; half++) {
                int gm = bm_base + warp_m * 32 + mt * 16 + gid + half * 8;
                float n1 = g_norm1[gm];
                float n2 = g_norm2[gm];
                float mean0 = fmaxf(acc[0][mt][nt][half * 2 + 0] + bm0, 0.f);
                float mean1 = fmaxf(acc[0][mt][nt][half * 2 + 1] + bm1, 0.f);
                float var0  = fmaxf(acc[1][mt][nt][half * 2 + 0] + bv0, 0.f);
                float var1  = fmaxf(acc[1][mt][nt][half * 2 + 1] + bv1, 0.f);
                float att0 = expf(-var0), att1 = expf(-var1);
                float2 om = make_float2(mean0 * att0 * n1, mean1 * att1 * n1);
                float2 ov = make_float2(var0 * att0 * att0 * n2, var1 * att1 * att1 * n2);
                *reinterpret_cast<__half2*>(Cm + (size_t)gm * OUTF + gc) = __float22half2_rn(om);
                *reinterpret_cast<__half2*>(Cv + (size_t)gm * OUTF + gc) = __float22half2_rn(ov);
            }
        }
    }
}

// ---------------- aggregation: warp per node, CSR pure-read reduce (fp16 in/out) ----------------
__global__ void k_agg1(const __half* __restrict__ msrc, const __half* __restrict__ vsrc,
                       __half* __restrict__ mdst, __half* __restrict__ vdst, int n) {
    int warp = (blockIdx.x * blockDim.x + threadIdx.x) >> 5;
    int lane = threadIdx.x & 31;
    if (warp >= n) return;
    const int D = 128;
    int start = g_offs[warp], end = g_offs[warp + 1];

    float am[4] = {0.f, 0.f, 0.f, 0.f};
    float av[4] = {0.f, 0.f, 0.f, 0.f};
    for (int e = start; e < end; e++) {
        int s = g_csr[e];
        uint2 ar = __ldg(reinterpret_cast<const uint2*>(msrc + (size_t)s * D + lane * 4));
        uint2 br = __ldg(reinterpret_cast<const uint2*>(vsrc + (size_t)s * D + lane * 4));
        float2 a0 = __half22float2(*reinterpret_cast<__half2*>(&ar.x));
        float2 a1 = __half22float2(*reinterpret_cast<__half2*>(&ar.y));
        float2 b0 = __half22float2(*reinterpret_cast<__half2*>(&br.x));
        float2 b1 = __half22float2(*reinterpret_cast<__half2*>(&br.y));
        am[0] += a0.x; am[1] += a0.y; am[2] += a1.x; am[3] += a1.y;
        av[0] += b0.x; av[1] += b0.y; av[2] += b1.x; av[3] += b1.y;
    }
    float n1 = g_norm1[warp], n2 = g_norm2[warp];
#pragma unroll
    for (int j = 0; j < 4; j++) {
        am[j] = fmaxf(am[j] * n1, 0.f);
        av[j] = fmaxf(av[j] * n2, 0.f);
    }
    __half2 m01 = __floats2half2_rn(am[0], am[1]);
    __half2 m23 = __floats2half2_rn(am[2], am[3]);
    __half2 v01 = __floats2half2_rn(av[0], av[1]);
    __half2 v23 = __floats2half2_rn(av[2], av[3]);
    uint2 mo, vo;
    mo.x = *reinterpret_cast<uint32_t*>(&m01); mo.y = *reinterpret_cast<uint32_t*>(&m23);
    vo.x = *reinterpret_cast<uint32_t*>(&v01); vo.y = *reinterpret_cast<uint32_t*>(&v23);
    *reinterpret_cast<uint2*>(mdst + (size_t)warp * D + lane * 4) = mo;
    *reinterpret_cast<uint2*>(vdst + (size_t)warp * D + lane * 4) = vo;
}

// ---------------- threefry-2x32-20 (KAT-verified) ----------------
__device__ __forceinline__ uint32_t rotl32(uint32_t x, int d) {
    return (x << d) | (x >> (32 - d));
}

__device__ __forceinline__ void threefry2x32(uint32_t k0, uint32_t k1,
                                             uint32_t& x0, uint32_t& x1) {
    uint32_t s0 = k0, s1 = k1, s2 = k0 ^ k1 ^ 0x1BD11BDAu;
    x0 += s0; x1 += s1;
#define TFR(r) { x0 += x1; x1 = rotl32(x1, r); x1 ^= x0; }
    TFR(13) TFR(15) TFR(26) TFR(6)   x0 += s1; x1 += s2 + 1u;
    TFR(17) TFR(29) TFR(16) TFR(24)  x0 += s2; x1 += s0 + 2u;
    TFR(13) TFR(15) TFR(26) TFR(6)   x0 += s0; x1 += s1 + 3u;
    TFR(17) TFR(29) TFR(16) TFR(24)  x0 += s1; x1 += s2 + 4u;
    TFR(13) TFR(15) TFR(26) TFR(6)   x0 += s2; x1 += s0 + 5u;
#undef TFR
}

__device__ __forceinline__ float jax_normal_elem(uint32_t idx) {
    uint32_t x0 = 0u, x1 = idx;
    threefry2x32(0u, 42u, x0, x1);
    uint32_t bits = x0 ^ x1;
    uint32_t fb = (bits >> 9) | 0x3F800000u;
    float u01 = __uint_as_float(fb) - 1.0f;
    const float lo = -0.99999994f;
    float u = fmaxf(u01 * 2.0f + lo, lo);
    return 1.41421356f * erfinvf(u);
}

// layer-2 aggregation fused with reparameterization (fp16 msgs): warp per node, D=64
__global__ void k_agg2_final(const __half* __restrict__ msrc, const __half* __restrict__ vsrc,
                             float* __restrict__ out, int n) {
    int warp = (blockIdx.x * blockDim.x + threadIdx.x) >> 5;
    int lane = threadIdx.x & 31;
    if (warp >= n) return;
    const int D = 64;
    int start = g_offs[warp], end = g_offs[warp + 1];

    float am0 = 0.f, am1 = 0.f, av0 = 0.f, av1 = 0.f;
    for (int e = start; e < end; e++) {
        int s = g_csr[e];
        __half2 ah = __ldg(reinterpret_cast<const __half2*>(msrc + (size_t)s * D + lane * 2));
        __half2 bh = __ldg(reinterpret_cast<const __half2*>(vsrc + (size_t)s * D + lane * 2));
        float2 a = __half22float2(ah);
        float2 b = __half22float2(bh);
        am0 += a.x; am1 += a.y;
        av0 += b.x; av1 += b.y;
    }
    float n1 = g_norm1[warp], n2 = g_norm2[warp];
    float m0 = am0 * n1, m1 = am1 * n1;
    float v0 = av0 * n2, v1 = av1 * n2;

    uint32_t t0 = (uint32_t)(warp * D + lane * 2);
    float e0 = jax_normal_elem(t0);
    float e1 = jax_normal_elem(t0 + 1u);
    float2 o;
    o.x = e0 * sqrtf(v0 + 1e-8f) + m0;
    o.y = e1 * sqrtf(v1 + 1e-8f) + m1;
    *reinterpret_cast<float2*>(out + (size_t)warp * D + lane * 2) = o;
}

// ---------------- launch ----------------
extern "C" void kernel_launch(void* const* d_in, const int* in_sizes, int n_in,
                              void* d_out, int out_size) {
    const float* x       = (const float*)d_in[0];
    const int*   src     = (const int*)d_in[1];
    const int*   dst     = (const int*)d_in[2];
    const float* w_mean1 = (const float*)d_in[3];
    const float* w_var1  = (const float*)d_in[4];
    const float* b_mean1 = (const float*)d_in[5];
    const float* b_var1  = (const float*)d_in[6];
    const float* w_mean2 = (const float*)d_in[7];
    const float* w_var2  = (const float*)d_in[8];
    const float* b_mean2 = (const float*)d_in[9];
    const float* b_var2  = (const float*)d_in[10];
    float* out = (float*)d_out;

    const int N = in_sizes[0] / IN_F;   // 100000
    const int E = in_sizes[1];          // 1600000

    __half* bufA = nullptr; __half* bufB = nullptr;
    __half* aggM = nullptr; __half* aggV = nullptr;
    cudaGetSymbolAddress((void**)&bufA, g_bufA);
    cudaGetSymbolAddress((void**)&bufB, g_bufB);
    cudaGetSymbolAddress((void**)&aggM, g_aggM);
    cudaGetSymbolAddress((void**)&aggV, g_aggV);

    const int T = 256;
    const int NB = (N + 1023) / 1024;

    // init (zero + flags + fp16 weight pack), degrees, single-pass scan, CSR
    k_init<<<(N + T - 1) / T, T>>>(w_mean1, w_var1, w_mean2, w_var2, N);
    k_count<<<(E + T - 1) / T, T>>>(dst, E);
    k_scan<<<NB, 1024>>>(N, NB);
    k_fill<<<(E + T - 1) / T, T>>>(src, dst, E);

    // ---- layer 1: BM=64 x 128 cols GEMM (1-term fp16) + fp16 msg epilogue ----
    {
        int blocks = (N + 63) / 64;   // 1563
        k_l1_f16<<<blocks, 256>>>(x, b_mean1, b_var1, bufA, bufB, N);
    }
    {
        int blocks = (N * 32 + T - 1) / T;   // warp per node
        k_agg1<<<blocks, T>>>(bufA, bufB, aggM, aggV, N);
    }

    // ---- layer 2: dual-A GEMM (fp16, 1-term) + fp16 msg epilogue ----
    {
        int blocks = (N + 127) / 128;   // 782, covers M_PAD exactly
        k_l2_f16<<<blocks, 256>>>(aggM, aggV, b_mean2, b_var2, bufA, bufB);
    }
    // ---- layer-2 aggregation fused with threefry reparameterization ----
    {
        int blocks = (N * 32 + T - 1) / T;
        k_agg2_final<<<blocks, T>>>(bufA, bufB, out, N);
    }
}

// round 13
// speedup vs baseline: 3.0967x; 1.0205x over previous
#include <cuda_runtime.h>
#include <cuda_fp16.h>
#include <stdint.h>
#include <math.h>

#define NODES_MAX 100000
#define M_PAD     100096   // 782 * 128 (also multiple of 64)
#define EDGES_MAX 1600000
#define IN_F 256
#define HID 128
#define OUTF 64
#define FILLB 512          // fill blocks prepended to the L1 GEMM grid

// ---------------- scratch (static __device__, no allocs) ----------------
__device__ __half  g_bufA[(size_t)M_PAD * HID];   // messages m (fp16)
__device__ __half  g_bufB[(size_t)M_PAD * HID];   // messages v (fp16)
__device__ __half  g_aggM[(size_t)M_PAD * HID];   // aggregated mean (fp16)
__device__ __half  g_aggV[(size_t)M_PAD * HID];
__device__ float   g_norm1[M_PAD];
__device__ float   g_norm2[M_PAD];
__device__ int     g_deg[NODES_MAX];
__device__ int     g_cursor[NODES_MAX];
__device__ int     g_offs[NODES_MAX + 1];
__device__ int     g_csr[EDGES_MAX];
__device__ int     g_bsum[128];
__device__ int     g_flag[128];
// fp16 weights, packed as k-pair half2: [mat][K/2][N]
__device__ __half2 g_w1[2 * 128 * 128];
__device__ __half2 g_w2[2 * 64 * 64];

// ---------------- init: zero counters/flags + weight fp16 pack ----------------
__global__ void k_init(const float* __restrict__ Wm1, const float* __restrict__ Wv1,
                       const float* __restrict__ Wm2, const float* __restrict__ Wv2, int n) {
    int i = blockIdx.x * blockDim.x + threadIdx.x;
    if (i < n) { g_deg[i] = 0; g_cursor[i] = 0; }
    if (i < 128) g_flag[i] = 0;
    if (i < 2 * 128 * 128) {   // W1: K=256 -> 128 k-pairs, N=128
        int mat = i >> 14;
        int rem = i & 16383;
        int kk = rem >> 7;
        int nn = rem & 127;
        const float* W = mat ? Wv1 : Wm1;
        g_w1[i] = __floats2half2_rn(W[(2 * kk) * HID + nn], W[(2 * kk + 1) * HID + nn]);
    }
    if (i < 2 * 64 * 64) {     // W2: K=128 -> 64 k-pairs, N=64
        int mat = i >> 12;
        int rem = i & 4095;
        int kk = rem >> 6;
        int nn = rem & 63;
        const float* W = mat ? Wv2 : Wm2;
        g_w2[i] = __floats2half2_rn(W[(2 * kk) * OUTF + nn], W[(2 * kk + 1) * OUTF + nn]);
    }
}

__global__ void k_count(const int* __restrict__ dst, int E) {
    int e = blockIdx.x * blockDim.x + threadIdx.x;
    if (e < E) atomicAdd(&g_deg[dst[e]], 1);
}

// ---------------- single-pass scan (+ fused norms), chained lookback ----------------
__global__ void k_scan(int n, int nb) {
    __shared__ int sm[1024];
    __shared__ int soff;
    int t = threadIdx.x;
    int bid = blockIdx.x;
    int i = bid * 1024 + t;
    int v = (i < n) ? g_deg[i] : 0;
    if (i < n) {
        float d = fmaxf((float)v, 1.0f);
        float n1 = 1.0f / sqrtf(d);
        g_norm1[i] = n1;
        g_norm2[i] = n1 * n1;
    }
    sm[t] = v;
    __syncthreads();
#pragma unroll
    for (int d = 1; d < 1024; d <<= 1) {
        int u = (t >= d) ? sm[t - d] : 0;
        __syncthreads();
        sm[t] += u;
        __syncthreads();
    }
    if (t == 1023) {
        g_bsum[bid] = sm[1023];
        __threadfence();
        atomicExch(&g_flag[bid], 1);
    }
    int acc = 0;
    for (int b = t; b < bid; b += 1024) {
        while (atomicAdd(&g_flag[b], 0) == 0) {}
        acc += g_bsum[b];
    }
#pragma unroll
    for (int o = 16; o; o >>= 1) acc += __shfl_down_sync(0xFFFFFFFFu, acc, o);
    __shared__ int sw[32];
    if ((t & 31) == 0) sw[t >> 5] = acc;
    __syncthreads();
    if (t < 32) {
        int vv = sw[t];
#pragma unroll
        for (int o = 16; o; o >>= 1) vv += __shfl_down_sync(0xFFFFFFFFu, vv, o);
        if (t == 0) soff = vv;
    }
    __syncthreads();
    int off = soff;
    if (i < n) g_offs[i] = off + sm[t] - v;   // exclusive
    if (bid == nb - 1 && t == 1023) g_offs[n] = off + sm[1023];
}

// ================= tensor-core helpers =================
__device__ __forceinline__ void mma_f16(float* d, uint32_t a0, uint32_t a1,
                                        uint32_t a2, uint32_t a3,
                                        uint32_t b0, uint32_t b1) {
    asm volatile(
        "mma.sync.aligned.m16n8k16.row.col.f32.f16.f16.f32 "
        "{%0,%1,%2,%3},{%4,%5,%6,%7},{%8,%9},{%0,%1,%2,%3};"
        : "+f"(d[0]), "+f"(d[1]), "+f"(d[2]), "+f"(d[3])
        : "r"(a0), "r"(a1), "r"(a2), "r"(a3), "r"(b0), "r"(b1));
}

__device__ __forceinline__ void cp16(uint32_t dst, const void* src, int sz) {
    asm volatile("cp.async.cg.shared.global [%0], [%1], 16, %2;"
                 :: "r"(dst), "l"(src), "r"(sz));
}
__device__ __forceinline__ void cp_commit() {
    asm volatile("cp.async.commit_group;");
}
template <int N> __device__ __forceinline__ void cp_wait() {
    asm volatile("cp.async.wait_group %0;" :: "n"(N));
}

#define APAD 20      // floats per A smem row (16 + 4)   [L1 fp32 A]
#define BPAD2 136    // half2 words per B pair-row (128 + 8)   [L2]
#define BPAD2N 264   // half2 words per B pair-row (256 + 8)   [L1]
#define A2PAD 24     // halfs per A smem row (16 + 8)    [L2 fp16 A]

// ================= FUSED: CSR fill (blocks 0..FILLB-1) + layer-1 GEMM =================
// Both depend only on k_scan output; mutually independent -> co-scheduled in one grid.
// GEMM: BM=64 x 128 cols, 1-term fp16; 8 warps = 2 warp_m x 4 warp_n. X read once.
__global__ void __launch_bounds__(256)
k_l1_fused(const float* __restrict__ X,
           const float* __restrict__ bm, const float* __restrict__ bv,
           __half* __restrict__ Cm, __half* __restrict__ Cv, int M,
           const int* __restrict__ src, const int* __restrict__ dst, int E) {
    // ---- fill blocks ----
    if (blockIdx.x < FILLB) {
        const int stride = FILLB * 256;
        for (int e = blockIdx.x * 256 + threadIdx.x; e < E; e += stride) {
            int d = dst[e];
            int p = atomicAdd(&g_cursor[d], 1);
            g_csr[g_offs[d] + p] = src[e];
        }
        return;
    }

    // ---- GEMM blocks ----
    __shared__ float    As[2][64 * APAD];
    __shared__ uint32_t Bh[2][8 * BPAD2N];

    const int tid = threadIdx.x;
    const int lane = tid & 31;
    const int wid = tid >> 5;
    const int warp_m = wid & 1;
    const int warp_n = wid >> 1;
    const int gid = lane >> 2;
    const int tig = lane & 3;
    const int bm_base = (blockIdx.x - FILLB) * 64;

    float acc[2][2][4][4];   // [matrix][mt][nt][reg]
#pragma unroll
    for (int a = 0; a < 2; a++)
#pragma unroll
        for (int b = 0; b < 2; b++)
#pragma unroll
            for (int c = 0; c < 4; c++)
#pragma unroll
                for (int d = 0; d < 4; d++) acc[a][b][c][d] = 0.f;

    uint32_t asb[2], bhb[2];
#pragma unroll
    for (int s = 0; s < 2; s++) {
        asb[s] = (uint32_t)__cvta_generic_to_shared(&As[s][0]);
        bhb[s] = (uint32_t)__cvta_generic_to_shared(&Bh[s][0]);
    }

    auto issue = [&](int stage, int k0) {
        int kk0 = k0 >> 1;
        // A tile: 64 rows x 16 k fp32 = 256 x 16B (1 chunk/thread)
        {
            int c = tid;
            int r = c >> 2, kq = c & 3;
            int gm = bm_base + r;
            int ok = (gm < M) ? 16 : 0;
            const float* srca = X + (size_t)min(gm, M - 1) * IN_F + k0 + kq * 4;
            cp16(asb[stage] + (uint32_t)(r * APAD + kq * 4) * 4, srca, ok);
        }
        // B tile: 2 mat x 8 prows x 32 chunks = 512 x 16B
#pragma unroll
        for (int c = tid; c < 512; c += 256) {
            int mat = c >> 8;
            int pr = (c >> 5) & 7;
            int q = c & 31;
            const __half2* srcb = g_w1 + ((mat * 128 + kk0 + pr) * 128 + q * 4);
            uint32_t dstb = bhb[stage] + (uint32_t)(pr * BPAD2N + mat * 128 + q * 4) * 4;
            cp16(dstb, srcb, 16);
        }
        cp_commit();
    };

    issue(0, 0);

    const int NITER = IN_F / 16;   // 16
    for (int it = 0; it < NITER; it++) {
        int stage = it & 1;
        if (it + 1 < NITER) {
            issue(stage ^ 1, (it + 1) * 16);
            cp_wait<1>();
        } else {
            cp_wait<0>();
        }
        __syncthreads();

        const float* as = As[stage];
        const uint32_t* bh = Bh[stage];

        uint32_t ahi[2][4];
#pragma unroll
        for (int mt = 0; mt < 2; mt++) {
            int rb = warp_m * 32 + mt * 16;
            const float* r0 = as + (rb + gid) * APAD;
            const float* r1 = as + (rb + gid + 8) * APAD;
            float2 x0 = *reinterpret_cast<const float2*>(r0 + 2 * tig);
            float2 x1 = *reinterpret_cast<const float2*>(r1 + 2 * tig);
            float2 x2 = *reinterpret_cast<const float2*>(r0 + 2 * tig + 8);
            float2 x3 = *reinterpret_cast<const float2*>(r1 + 2 * tig + 8);
            __half2 h;
            h = __floats2half2_rn(x0.x, x0.y); ahi[mt][0] = *reinterpret_cast<uint32_t*>(&h);
            h = __floats2half2_rn(x1.x, x1.y); ahi[mt][1] = *reinterpret_cast<uint32_t*>(&h);
            h = __floats2half2_rn(x2.x, x2.y); ahi[mt][2] = *reinterpret_cast<uint32_t*>(&h);
            h = __floats2half2_rn(x3.x, x3.y); ahi[mt][3] = *reinterpret_cast<uint32_t*>(&h);
        }

#pragma unroll
        for (int mat = 0; mat < 2; mat++) {
#pragma unroll
            for (int nt = 0; nt < 4; nt++) {
                int col = mat * 128 + warp_n * 32 + nt * 8 + gid;
                uint32_t bh0 = bh[tig * BPAD2N + col];
                uint32_t bh1 = bh[(tig + 4) * BPAD2N + col];
#pragma unroll
                for (int mt = 0; mt < 2; mt++) {
                    mma_f16(acc[mat][mt][nt], ahi[mt][0], ahi[mt][1], ahi[mt][2], ahi[mt][3],
                            bh0, bh1);
                }
            }
        }
        __syncthreads();
    }

    // ---- epilogue: bias + relu + att + norms -> fp16 messages ----
#pragma unroll
    for (int nt = 0; nt < 4; nt++) {
        int gc = warp_n * 32 + nt * 8 + tig * 2;
        float bm0 = bm[gc], bm1 = bm[gc + 1];
        float bv0 = bv[gc], bv1 = bv[gc + 1];
#pragma unroll
        for (int mt = 0; mt < 2; mt++) {
#pragma unroll
            for (int half = 0; half < 2; half++) {
                int gm = bm_base + warp_m * 32 + mt * 16 + gid + half * 8;
                float n1 = g_norm1[gm];
                float n2 = g_norm2[gm];
                float mean0 = fmaxf(acc[0][mt][nt][half * 2 + 0] + bm0, 0.f);
                float mean1 = fmaxf(acc[0][mt][nt][half * 2 + 1] + bm1, 0.f);
                float var0  = fmaxf(acc[1][mt][nt][half * 2 + 0] + bv0, 0.f);
                float var1  = fmaxf(acc[1][mt][nt][half * 2 + 1] + bv1, 0.f);
                float att0 = expf(-var0), att1 = expf(-var1);
                float2 om = make_float2(mean0 * att0 * n1, mean1 * att1 * n1);
                float2 ov = make_float2(var0 * att0 * att0 * n2, var1 * att1 * att1 * n2);
                *reinterpret_cast<__half2*>(Cm + (size_t)gm * HID + gc) = __float22half2_rn(om);
                *reinterpret_cast<__half2*>(Cv + (size_t)gm * HID + gc) = __float22half2_rn(ov);
            }
        }
    }
}

// ================= layer-2: dual-A (fp16) GEMM, 1-term, fp16 weights =================
__global__ void __launch_bounds__(256)
k_l2_f16(const __half* __restrict__ Am, const __half* __restrict__ Av,
         const float* __restrict__ bm, const float* __restrict__ bv,
         __half* __restrict__ Cm, __half* __restrict__ Cv) {
    __shared__ __half   As[2][2][128 * A2PAD];   // [stage][matrix]
    __shared__ uint32_t Bh[2][8 * BPAD2];

    const int tid = threadIdx.x;
    const int lane = tid & 31;
    const int wid = tid >> 5;
    const int warp_m = wid & 3;
    const int warp_n = wid >> 2;
    const int gid = lane >> 2;
    const int tig = lane & 3;
    const int bm_base = blockIdx.x * 128;

    float acc[2][2][4][4];
#pragma unroll
    for (int a = 0; a < 2; a++)
#pragma unroll
        for (int b = 0; b < 2; b++)
#pragma unroll
            for (int c = 0; c < 4; c++)
#pragma unroll
                for (int d = 0; d < 4; d++) acc[a][b][c][d] = 0.f;

    uint32_t asb[2][2], bhb[2];
#pragma unroll
    for (int s = 0; s < 2; s++) {
        asb[s][0] = (uint32_t)__cvta_generic_to_shared(&As[s][0][0]);
        asb[s][1] = (uint32_t)__cvta_generic_to_shared(&As[s][1][0]);
        bhb[s] = (uint32_t)__cvta_generic_to_shared(&Bh[s][0]);
    }

    auto issue = [&](int stage, int k0) {
        int kk0 = k0 >> 1;
#pragma unroll
        for (int c = tid; c < 512; c += 256) {
            int mat = c >> 8;
            int r = (c >> 1) & 127;
            int q = c & 1;
            const __half* srca = (mat ? Av : Am) + (size_t)(bm_base + r) * HID + k0 + q * 8;
            cp16(asb[stage][mat] + (uint32_t)(r * A2PAD + q * 8) * 2, srca, 16);
        }
        {
            int c = tid;
            int mat = c >> 7;
            int pr = (c >> 4) & 7;
            int q = c & 15;
            const __half2* srcb = g_w2 + ((mat * 64 + kk0 + pr) * 64 + q * 4);
            uint32_t dstb = bhb[stage] + (uint32_t)(pr * BPAD2 + mat * 64 + q * 4) * 4;
            cp16(dstb, srcb, 16);
        }
        cp_commit();
    };

    issue(0, 0);

    const int NITER = HID / 16;   // 8
    for (int it = 0; it < NITER; it++) {
        int stage = it & 1;
        if (it + 1 < NITER) {
            issue(stage ^ 1, (it + 1) * 16);
            cp_wait<1>();
        } else {
            cp_wait<0>();
        }
        __syncthreads();

        const uint32_t* bh = Bh[stage];

#pragma unroll
        for (int mat = 0; mat < 2; mat++) {
            const __half* as = As[stage][mat];
            uint32_t a[2][4];
#pragma unroll
            for (int mt = 0; mt < 2; mt++) {
                int rb = warp_m * 32 + mt * 16;
                const __half* r0 = as + (rb + gid) * A2PAD;
                const __half* r1 = as + (rb + gid + 8) * A2PAD;
                a[mt][0] = *reinterpret_cast<const uint32_t*>(r0 + 2 * tig);
                a[mt][1] = *reinterpret_cast<const uint32_t*>(r1 + 2 * tig);
                a[mt][2] = *reinterpret_cast<const uint32_t*>(r0 + 2 * tig + 8);
                a[mt][3] = *reinterpret_cast<const uint32_t*>(r1 + 2 * tig + 8);
            }
#pragma unroll
            for (int nt = 0; nt < 4; nt++) {
                int col = mat * 64 + warp_n * 32 + nt * 8 + gid;
                uint32_t bh0 = bh[tig * BPAD2 + col];
                uint32_t bh1 = bh[(tig + 4) * BPAD2 + col];
#pragma unroll
                for (int mt = 0; mt < 2; mt++) {
                    mma_f16(acc[mat][mt][nt], a[mt][0], a[mt][1], a[mt][2], a[mt][3], bh0, bh1);
                }
            }
        }
        __syncthreads();
    }

    // ---- epilogue -> fp16 messages [M_PAD][64] ----
#pragma unroll
    for (int nt = 0; nt < 4; nt++) {
        int gc = warp_n * 32 + nt * 8 + tig * 2;
        float bm0 = bm[gc], bm1 = bm[gc + 1];
        float bv0 = bv[gc], bv1 = bv[gc + 1];
#pragma unroll
        for (int mt = 0; mt < 2; mt++) {
#pragma unroll
            for (int half = 0; half < 2; half++) {
                int gm = bm_base + warp_m * 32 + mt * 16 + gid + half * 8;
                float n1 = g_norm1[gm];
                float n2 = g_norm2[gm];
                float mean0 = fmaxf(acc[0][mt][nt][half * 2 + 0] + bm0, 0.f);
                float mean1 = fmaxf(acc[0][mt][nt][half * 2 + 1] + bm1, 0.f);
                float var0  = fmaxf(acc[1][mt][nt][half * 2 + 0] + bv0, 0.f);
                float var1  = fmaxf(acc[1][mt][nt][half * 2 + 1] + bv1, 0.f);
                float att0 = expf(-var0), att1 = expf(-var1);
                float2 om = make_float2(mean0 * att0 * n1, mean1 * att1 * n1);
                float2 ov = make_float2(var0 * att0 * att0 * n2, var1 * att1 * att1 * n2);
                *reinterpret_cast<__half2*>(Cm + (size_t)gm * OUTF + gc) = __float22half2_rn(om);
                *reinterpret_cast<__half2*>(Cv + (size_t)gm * OUTF + gc) = __float22half2_rn(ov);
            }
        }
    }
}

// ---------------- aggregation: warp per node, CSR pure-read reduce (fp16 in/out) ----------------
__global__ void k_agg1(const __half* __restrict__ msrc, const __half* __restrict__ vsrc,
                       __half* __restrict__ mdst, __half* __restrict__ vdst, int n) {
    int warp = (blockIdx.x * blockDim.x + threadIdx.x) >> 5;
    int lane = threadIdx.x & 31;
    if (warp >= n) return;
    const int D = 128;
    int start = g_offs[warp], end = g_offs[warp + 1];

    float am[4] = {0.f, 0.f, 0.f, 0.f};
    float av[4] = {0.f, 0.f, 0.f, 0.f};
    for (int e = start; e < end; e++) {
        int s = g_csr[e];
        uint2 ar = __ldg(reinterpret_cast<const uint2*>(msrc + (size_t)s * D + lane * 4));
        uint2 br = __ldg(reinterpret_cast<const uint2*>(vsrc + (size_t)s * D + lane * 4));
        float2 a0 = __half22float2(*reinterpret_cast<__half2*>(&ar.x));
        float2 a1 = __half22float2(*reinterpret_cast<__half2*>(&ar.y));
        float2 b0 = __half22float2(*reinterpret_cast<__half2*>(&br.x));
        float2 b1 = __half22float2(*reinterpret_cast<__half2*>(&br.y));
        am[0] += a0.x; am[1] += a0.y; am[2] += a1.x; am[3] += a1.y;
        av[0] += b0.x; av[1] += b0.y; av[2] += b1.x; av[3] += b1.y;
    }
    float n1 = g_norm1[warp], n2 = g_norm2[warp];
#pragma unroll
    for (int j = 0; j < 4; j++) {
        am[j] = fmaxf(am[j] * n1, 0.f);
        av[j] = fmaxf(av[j] * n2, 0.f);
    }
    __half2 m01 = __floats2half2_rn(am[0], am[1]);
    __half2 m23 = __floats2half2_rn(am[2], am[3]);
    __half2 v01 = __floats2half2_rn(av[0], av[1]);
    __half2 v23 = __floats2half2_rn(av[2], av[3]);
    uint2 mo, vo;
    mo.x = *reinterpret_cast<uint32_t*>(&m01); mo.y = *reinterpret_cast<uint32_t*>(&m23);
    vo.x = *reinterpret_cast<uint32_t*>(&v01); vo.y = *reinterpret_cast<uint32_t*>(&v23);
    *reinterpret_cast<uint2*>(mdst + (size_t)warp * D + lane * 4) = mo;
    *reinterpret_cast<uint2*>(vdst + (size_t)warp * D + lane * 4) = vo;
}

// ---------------- threefry-2x32-20 (KAT-verified) ----------------
__device__ __forceinline__ uint32_t rotl32(uint32_t x, int d) {
    return (x << d) | (x >> (32 - d));
}

__device__ __forceinline__ void threefry2x32(uint32_t k0, uint32_t k1,
                                             uint32_t& x0, uint32_t& x1) {
    uint32_t s0 = k0, s1 = k1, s2 = k0 ^ k1 ^ 0x1BD11BDAu;
    x0 += s0; x1 += s1;
#define TFR(r) { x0 += x1; x1 = rotl32(x1, r); x1 ^= x0; }
    TFR(13) TFR(15) TFR(26) TFR(6)   x0 += s1; x1 += s2 + 1u;
    TFR(17) TFR(29) TFR(16) TFR(24)  x0 += s2; x1 += s0 + 2u;
    TFR(13) TFR(15) TFR(26) TFR(6)   x0 += s0; x1 += s1 + 3u;
    TFR(17) TFR(29) TFR(16) TFR(24)  x0 += s1; x1 += s2 + 4u;
    TFR(13) TFR(15) TFR(26) TFR(6)   x0 += s2; x1 += s0 + 5u;
#undef TFR
}

__device__ __forceinline__ float jax_normal_elem(uint32_t idx) {
    uint32_t x0 = 0u, x1 = idx;
    threefry2x32(0u, 42u, x0, x1);
    uint32_t bits = x0 ^ x1;
    uint32_t fb = (bits >> 9) | 0x3F800000u;
    float u01 = __uint_as_float(fb) - 1.0f;
    const float lo = -0.99999994f;
    float u = fmaxf(u01 * 2.0f + lo, lo);
    return 1.41421356f * erfinvf(u);
}

// layer-2 aggregation fused with reparameterization (fp16 msgs): warp per node, D=64
__global__ void k_agg2_final(const __half* __restrict__ msrc, const __half* __restrict__ vsrc,
                             float* __restrict__ out, int n) {
    int warp = (blockIdx.x * blockDim.x + threadIdx.x) >> 5;
    int lane = threadIdx.x & 31;
    if (warp >= n) return;
    const int D = 64;
    int start = g_offs[warp], end = g_offs[warp + 1];

    float am0 = 0.f, am1 = 0.f, av0 = 0.f, av1 = 0.f;
    for (int e = start; e < end; e++) {
        int s = g_csr[e];
        __half2 ah = __ldg(reinterpret_cast<const __half2*>(msrc + (size_t)s * D + lane * 2));
        __half2 bh = __ldg(reinterpret_cast<const __half2*>(vsrc + (size_t)s * D + lane * 2));
        float2 a = __half22float2(ah);
        float2 b = __half22float2(bh);
        am0 += a.x; am1 += a.y;
        av0 += b.x; av1 += b.y;
    }
    float n1 = g_norm1[warp], n2 = g_norm2[warp];
    float m0 = am0 * n1, m1 = am1 * n1;
    float v0 = av0 * n2, v1 = av1 * n2;

    uint32_t t0 = (uint32_t)(warp * D + lane * 2);
    float e0 = jax_normal_elem(t0);
    float e1 = jax_normal_elem(t0 + 1u);
    float2 o;
    o.x = e0 * sqrtf(v0 + 1e-8f) + m0;
    o.y = e1 * sqrtf(v1 + 1e-8f) + m1;
    *reinterpret_cast<float2*>(out + (size_t)warp * D + lane * 2) = o;
}

// ---------------- launch ----------------
extern "C" void kernel_launch(void* const* d_in, const int* in_sizes, int n_in,
                              void* d_out, int out_size) {
    const float* x       = (const float*)d_in[0];
    const int*   src     = (const int*)d_in[1];
    const int*   dst     = (const int*)d_in[2];
    const float* w_mean1 = (const float*)d_in[3];
    const float* w_var1  = (const float*)d_in[4];
    const float* b_mean1 = (const float*)d_in[5];
    const float* b_var1  = (const float*)d_in[6];
    const float* w_mean2 = (const float*)d_in[7];
    const float* w_var2  = (const float*)d_in[8];
    const float* b_mean2 = (const float*)d_in[9];
    const float* b_var2  = (const float*)d_in[10];
    float* out = (float*)d_out;

    const int N = in_sizes[0] / IN_F;   // 100000
    const int E = in_sizes[1];          // 1600000

    __half* bufA = nullptr; __half* bufB = nullptr;
    __half* aggM = nullptr; __half* aggV = nullptr;
    cudaGetSymbolAddress((void**)&bufA, g_bufA);
    cudaGetSymbolAddress((void**)&bufB, g_bufB);
    cudaGetSymbolAddress((void**)&aggM, g_aggM);
    cudaGetSymbolAddress((void**)&aggV, g_aggV);

    const int T = 256;
    const int NB = (N + 1023) / 1024;

    // init (zero + flags + fp16 weight pack), degrees, single-pass scan
    k_init<<<(N + T - 1) / T, T>>>(w_mean1, w_var1, w_mean2, w_var2, N);
    k_count<<<(E + T - 1) / T, T>>>(dst, E);
    k_scan<<<NB, 1024>>>(N, NB);

    // ---- FUSED: CSR fill + layer-1 GEMM (both depend only on scan) ----
    {
        int gemm_blocks = (N + 63) / 64;   // 1563
        k_l1_fused<<<FILLB + gemm_blocks, 256>>>(
            x, b_mean1, b_var1, bufA, bufB, N, src, dst, E);
    }
    {
        int blocks = (N * 32 + T - 1) / T;   // warp per node
        k_agg1<<<blocks, T>>>(bufA, bufB, aggM, aggV, N);
    }

    // ---- layer 2: dual-A GEMM (fp16, 1-term) + fp16 msg epilogue ----
    {
        int blocks = (N + 127) / 128;   // 782, covers M_PAD exactly
        k_l2_f16<<<blocks, 256>>>(aggM, aggV, b_mean2, b_var2, bufA, bufB);
    }
    // ---- layer-2 aggregation fused with threefry reparameterization ----
    {
        int blocks = (N * 32 + T - 1) / T;
        k_agg2_final<<<blocks, T>>>(bufA, bufB, out, N);
    }
}